// round 10
// baseline (speedup 1.0000x reference)
#include <cuda_runtime.h>
#include <math.h>

#define BB 2
#define NN 384
#define CC 1024
#define HREPN 256
#define GHID 256
#define NHEADS 4
#define TOPKK 8
#define MAXDEG 400
#define NB 148

typedef unsigned long long ull;

// ---------------- scratch (device globals; no allocation allowed) ------------
__device__ __align__(16) float g_p1 [BB*NN*HREPN];
__device__ __align__(16) float g_p2 [BB*NN*HREPN];
__device__ __align__(16) float g_xw1[BB*NN*NHEADS*GHID];
__device__ float g_as1[BB*NN*NHEADS];
__device__ float g_ad1[BB*NN*NHEADS];
__device__ int   g_nbr[BB*NN*TOPKK];
__device__ int   g_srcl[BB*NN*MAXDEG];
__device__ int   g_deg [BB*NN];
__device__ float g_xw2[BB*NN*2];
__device__ float g_as2[BB*NN];
__device__ float g_ad2[BB*NN];
__device__ unsigned g_bar_cnt = 0;
__device__ unsigned g_bar_gen = 0;

// ---------------- f32x2 helpers ----------------------------------------------
__device__ __forceinline__ void ffma2(ull &d, ull a, ull b) {
    asm("fma.rn.f32x2 %0, %1, %2, %0;" : "+l"(d) : "l"(a), "l"(b));
}
__device__ __forceinline__ ull fma2v(ull a, ull b, ull c) {
    ull r; asm("fma.rn.f32x2 %0, %1, %2, %3;" : "=l"(r) : "l"(a), "l"(b), "l"(c)); return r;
}
__device__ __forceinline__ ull add2v(ull a, ull b) {
    ull r; asm("add.rn.f32x2 %0, %1, %2;" : "=l"(r) : "l"(a), "l"(b)); return r;
}
__device__ __forceinline__ ull pack2(float lo, float hi) {
    ull r; asm("mov.b64 %0, {%1, %2};" : "=l"(r) : "f"(lo), "f"(hi)); return r;
}
__device__ __forceinline__ void unpack2(ull v, float &lo, float &hi) {
    asm("mov.b64 {%0, %1}, %2;" : "=f"(lo), "=f"(hi) : "l"(v));
}
__device__ __forceinline__ float lo2(ull v) { return __uint_as_float((unsigned)(v & 0xffffffffull)); }
__device__ __forceinline__ float hi2(ull v) { return __uint_as_float((unsigned)(v >> 32)); }

// ---------------- grid-wide barrier (all NB blocks resident: 1 block/SM) -----
__device__ __forceinline__ void grid_bar() {
    __syncthreads();
    if (threadIdx.x == 0) {
        __threadfence();
        unsigned my = atomicAdd(&g_bar_gen, 0u);
        unsigned prev = atomicAdd(&g_bar_cnt, 1u);
        if (prev == NB - 1u) {
            g_bar_cnt = 0u;
            __threadfence();
            atomicAdd(&g_bar_gen, 1u);
        } else {
            while (atomicAdd(&g_bar_gen, 0u) == my) { __nanosleep(64); }
        }
        __threadfence();
    }
    __syncthreads();
}

// -------- fused SGEMM: 128x64 tiles, 256 thr, intra-block K-split ------------
// (R7 proven config; inner loads widened to LDS.128)
__global__ __launch_bounds__(256, 1) void k_gemms(
    const float* __restrict__ feats,
    const float* __restrict__ fc1_w,
    const float* __restrict__ gat1_w,
    const float* __restrict__ boxes)
{
    __shared__ float As[2][2][128*20];   // [khalf][buf][row*20+k]
    __shared__ float Bs[2][2][64*20];    // [khalf][buf][col*20+k]
    __shared__ float Wg4[4*64];

    int tid = threadIdx.x;
    int khalf = tid >> 7;          // 0 or 1
    int htid  = tid & 127;
    int bid = blockIdx.x;
    int sel, b, by, bx;
    if (bid < 48) { sel = 0; b = bid / 24; int r = bid % 24; by = r / 8;  bx = r % 8;  }
    else { sel = 1; int r = bid - 48; b = r / 48; r %= 48;   by = r / 16; bx = r % 16; }

    int row0 = by * 128, col0 = bx * 64;

    const float* A = feats + b*NN*CC;
    const float* Bm; float* Cm;
    int ldb, Nc, dcol0;
    if (sel == 0) {
        ldb = 256; Nc = 256;
        if (col0 < 256) { Bm = fc1_w;            Cm = g_p1 + b*NN*256; dcol0 = col0; }
        else            { Bm = fc1_w + 1024*256; Cm = g_p2 + b*NN*256; dcol0 = col0 - 256; }
    } else {
        ldb = 1024; Nc = 1024; Bm = gat1_w; Cm = g_xw1 + b*NN*1024; dcol0 = col0;
        Wg4[tid] = gat1_w[(1024 + (tid >> 6))*1024 + col0 + (tid & 63)];
    }

    int tx = htid & 7, ty = htid >> 3;      // 8 x 16 thread grid per half
    ull acc[8][8];
    #pragma unroll
    for (int r = 0; r < 8; r++)
        #pragma unroll
        for (int j = 0; j < 8; j++) acc[r][j] = 0ull;

    int arow = htid >> 2, aslot = htid & 3;   // A loader: rows arow+32m
    int bc = htid & 63, bk = htid >> 6;       // B loader: col bc, k's bk*8..+7

    int kbase = khalf * 512;
    const float* ApB = feats + b*NN*CC + (row0 + arow)*1024 + kbase + aslot*4;
    const float* Bp  = Bm + (ull)kbase*ldb + dcol0 + bc;
    (void)A;

    float4 pa[4]; float pb[8];
    #pragma unroll
    for (int m = 0; m < 4; m++) pa[m] = *(const float4*)(ApB + m*32*1024);
    #pragma unroll
    for (int m = 0; m < 8; m++) pb[m] = Bp[(bk*8 + m)*ldb];
    #pragma unroll
    for (int m = 0; m < 4; m++) *(float4*)&As[khalf][0][(arow + 32*m)*20 + aslot*4] = pa[m];
    #pragma unroll
    for (int m = 0; m < 8; m++) Bs[khalf][0][bc*20 + bk*8 + m] = pb[m];
    __syncthreads();

    for (int t = 0; t < 32; t++) {
        int cur = t & 1, nxt = cur ^ 1;
        if (t < 31) {
            int k0 = (t + 1) * 16;
            #pragma unroll
            for (int m = 0; m < 4; m++) pa[m] = *(const float4*)(ApB + m*32*1024 + k0);
            #pragma unroll
            for (int m = 0; m < 8; m++) pb[m] = Bp[(k0 + bk*8 + m)*ldb];
        }
        #pragma unroll
        for (int kph = 0; kph < 4; kph++) {
            ulonglong2 av[8], bv[8];
            #pragma unroll
            for (int r = 0; r < 8; r++)
                av[r] = *(const ulonglong2*)&As[khalf][cur][(ty + 16*r)*20 + 4*kph];
            #pragma unroll
            for (int j = 0; j < 8; j++)
                bv[j] = *(const ulonglong2*)&Bs[khalf][cur][(tx + 8*j)*20 + 4*kph];
            #pragma unroll
            for (int r = 0; r < 8; r++)
                #pragma unroll
                for (int j = 0; j < 8; j++) ffma2(acc[r][j], av[r].x, bv[j].x);
            #pragma unroll
            for (int r = 0; r < 8; r++)
                #pragma unroll
                for (int j = 0; j < 8; j++) ffma2(acc[r][j], av[r].y, bv[j].y);
        }
        if (t < 31) {
            #pragma unroll
            for (int m = 0; m < 4; m++) *(float4*)&As[khalf][nxt][(arow + 32*m)*20 + aslot*4] = pa[m];
            #pragma unroll
            for (int m = 0; m < 8; m++) Bs[khalf][nxt][bc*20 + bk*8 + m] = pb[m];
        }
        __syncthreads();
    }

    // ---- combine halves via padded smem (stride 65: bank-conflict-free) ----
    float* comb = (float*)As;
    if (khalf == 1) {
        #pragma unroll
        for (int r = 0; r < 8; r++)
            #pragma unroll
            for (int j = 0; j < 8; j++)
                comb[htid*65 + r*8 + j] = lo2(acc[r][j]) + hi2(acc[r][j]);
    }
    __syncthreads();
    if (khalf == 0) {
        #pragma unroll
        for (int r = 0; r < 8; r++) {
            int row = row0 + ty + 16*r;
            float g0 = 0.f, g1 = 0.f, g2 = 0.f, g3 = 0.f;
            if (sel == 1) {
                const float* bx4 = boxes + (b*NN + row)*4;
                float x0 = bx4[0]*(1.0f/800.0f), y0 = bx4[1]*(1.0f/800.0f);
                float x1 = bx4[2]*(1.0f/800.0f), y1 = bx4[3]*(1.0f/800.0f);
                g0 = x0; g1 = y0; g2 = x1 - x0; g3 = y1 - y0;
            }
            #pragma unroll
            for (int j = 0; j < 8; j++) {
                int c = tx + 8*j;
                float s = (lo2(acc[r][j]) + hi2(acc[r][j])) + comb[htid*65 + r*8 + j];
                if (sel == 1) {
                    s = fmaf(g0, Wg4[0*64 + c], s);
                    s = fmaf(g1, Wg4[1*64 + c], s);
                    s = fmaf(g2, Wg4[2*64 + c], s);
                    s = fmaf(g3, Wg4[3*64 + c], s);
                }
                Cm[row*Nc + dcol0 + c] = s;
            }
        }
    }
}

// ============ persistent TAIL kernel: rel+asad | gat1 | gat2 =================
__global__ __launch_bounds__(256, 1) void k_tail(
    const float* __restrict__ boxes,
    const float* __restrict__ fc1_w,
    const float* __restrict__ fc1_b,
    const float* __restrict__ fc2_w,
    const float* __restrict__ att_src,
    const float* __restrict__ att_dst,
    const float* __restrict__ gat1_b,
    const float* __restrict__ gat2_w,
    const float* __restrict__ att_src2,
    const float* __restrict__ att_dst2,
    const float* __restrict__ gat2_b,
    float* __restrict__ out)
{
    __shared__ __align__(16) float sm[7680];   // 30.7KB union
    int tid = threadIdx.x;
    int bid0 = blockIdx.x;
    int warp = tid >> 5, lane = tid & 31;

    // ========== PHASE A: rel+topk (tasks 0..191) | asad (192..575) ==========
    for (int task = bid0; task < 576; task += NB) {
        __syncthreads();
        if (task >= 192) {
            int bn = (task - 192)*2 + (tid >> 7);
            int h = (tid >> 5) & 3;
            const float* xw = g_xw1 + bn*1024 + h*256 + lane*8;
            float4 v0 = *(const float4*)xw;
            float4 v1 = *(const float4*)(xw + 4);
            const float* asr = att_src + h*256 + lane*8;
            const float* adr = att_dst + h*256 + lane*8;
            float4 s0 = *(const float4*)asr;
            float4 s1 = *(const float4*)(asr + 4);
            float4 d0 = *(const float4*)adr;
            float4 d1 = *(const float4*)(adr + 4);
            float ss = v0.x*s0.x + v0.y*s0.y + v0.z*s0.z + v0.w*s0.w
                     + v1.x*s1.x + v1.y*s1.y + v1.z*s1.z + v1.w*s1.w;
            float dd = v0.x*d0.x + v0.y*d0.y + v0.z*d0.z + v0.w*d0.w
                     + v1.x*d1.x + v1.y*d1.y + v1.z*d1.z + v1.w*d1.w;
            #pragma unroll
            for (int o = 16; o; o >>= 1) {
                ss += __shfl_down_sync(0xffffffffu, ss, o);
                dd += __shfl_down_sync(0xffffffffu, dd, o);
            }
            if (lane == 0) { g_as1[bn*4 + h] = ss; g_ad1[bn*4 + h] = dd; }
            continue;
        }

        int b = task / 96, igrp = task % 96;
        int i0 = igrp * 4;
        float* srow = sm;            // [4][NN]
        float* sbx  = sm + 1536;     // [16]

        if (tid < 16) sbx[tid] = boxes[(b*NN + i0 + (tid >> 2))*4 + (tid & 3)];

        ull wg2[4][4], sp1q[4][4];
        float w2lo[4], w2hi[4];
        #pragma unroll
        for (int p = 0; p < 4; p++) {
            int k0 = lane + 64*p, k1 = k0 + 32;
            w2lo[p] = fc2_w[k0];
            w2hi[p] = fc2_w[k1];
            #pragma unroll
            for (int d = 0; d < 4; d++)
                wg2[d][p] = pack2(fc1_w[(2048+d)*256 + k0], fc1_w[(2048+d)*256 + k1]);
            float b0 = fc1_b[k0], b1 = fc1_b[k1];
            #pragma unroll
            for (int q = 0; q < 4; q++) {
                const float* p1r = g_p1 + (b*NN + i0 + q)*256;
                sp1q[q][p] = pack2(p1r[k0] + b0, p1r[k1] + b1);
            }
        }
        __syncthreads();

        const float* p2b = g_p2 + b*NN*256;
        const float* bxb = boxes + b*NN*4;

        for (int j = warp; j < NN; j += 8) {
            float4 bj = *(const float4*)&bxb[j*4];
            ull p2v[4];
            #pragma unroll
            for (int p = 0; p < 4; p++) {
                int k0 = lane + 64*p;
                p2v[p] = pack2(p2b[j*256 + k0], p2b[j*256 + k0 + 32]);
            }
            #pragma unroll
            for (int q = 0; q < 4; q++) {
                float d0 = fabsf(sbx[q*4+0] - bj.x);
                float d1 = fabsf(sbx[q*4+1] - bj.y);
                float d2 = fabsf(sbx[q*4+2] - bj.z);
                float d3 = fabsf(sbx[q*4+3] - bj.w);
                ull a0 = pack2(d0, d0), a1 = pack2(d1, d1);
                ull a2 = pack2(d2, d2), a3 = pack2(d3, d3);
                float sum = 0.f;
                #pragma unroll
                for (int p = 0; p < 4; p++) {
                    ull t2 = add2v(sp1q[q][p], p2v[p]);
                    t2 = fma2v(a0, wg2[0][p], t2);
                    t2 = fma2v(a1, wg2[1][p], t2);
                    t2 = fma2v(a2, wg2[2][p], t2);
                    t2 = fma2v(a3, wg2[3][p], t2);
                    float tl, th;
                    unpack2(t2, tl, th);
                    tl = fmaxf(tl, 0.f);
                    th = fmaxf(th, 0.f);
                    sum = fmaf(tl, w2lo[p], sum);
                    sum = fmaf(th, w2hi[p], sum);
                }
                #pragma unroll
                for (int o = 16; o; o >>= 1) sum += __shfl_down_sync(0xffffffffu, sum, o);
                if (lane == 0)
                    srow[q*NN + j] = sum - ((j == i0 + q) ? 1e6f : 0.f);
            }
        }
        __syncthreads();

        if (warp < 4) {
            int q = warp, i = i0 + q;
            for (int sel2 = 0; sel2 < TOPKK; sel2++) {
                float bv = -3.4e38f; int bi = 1 << 30;
                for (int j = lane; j < NN; j += 32) {
                    float v = srow[q*NN + j];
                    if (v > bv || (v == bv && j < bi)) { bv = v; bi = j; }
                }
                #pragma unroll
                for (int o = 16; o; o >>= 1) {
                    float ov = __shfl_xor_sync(0xffffffffu, bv, o);
                    int   oi = __shfl_xor_sync(0xffffffffu, bi, o);
                    if (ov > bv || (ov == bv && oi < bi)) { bv = ov; bi = oi; }
                }
                if (lane == 0) {
                    g_nbr[(b*NN + i)*TOPKK + sel2] = bi;
                    srow[q*NN + bi] = -3.4e38f;
                }
                __syncwarp();
            }
        }
    }
    grid_bar();

    // ========== PHASE B: GAT1 fused build+softmax+aggregate+xw2 (768) =======
    for (int task = bid0; task < 768; task += NB) {
        __syncthreads();
        int bn = task; int b = bn / NN, tt = bn % NN;
        int*   ssrc = (int*)sm;            // 400
        float* sal  = sm + 400;            // 4*400
        float* sas1 = sm + 2000;           // 1536
        int*   scnt = (int*)(sm + 3536);   // 256
        float* red  = sm + 3792;           // 16
        int*   sdeg = (int*)(sm + 3808);

        #pragma unroll
        for (int it = 0; it < 6; it++)
            sas1[tid + it*256] = g_as1[b*NN*4 + tid + it*256];

        const int* nb = g_nbr + b*NN*TOPKK;
        int myc0 = 0, myc1 = 0;
        int ia = 2*tid, ib = 2*tid + 1;
        if (tid < 192) {
            #pragma unroll
            for (int k = 0; k < TOPKK; k++) {
                myc0 += (nb[ia*TOPKK + k] == tt);
                myc1 += (nb[ib*TOPKK + k] == tt);
            }
        }
        int tot = myc0 + myc1;
        scnt[tid] = tot;
        __syncthreads();
        for (int s = 1; s < 256; s <<= 1) {
            int v = (tid >= s) ? scnt[tid - s] : 0;
            __syncthreads();
            scnt[tid] += v;
            __syncthreads();
        }
        int off = scnt[tid] - tot;
        int* dst = g_srcl + bn*MAXDEG;
        if (tid < 192) {
            if (myc0) {
                #pragma unroll
                for (int k = 0; k < TOPKK; k++)
                    if (nb[ia*TOPKK + k] == tt) { ssrc[off] = ia; dst[off] = ia; off++; }
            }
            if (myc1) {
                #pragma unroll
                for (int k = 0; k < TOPKK; k++)
                    if (nb[ib*TOPKK + k] == tt) { ssrc[off] = ib; dst[off] = ib; off++; }
            }
        }
        if (tid == 255) {
            int total = scnt[255];
            ssrc[total] = tt;
            dst[total] = tt;
            g_deg[bn] = total + 1;
            *sdeg = total + 1;
        }
        __syncthreads();
        int deg = *sdeg;

        if (warp < NHEADS) {
            int h = warp;
            float adv = g_ad1[bn*4 + h];
            float m = -3.4e38f;
            for (int s = lane; s < deg; s += 32) {
                float e = sas1[ssrc[s]*4 + h] + adv;
                e = (e >= 0.f) ? e : 0.2f*e;
                sal[h*MAXDEG + s] = e;
                m = fmaxf(m, e);
            }
            #pragma unroll
            for (int o = 16; o; o >>= 1) m = fmaxf(m, __shfl_xor_sync(0xffffffffu, m, o));
            float sum = 0.f;
            for (int s = lane; s < deg; s += 32) {
                float ex = expf(sal[h*MAXDEG + s] - m);
                sal[h*MAXDEG + s] = ex;
                sum += ex;
            }
            #pragma unroll
            for (int o = 16; o; o >>= 1) sum += __shfl_xor_sync(0xffffffffu, sum, o);
            float inv = 1.f / fmaxf(sum, 1e-16f);
            for (int s = lane; s < deg; s += 32) sal[h*MAXDEG + s] *= inv;
        }
        __syncthreads();

        const float* xwb = g_xw1 + b*NN*1024;
        const float* salh = sal + (tid >> 6)*MAXDEG;
        float4 acc0 = make_float4(0.f, 0.f, 0.f, 0.f);
        float4 acc1 = make_float4(0.f, 0.f, 0.f, 0.f);
        int col4 = tid * 4;
        int s = 0;
        for (; s + 1 < deg; s += 2) {
            float4 v0 = *(const float4*)&xwb[ssrc[s  ]*1024 + col4];
            float4 v1 = *(const float4*)&xwb[ssrc[s+1]*1024 + col4];
            float a0 = salh[s], a1 = salh[s+1];
            acc0.x = fmaf(v0.x, a0, acc0.x); acc0.y = fmaf(v0.y, a0, acc0.y);
            acc0.z = fmaf(v0.z, a0, acc0.z); acc0.w = fmaf(v0.w, a0, acc0.w);
            acc1.x = fmaf(v1.x, a1, acc1.x); acc1.y = fmaf(v1.y, a1, acc1.y);
            acc1.z = fmaf(v1.z, a1, acc1.z); acc1.w = fmaf(v1.w, a1, acc1.w);
        }
        if (s < deg) {
            float4 v0 = *(const float4*)&xwb[ssrc[s]*1024 + col4];
            float a0 = salh[s];
            acc0.x = fmaf(v0.x, a0, acc0.x); acc0.y = fmaf(v0.y, a0, acc0.y);
            acc0.z = fmaf(v0.z, a0, acc0.z); acc0.w = fmaf(v0.w, a0, acc0.w);
        }
        float4 bia = *(const float4*)&gat1_b[col4];
        float4 oh;
        oh.x = fmaxf(acc0.x + acc1.x + bia.x, 0.f);
        oh.y = fmaxf(acc0.y + acc1.y + bia.y, 0.f);
        oh.z = fmaxf(acc0.z + acc1.z + bia.z, 0.f);
        oh.w = fmaxf(acc0.w + acc1.w + bia.w, 0.f);

        float4 w0 = *(const float4*)&gat2_w[col4*2];
        float4 w1 = *(const float4*)&gat2_w[col4*2 + 4];
        float c0 = oh.x*w0.x + oh.y*w0.z + oh.z*w1.x + oh.w*w1.z;
        float c1 = oh.x*w0.y + oh.y*w0.w + oh.z*w1.y + oh.w*w1.w;
        #pragma unroll
        for (int o = 16; o; o >>= 1) {
            c0 += __shfl_down_sync(0xffffffffu, c0, o);
            c1 += __shfl_down_sync(0xffffffffu, c1, o);
        }
        if (lane == 0) { red[warp*2 + 0] = c0; red[warp*2 + 1] = c1; }
        __syncthreads();
        if (tid == 0) {
            float s0 = 0.f, s1 = 0.f;
            #pragma unroll
            for (int w = 0; w < 8; w++) { s0 += red[w*2]; s1 += red[w*2 + 1]; }
            g_xw2[bn*2 + 0] = s0;
            g_xw2[bn*2 + 1] = s1;
            g_as2[bn] = s0*att_src2[0] + s1*att_src2[1];
            g_ad2[bn] = s0*att_dst2[0] + s1*att_dst2[1];
        }
    }
    grid_bar();

    // ========== PHASE C: GAT2 (96 tasks, 8 nodes each) ======================
    if (bid0 < 96) {
        float* s_as2 = sm;                  // 384
        float* s_xw2 = sm + 384;            // 768
        float* sal2  = sm + 1152;           // 8*400
        int*   ssrc2 = (int*)(sm + 4352);   // 8*400
        int n0 = bid0 * 8;
        int b = n0 / NN;

        for (int i = tid; i < NN; i += 256)   s_as2[i] = g_as2[b*NN + i];
        for (int i = tid; i < NN*2; i += 256) s_xw2[i] = g_xw2[b*NN*2 + i];
        __syncthreads();

        int bn = n0 + warp;
        int deg = g_deg[bn];
        float* salw = sal2 + warp*MAXDEG;
        int*   srcw = ssrc2 + warp*MAXDEG;
        for (int s = lane; s < deg; s += 32) srcw[s] = g_srcl[bn*MAXDEG + s];
        __syncwarp();
        float adv = g_ad2[bn];
        float m = -3.4e38f;
        for (int s = lane; s < deg; s += 32) {
            float e = s_as2[srcw[s]] + adv;
            e = (e >= 0.f) ? e : 0.2f*e;
            salw[s] = e;
            m = fmaxf(m, e);
        }
        #pragma unroll
        for (int o = 16; o; o >>= 1) m = fmaxf(m, __shfl_xor_sync(0xffffffffu, m, o));
        float sum = 0.f;
        for (int s = lane; s < deg; s += 32) {
            float ex = expf(salw[s] - m);
            salw[s] = ex;
            sum += ex;
        }
        #pragma unroll
        for (int o = 16; o; o >>= 1) sum += __shfl_xor_sync(0xffffffffu, sum, o);
        float inv = 1.f / fmaxf(sum, 1e-16f);
        __syncwarp();
        float a0 = 0.f, a1 = 0.f;
        for (int s = lane; s < deg; s += 32) {
            float w = salw[s] * inv;
            int sc = srcw[s];
            a0 = fmaf(s_xw2[sc*2 + 0], w, a0);
            a1 = fmaf(s_xw2[sc*2 + 1], w, a1);
        }
        #pragma unroll
        for (int o = 16; o; o >>= 1) {
            a0 += __shfl_down_sync(0xffffffffu, a0, o);
            a1 += __shfl_down_sync(0xffffffffu, a1, o);
        }
        if (lane == 0) {
            out[bn*2 + 0] = a0 + gat2_b[0];
            out[bn*2 + 1] = a1 + gat2_b[1];
        }
    }
}

// ---------------- launch ------------------------------------------------------
extern "C" void kernel_launch(void* const* d_in, const int* in_sizes, int n_in,
                              void* d_out, int out_size)
{
    const float* feats   = (const float*)d_in[0];
    const float* boxes   = (const float*)d_in[1];
    const float* fc1_w   = (const float*)d_in[2];
    const float* fc1_b   = (const float*)d_in[3];
    const float* fc2_w   = (const float*)d_in[4];
    // d_in[5] = fc2_b : constant shift, irrelevant for top-k
    const float* gat1_w  = (const float*)d_in[6];
    const float* g1as    = (const float*)d_in[7];
    const float* g1ad    = (const float*)d_in[8];
    const float* gat1_b  = (const float*)d_in[9];
    const float* gat2_w  = (const float*)d_in[10];
    const float* g2as    = (const float*)d_in[11];
    const float* g2ad    = (const float*)d_in[12];
    const float* gat2_b  = (const float*)d_in[13];
    float* out = (float*)d_out;

    k_gemms<<<144, 256>>>(feats, fc1_w, gat1_w, boxes);
    k_tail <<<NB, 256>>>(boxes, fc1_w, fc1_b, fc2_w, g1as, g1ad,
                         gat1_b, gat2_w, g2as, g2ad, gat2_b, out);
    (void)in_sizes; (void)n_in; (void)out_size;
}

// round 11
// speedup vs baseline: 1.1824x; 1.1824x over previous
#include <cuda_runtime.h>
#include <math.h>

#define BB 2
#define NN 384
#define CC 1024
#define HREPN 256
#define GHID 256
#define NHEADS 4
#define TOPKK 8
#define MAXDEG 400

typedef unsigned long long ull;

// ---------------- scratch (device globals; no allocation allowed) ------------
__device__ __align__(16) float g_p1 [BB*NN*HREPN];
__device__ __align__(16) float g_p2 [BB*NN*HREPN];
__device__ __align__(16) float g_xw1[BB*NN*NHEADS*GHID];
__device__ float g_as1[BB*NN*NHEADS];
__device__ float g_ad1[BB*NN*NHEADS];
__device__ int   g_nbr[BB*NN*TOPKK];
__device__ int   g_srcl[BB*NN*MAXDEG];
__device__ int   g_deg [BB*NN];
__device__ float g_xw2[BB*NN*2];
__device__ float g_as2[BB*NN];
__device__ float g_ad2[BB*NN];

// ---------------- f32x2 helpers ----------------------------------------------
__device__ __forceinline__ void ffma2(ull &d, ull a, ull b) {
    asm("fma.rn.f32x2 %0, %1, %2, %0;" : "+l"(d) : "l"(a), "l"(b));
}
__device__ __forceinline__ ull fma2v(ull a, ull b, ull c) {
    ull r; asm("fma.rn.f32x2 %0, %1, %2, %3;" : "=l"(r) : "l"(a), "l"(b), "l"(c)); return r;
}
__device__ __forceinline__ ull add2v(ull a, ull b) {
    ull r; asm("add.rn.f32x2 %0, %1, %2;" : "=l"(r) : "l"(a), "l"(b)); return r;
}
__device__ __forceinline__ ull pack2(float lo, float hi) {
    ull r; asm("mov.b64 %0, {%1, %2};" : "=l"(r) : "f"(lo), "f"(hi)); return r;
}
__device__ __forceinline__ void unpack2(ull v, float &lo, float &hi) {
    asm("mov.b64 {%0, %1}, %2;" : "=f"(lo), "=f"(hi) : "l"(v));
}
__device__ __forceinline__ float lo2(ull v) { return __uint_as_float((unsigned)(v & 0xffffffffull)); }
__device__ __forceinline__ float hi2(ull v) { return __uint_as_float((unsigned)(v >> 32)); }

// -------- fused SGEMM: 128x64 tiles, 256 thr, intra-block K-split ------------
__global__ __launch_bounds__(256, 1) void k_gemms(
    const float* __restrict__ feats,
    const float* __restrict__ fc1_w,
    const float* __restrict__ gat1_w,
    const float* __restrict__ boxes)
{
    __shared__ float As[2][2][128*20];
    __shared__ float Bs[2][2][64*20];
    __shared__ float Wg4[4*64];

    int tid = threadIdx.x;
    int khalf = tid >> 7;
    int htid  = tid & 127;
    int bid = blockIdx.x;
    int sel, b, by, bx;
    if (bid < 48) { sel = 0; b = bid / 24; int r = bid % 24; by = r / 8;  bx = r % 8;  }
    else { sel = 1; int r = bid - 48; b = r / 48; r %= 48;   by = r / 16; bx = r % 16; }

    int row0 = by * 128, col0 = bx * 64;

    const float* Bm; float* Cm;
    int ldb, Nc, dcol0;
    if (sel == 0) {
        ldb = 256; Nc = 256;
        if (col0 < 256) { Bm = fc1_w;            Cm = g_p1 + b*NN*256; dcol0 = col0; }
        else            { Bm = fc1_w + 1024*256; Cm = g_p2 + b*NN*256; dcol0 = col0 - 256; }
    } else {
        ldb = 1024; Nc = 1024; Bm = gat1_w; Cm = g_xw1 + b*NN*1024; dcol0 = col0;
        Wg4[tid] = gat1_w[(1024 + (tid >> 6))*1024 + col0 + (tid & 63)];
    }

    int tx = htid & 7, ty = htid >> 3;
    ull acc[8][8];
    #pragma unroll
    for (int r = 0; r < 8; r++)
        #pragma unroll
        for (int j = 0; j < 8; j++) acc[r][j] = 0ull;

    int arow = htid >> 2, aslot = htid & 3;
    int bc = htid & 63, bk = htid >> 6;

    int kbase = khalf * 512;
    const float* ApB = feats + b*NN*CC + (row0 + arow)*1024 + kbase + aslot*4;
    const float* Bp  = Bm + (ull)kbase*ldb + dcol0 + bc;

    float4 pa[4]; float pb[8];
    #pragma unroll
    for (int m = 0; m < 4; m++) pa[m] = *(const float4*)(ApB + m*32*1024);
    #pragma unroll
    for (int m = 0; m < 8; m++) pb[m] = Bp[(bk*8 + m)*ldb];
    #pragma unroll
    for (int m = 0; m < 4; m++) *(float4*)&As[khalf][0][(arow + 32*m)*20 + aslot*4] = pa[m];
    #pragma unroll
    for (int m = 0; m < 8; m++) Bs[khalf][0][bc*20 + bk*8 + m] = pb[m];
    __syncthreads();

    for (int t = 0; t < 32; t++) {
        int cur = t & 1, nxt = cur ^ 1;
        if (t < 31) {
            int k0 = (t + 1) * 16;
            #pragma unroll
            for (int m = 0; m < 4; m++) pa[m] = *(const float4*)(ApB + m*32*1024 + k0);
            #pragma unroll
            for (int m = 0; m < 8; m++) pb[m] = Bp[(k0 + bk*8 + m)*ldb];
        }
        #pragma unroll
        for (int kph = 0; kph < 4; kph++) {
            ulonglong2 av[8], bv[8];
            #pragma unroll
            for (int r = 0; r < 8; r++)
                av[r] = *(const ulonglong2*)&As[khalf][cur][(ty + 16*r)*20 + 4*kph];
            #pragma unroll
            for (int j = 0; j < 8; j++)
                bv[j] = *(const ulonglong2*)&Bs[khalf][cur][(tx + 8*j)*20 + 4*kph];
            #pragma unroll
            for (int r = 0; r < 8; r++)
                #pragma unroll
                for (int j = 0; j < 8; j++) ffma2(acc[r][j], av[r].x, bv[j].x);
            #pragma unroll
            for (int r = 0; r < 8; r++)
                #pragma unroll
                for (int j = 0; j < 8; j++) ffma2(acc[r][j], av[r].y, bv[j].y);
        }
        if (t < 31) {
            #pragma unroll
            for (int m = 0; m < 4; m++) *(float4*)&As[khalf][nxt][(arow + 32*m)*20 + aslot*4] = pa[m];
            #pragma unroll
            for (int m = 0; m < 8; m++) Bs[khalf][nxt][bc*20 + bk*8 + m] = pb[m];
        }
        __syncthreads();
    }

    float* comb = (float*)As;
    if (khalf == 1) {
        #pragma unroll
        for (int r = 0; r < 8; r++)
            #pragma unroll
            for (int j = 0; j < 8; j++)
                comb[htid*65 + r*8 + j] = lo2(acc[r][j]) + hi2(acc[r][j]);
    }
    __syncthreads();
    if (khalf == 0) {
        #pragma unroll
        for (int r = 0; r < 8; r++) {
            int row = row0 + ty + 16*r;
            float g0 = 0.f, g1 = 0.f, g2 = 0.f, g3 = 0.f;
            if (sel == 1) {
                const float* bx4 = boxes + (b*NN + row)*4;
                float x0 = bx4[0]*(1.0f/800.0f), y0 = bx4[1]*(1.0f/800.0f);
                float x1 = bx4[2]*(1.0f/800.0f), y1 = bx4[3]*(1.0f/800.0f);
                g0 = x0; g1 = y0; g2 = x1 - x0; g3 = y1 - y0;
            }
            #pragma unroll
            for (int j = 0; j < 8; j++) {
                int c = tx + 8*j;
                float s = (lo2(acc[r][j]) + hi2(acc[r][j])) + comb[htid*65 + r*8 + j];
                if (sel == 1) {
                    s = fmaf(g0, Wg4[0*64 + c], s);
                    s = fmaf(g1, Wg4[1*64 + c], s);
                    s = fmaf(g2, Wg4[2*64 + c], s);
                    s = fmaf(g3, Wg4[3*64 + c], s);
                }
                Cm[row*Nc + dcol0 + c] = s;
            }
        }
    }
}

// ------- merged: rel+topk 2 rows/block (0..383)  |  asad (384..767) ----------
__global__ __launch_bounds__(256) void k_rel_asad(
    const float* __restrict__ boxes,
    const float* __restrict__ fc1_w,
    const float* __restrict__ fc1_b,
    const float* __restrict__ fc2_w,
    const float* __restrict__ att_src,
    const float* __restrict__ att_dst)
{
    __shared__ float srow[2][NN];
    __shared__ float sbx[8];
    int bid = blockIdx.x;
    int tid = threadIdx.x, warp = tid >> 5, lane = tid & 31;

    if (bid >= 384) {
        int bn = (bid - 384)*2 + (tid >> 7);
        int h = (tid >> 5) & 3;
        const float* xw = g_xw1 + bn*1024 + h*256 + lane*8;
        float4 v0 = *(const float4*)xw;
        float4 v1 = *(const float4*)(xw + 4);
        const float* asr = att_src + h*256 + lane*8;
        const float* adr = att_dst + h*256 + lane*8;
        float4 s0 = *(const float4*)asr;
        float4 s1 = *(const float4*)(asr + 4);
        float4 d0 = *(const float4*)adr;
        float4 d1 = *(const float4*)(adr + 4);
        float ss = v0.x*s0.x + v0.y*s0.y + v0.z*s0.z + v0.w*s0.w
                 + v1.x*s1.x + v1.y*s1.y + v1.z*s1.z + v1.w*s1.w;
        float dd = v0.x*d0.x + v0.y*d0.y + v0.z*d0.z + v0.w*d0.w
                 + v1.x*d1.x + v1.y*d1.y + v1.z*d1.z + v1.w*d1.w;
        #pragma unroll
        for (int o = 16; o; o >>= 1) {
            ss += __shfl_down_sync(0xffffffffu, ss, o);
            dd += __shfl_down_sync(0xffffffffu, dd, o);
        }
        if (lane == 0) { g_as1[bn*4 + h] = ss; g_ad1[bn*4 + h] = dd; }
        return;
    }

    int b = bid / 192, igrp = bid % 192;
    int i0 = igrp * 2;

    if (tid < 8) sbx[tid] = boxes[(b*NN + i0 + (tid >> 2))*4 + (tid & 3)];

    ull wg2[4][4], sp1q[2][4];
    float w2lo[4], w2hi[4];
    #pragma unroll
    for (int p = 0; p < 4; p++) {
        int k0 = lane + 64*p, k1 = k0 + 32;
        w2lo[p] = fc2_w[k0];
        w2hi[p] = fc2_w[k1];
        #pragma unroll
        for (int d = 0; d < 4; d++)
            wg2[d][p] = pack2(fc1_w[(2048+d)*256 + k0], fc1_w[(2048+d)*256 + k1]);
        float b0 = fc1_b[k0], b1 = fc1_b[k1];
        #pragma unroll
        for (int q = 0; q < 2; q++) {
            const float* p1r = g_p1 + (b*NN + i0 + q)*256;
            sp1q[q][p] = pack2(p1r[k0] + b0, p1r[k1] + b1);
        }
    }
    __syncthreads();

    const float* p2b = g_p2 + b*NN*256;
    const float* bxb = boxes + b*NN*4;

    for (int j = warp; j < NN; j += 8) {
        float4 bj = *(const float4*)&bxb[j*4];
        ull p2v[4];
        #pragma unroll
        for (int p = 0; p < 4; p++) {
            int k0 = lane + 64*p;
            p2v[p] = pack2(p2b[j*256 + k0], p2b[j*256 + k0 + 32]);
        }
        #pragma unroll
        for (int q = 0; q < 2; q++) {
            float d0 = fabsf(sbx[q*4+0] - bj.x);
            float d1 = fabsf(sbx[q*4+1] - bj.y);
            float d2 = fabsf(sbx[q*4+2] - bj.z);
            float d3 = fabsf(sbx[q*4+3] - bj.w);
            ull a0 = pack2(d0, d0), a1 = pack2(d1, d1);
            ull a2 = pack2(d2, d2), a3 = pack2(d3, d3);
            float sum = 0.f;
            #pragma unroll
            for (int p = 0; p < 4; p++) {
                ull t2 = add2v(sp1q[q][p], p2v[p]);
                t2 = fma2v(a0, wg2[0][p], t2);
                t2 = fma2v(a1, wg2[1][p], t2);
                t2 = fma2v(a2, wg2[2][p], t2);
                t2 = fma2v(a3, wg2[3][p], t2);
                float tl, th;
                unpack2(t2, tl, th);
                tl = fmaxf(tl, 0.f);
                th = fmaxf(th, 0.f);
                sum = fmaf(tl, w2lo[p], sum);
                sum = fmaf(th, w2hi[p], sum);
            }
            #pragma unroll
            for (int o = 16; o; o >>= 1) sum += __shfl_down_sync(0xffffffffu, sum, o);
            if (lane == 0)
                srow[q][j] = sum - ((j == i0 + q) ? 1e6f : 0.f);
        }
    }
    __syncthreads();

    if (warp < 2) {
        int q = warp, i = i0 + q;
        for (int sel2 = 0; sel2 < TOPKK; sel2++) {
            float bv = -3.4e38f; int bi = 1 << 30;
            for (int j = lane; j < NN; j += 32) {
                float v = srow[q][j];
                if (v > bv || (v == bv && j < bi)) { bv = v; bi = j; }
            }
            #pragma unroll
            for (int o = 16; o; o >>= 1) {
                float ov = __shfl_xor_sync(0xffffffffu, bv, o);
                int   oi = __shfl_xor_sync(0xffffffffu, bi, o);
                if (ov > bv || (ov == bv && oi < bi)) { bv = ov; bi = oi; }
            }
            if (lane == 0) {
                g_nbr[(b*NN + i)*TOPKK + sel2] = bi;
                srow[q][bi] = -3.4e38f;
            }
            __syncwarp();
        }
    }
}

// -------- GAT1: warp-shfl scan build + softmax + float4 aggregate + xw2 ------
__global__ __launch_bounds__(256) void k_gat1(
    const float* __restrict__ gat1_b,
    const float* __restrict__ gat2_w,
    const float* __restrict__ att_src2,
    const float* __restrict__ att_dst2)
{
    int bn = blockIdx.x; int b = bn / NN, tt = bn % NN;
    __shared__ int   ssrc[MAXDEG];
    __shared__ float sal[NHEADS][MAXDEG];
    __shared__ float sas1[NN*4];
    __shared__ int   wtot[8];
    __shared__ float red[8][2];
    int tid = threadIdx.x;
    int warp = tid >> 5, lane = tid & 31;

    #pragma unroll
    for (int it = 0; it < 6; it++)
        sas1[tid + it*256] = g_as1[b*NN*4 + tid + it*256];

    // ---- build: warp-shfl prefix scan (2 syncs total) ----
    const int* nb = g_nbr + b*NN*TOPKK;
    int myc0 = 0, myc1 = 0;
    int ia = 2*tid, ib2 = 2*tid + 1;
    if (tid < 192) {
        #pragma unroll
        for (int k = 0; k < TOPKK; k++) {
            myc0 += (nb[ia*TOPKK + k] == tt);
            myc1 += (nb[ib2*TOPKK + k] == tt);
        }
    }
    int cnt = myc0 + myc1;
    int incl = cnt;
    #pragma unroll
    for (int d = 1; d < 32; d <<= 1) {
        int v = __shfl_up_sync(0xffffffffu, incl, d);
        if (lane >= d) incl += v;
    }
    if (lane == 31) wtot[warp] = incl;
    __syncthreads();
    int woff = 0, total = 0;
    #pragma unroll
    for (int w = 0; w < 8; w++) {
        int v = wtot[w];
        if (w < warp) woff += v;
        total += v;
    }
    int off = woff + incl - cnt;   // exclusive prefix, tid-ordered
    int* dst = g_srcl + bn*MAXDEG;
    if (tid < 192) {
        if (myc0) {
            #pragma unroll
            for (int k = 0; k < TOPKK; k++)
                if (nb[ia*TOPKK + k] == tt) { ssrc[off] = ia; dst[off] = ia; off++; }
        }
        if (myc1) {
            #pragma unroll
            for (int k = 0; k < TOPKK; k++)
                if (nb[ib2*TOPKK + k] == tt) { ssrc[off] = ib2; dst[off] = ib2; off++; }
        }
    }
    if (tid == 0) {
        ssrc[total] = tt;
        dst[total] = tt;
        g_deg[bn] = total + 1;
    }
    __syncthreads();
    int deg = total + 1;

    // ---- softmax (warp h handles head h; as1 from smem) ----
    if (warp < NHEADS) {
        int h = warp;
        float adv = g_ad1[bn*4 + h];
        float m = -3.4e38f;
        for (int s = lane; s < deg; s += 32) {
            float e = sas1[ssrc[s]*4 + h] + adv;
            e = (e >= 0.f) ? e : 0.2f*e;
            sal[h][s] = e;
            m = fmaxf(m, e);
        }
        #pragma unroll
        for (int o = 16; o; o >>= 1) m = fmaxf(m, __shfl_xor_sync(0xffffffffu, m, o));
        float sum = 0.f;
        for (int s = lane; s < deg; s += 32) {
            float ex = expf(sal[h][s] - m);
            sal[h][s] = ex;
            sum += ex;
        }
        #pragma unroll
        for (int o = 16; o; o >>= 1) sum += __shfl_xor_sync(0xffffffffu, sum, o);
        float inv = 1.f / fmaxf(sum, 1e-16f);
        for (int s = lane; s < deg; s += 32) sal[h][s] *= inv;
    }
    __syncthreads();

    // ---- aggregate: thread owns 4 contiguous cols (float4), h = tid>>6 ----
    const float* xwb = g_xw1 + b*NN*1024;
    const float* salh = sal[tid >> 6];
    float4 acc0 = make_float4(0.f, 0.f, 0.f, 0.f);
    float4 acc1 = make_float4(0.f, 0.f, 0.f, 0.f);
    int col4 = tid * 4;
    int s = 0;
    for (; s + 1 < deg; s += 2) {
        float4 v0 = *(const float4*)&xwb[ssrc[s  ]*1024 + col4];
        float4 v1 = *(const float4*)&xwb[ssrc[s+1]*1024 + col4];
        float a0 = salh[s], a1 = salh[s+1];
        acc0.x = fmaf(v0.x, a0, acc0.x); acc0.y = fmaf(v0.y, a0, acc0.y);
        acc0.z = fmaf(v0.z, a0, acc0.z); acc0.w = fmaf(v0.w, a0, acc0.w);
        acc1.x = fmaf(v1.x, a1, acc1.x); acc1.y = fmaf(v1.y, a1, acc1.y);
        acc1.z = fmaf(v1.z, a1, acc1.z); acc1.w = fmaf(v1.w, a1, acc1.w);
    }
    if (s < deg) {
        float4 v0 = *(const float4*)&xwb[ssrc[s]*1024 + col4];
        float a0 = salh[s];
        acc0.x = fmaf(v0.x, a0, acc0.x); acc0.y = fmaf(v0.y, a0, acc0.y);
        acc0.z = fmaf(v0.z, a0, acc0.z); acc0.w = fmaf(v0.w, a0, acc0.w);
    }
    float4 bia = *(const float4*)&gat1_b[col4];
    float4 oh;
    oh.x = fmaxf(acc0.x + acc1.x + bia.x, 0.f);
    oh.y = fmaxf(acc0.y + acc1.y + bia.y, 0.f);
    oh.z = fmaxf(acc0.z + acc1.z + bia.z, 0.f);
    oh.w = fmaxf(acc0.w + acc1.w + bia.w, 0.f);

    // ---- fused xw2 = h1 @ gat2_w  (block reduction) ----
    float4 w0 = *(const float4*)&gat2_w[col4*2];
    float4 w1 = *(const float4*)&gat2_w[col4*2 + 4];
    float c0 = oh.x*w0.x + oh.y*w0.z + oh.z*w1.x + oh.w*w1.z;
    float c1 = oh.x*w0.y + oh.y*w0.w + oh.z*w1.y + oh.w*w1.w;
    #pragma unroll
    for (int o = 16; o; o >>= 1) {
        c0 += __shfl_down_sync(0xffffffffu, c0, o);
        c1 += __shfl_down_sync(0xffffffffu, c1, o);
    }
    if (lane == 0) { red[warp][0] = c0; red[warp][1] = c1; }
    __syncthreads();
    if (tid == 0) {
        float s0 = 0.f, s1 = 0.f;
        #pragma unroll
        for (int w = 0; w < 8; w++) { s0 += red[w][0]; s1 += red[w][1]; }
        g_xw2[bn*2 + 0] = s0;
        g_xw2[bn*2 + 1] = s1;
        g_as2[bn] = s0*att_src2[0] + s1*att_src2[1];
        g_ad2[bn] = s0*att_dst2[0] + s1*att_dst2[1];
    }
}

// ------- GAT layer 2: 8 nodes/block, batch as2/xw2 preloaded into smem -------
__global__ __launch_bounds__(256) void k_gat2(const float* __restrict__ gat2_b,
                                              float* __restrict__ out)
{
    __shared__ float s_as2[NN];
    __shared__ float s_xw2[NN*2];
    __shared__ float sal[8][MAXDEG];
    __shared__ int   ssrc[8][MAXDEG];
    int tid = threadIdx.x;
    int warp = tid >> 5, lane = tid & 31;
    int n0 = blockIdx.x * 8;
    int b = n0 / NN;

    for (int i = tid; i < NN; i += 256)   s_as2[i] = g_as2[b*NN + i];
    for (int i = tid; i < NN*2; i += 256) s_xw2[i] = g_xw2[b*NN*2 + i];
    __syncthreads();

    int bn = n0 + warp;
    int deg = g_deg[bn];
    for (int s = lane; s < deg; s += 32) ssrc[warp][s] = g_srcl[bn*MAXDEG + s];
    __syncwarp();
    float adv = g_ad2[bn];
    float m = -3.4e38f;
    for (int s = lane; s < deg; s += 32) {
        float e = s_as2[ssrc[warp][s]] + adv;
        e = (e >= 0.f) ? e : 0.2f*e;
        sal[warp][s] = e;
        m = fmaxf(m, e);
    }
    #pragma unroll
    for (int o = 16; o; o >>= 1) m = fmaxf(m, __shfl_xor_sync(0xffffffffu, m, o));
    float sum = 0.f;
    for (int s = lane; s < deg; s += 32) {
        float ex = expf(sal[warp][s] - m);
        sal[warp][s] = ex;
        sum += ex;
    }
    #pragma unroll
    for (int o = 16; o; o >>= 1) sum += __shfl_xor_sync(0xffffffffu, sum, o);
    float inv = 1.f / fmaxf(sum, 1e-16f);
    __syncwarp();
    float a0 = 0.f, a1 = 0.f;
    for (int s = lane; s < deg; s += 32) {
        float w = sal[warp][s] * inv;
        int sc = ssrc[warp][s];
        a0 = fmaf(s_xw2[sc*2 + 0], w, a0);
        a1 = fmaf(s_xw2[sc*2 + 1], w, a1);
    }
    #pragma unroll
    for (int o = 16; o; o >>= 1) {
        a0 += __shfl_down_sync(0xffffffffu, a0, o);
        a1 += __shfl_down_sync(0xffffffffu, a1, o);
    }
    if (lane == 0) {
        out[bn*2 + 0] = a0 + gat2_b[0];
        out[bn*2 + 1] = a1 + gat2_b[1];
    }
}

// ---------------- launch ------------------------------------------------------
extern "C" void kernel_launch(void* const* d_in, const int* in_sizes, int n_in,
                              void* d_out, int out_size)
{
    const float* feats   = (const float*)d_in[0];
    const float* boxes   = (const float*)d_in[1];
    const float* fc1_w   = (const float*)d_in[2];
    const float* fc1_b   = (const float*)d_in[3];
    const float* fc2_w   = (const float*)d_in[4];
    // d_in[5] = fc2_b : constant shift, irrelevant for top-k
    const float* gat1_w  = (const float*)d_in[6];
    const float* g1as    = (const float*)d_in[7];
    const float* g1ad    = (const float*)d_in[8];
    const float* gat1_b  = (const float*)d_in[9];
    const float* gat2_w  = (const float*)d_in[10];
    const float* g2as    = (const float*)d_in[11];
    const float* g2ad    = (const float*)d_in[12];
    const float* gat2_b  = (const float*)d_in[13];
    float* out = (float*)d_out;

    k_gemms   <<<144, 256>>>(feats, fc1_w, gat1_w, boxes);
    k_rel_asad<<<768, 256>>>(boxes, fc1_w, fc1_b, fc2_w, g1as, g1ad);
    k_gat1    <<<BB*NN, 256>>>(gat1_b, gat2_w, g2as, g2ad);
    k_gat2    <<<96, 256>>>(gat2_b, out);
    (void)in_sizes; (void)n_in; (void)out_size;
}

// round 12
// speedup vs baseline: 1.4044x; 1.1878x over previous
#include <cuda_runtime.h>
#include <math.h>

#define BB 2
#define NN 384
#define CC 1024
#define HREPN 256
#define GHID 256
#define NHEADS 4
#define TOPKK 8
#define MAXDEG 400

typedef unsigned long long ull;

// ---------------- scratch (device globals; no allocation allowed) ------------
__device__ __align__(16) float g_p1 [BB*NN*HREPN];
__device__ __align__(16) float g_p2 [BB*NN*HREPN];
__device__ __align__(16) float g_xw1[BB*NN*NHEADS*GHID];
__device__ float g_as1[BB*NN*NHEADS];
__device__ float g_ad1[BB*NN*NHEADS];
__device__ int   g_nbr[BB*NN*TOPKK];
__device__ int   g_srcl[BB*NN*MAXDEG];
__device__ int   g_deg [BB*NN];
__device__ float g_xw2[BB*NN*2];
__device__ float g_as2[BB*NN];
__device__ float g_ad2[BB*NN];

// ---------------- f32x2 helpers ----------------------------------------------
__device__ __forceinline__ void ffma2(ull &d, ull a, ull b) {
    asm("fma.rn.f32x2 %0, %1, %2, %0;" : "+l"(d) : "l"(a), "l"(b));
}
__device__ __forceinline__ ull fma2v(ull a, ull b, ull c) {
    ull r; asm("fma.rn.f32x2 %0, %1, %2, %3;" : "=l"(r) : "l"(a), "l"(b), "l"(c)); return r;
}
__device__ __forceinline__ ull add2v(ull a, ull b) {
    ull r; asm("add.rn.f32x2 %0, %1, %2;" : "=l"(r) : "l"(a), "l"(b)); return r;
}
__device__ __forceinline__ ull pack2(float lo, float hi) {
    ull r; asm("mov.b64 %0, {%1, %2};" : "=l"(r) : "f"(lo), "f"(hi)); return r;
}
__device__ __forceinline__ void unpack2(ull v, float &lo, float &hi) {
    asm("mov.b64 {%0, %1}, %2;" : "=f"(lo), "=f"(hi) : "l"(v));
}
__device__ __forceinline__ float lo2(ull v) { return __uint_as_float((unsigned)(v & 0xffffffffull)); }
__device__ __forceinline__ float hi2(ull v) { return __uint_as_float((unsigned)(v >> 32)); }

// -------- fused SGEMM: 128x64 tiles, 256 thr, intra-block K-split ------------
// (exact R7 kernel — proven 143.4 configuration)
__global__ __launch_bounds__(256, 1) void k_gemms(
    const float* __restrict__ feats,
    const float* __restrict__ fc1_w,
    const float* __restrict__ gat1_w,
    const float* __restrict__ boxes)
{
    __shared__ float As[2][2][128*20];   // [khalf][buf][row*20+k]
    __shared__ float Bs[2][2][64*20];    // [khalf][buf][col*20+k]
    __shared__ float Wg4[4*64];

    int tid = threadIdx.x;
    int khalf = tid >> 7;          // 0 or 1
    int htid  = tid & 127;
    int bid = blockIdx.x;
    int sel, b, by, bx;
    if (bid < 48) { sel = 0; b = bid / 24; int r = bid % 24; by = r / 8;  bx = r % 8;  }
    else { sel = 1; int r = bid - 48; b = r / 48; r %= 48;   by = r / 16; bx = r % 16; }

    int row0 = by * 128, col0 = bx * 64;

    const float* Bm; float* Cm;
    int ldb, Nc, dcol0;
    if (sel == 0) {
        ldb = 256; Nc = 256;
        if (col0 < 256) { Bm = fc1_w;            Cm = g_p1 + b*NN*256; dcol0 = col0; }
        else            { Bm = fc1_w + 1024*256; Cm = g_p2 + b*NN*256; dcol0 = col0 - 256; }
    } else {
        ldb = 1024; Nc = 1024; Bm = gat1_w; Cm = g_xw1 + b*NN*1024; dcol0 = col0;
        Wg4[tid] = gat1_w[(1024 + (tid >> 6))*1024 + col0 + (tid & 63)];
    }

    int tx = htid & 7, ty = htid >> 3;      // 8 x 16 thread grid per half
    ull acc[8][8];
    #pragma unroll
    for (int r = 0; r < 8; r++)
        #pragma unroll
        for (int j = 0; j < 8; j++) acc[r][j] = 0ull;

    int arow = htid >> 2, aslot = htid & 3;   // A loader: rows arow+32m
    int bc = htid & 63, bk = htid >> 6;       // B loader: col bc, k's bk*8..+7

    int kbase = khalf * 512;
    const float* ApB = feats + b*NN*CC + (row0 + arow)*1024 + kbase + aslot*4;
    const float* Bp  = Bm + (ull)kbase*ldb + dcol0 + bc;

    float4 pa[4]; float pb[8];
    #pragma unroll
    for (int m = 0; m < 4; m++) pa[m] = *(const float4*)(ApB + m*32*1024);
    #pragma unroll
    for (int m = 0; m < 8; m++) pb[m] = Bp[(bk*8 + m)*ldb];
    #pragma unroll
    for (int m = 0; m < 4; m++) *(float4*)&As[khalf][0][(arow + 32*m)*20 + aslot*4] = pa[m];
    #pragma unroll
    for (int m = 0; m < 8; m++) Bs[khalf][0][bc*20 + bk*8 + m] = pb[m];
    __syncthreads();

    for (int t = 0; t < 32; t++) {
        int cur = t & 1, nxt = cur ^ 1;
        if (t < 31) {
            int k0 = (t + 1) * 16;
            #pragma unroll
            for (int m = 0; m < 4; m++) pa[m] = *(const float4*)(ApB + m*32*1024 + k0);
            #pragma unroll
            for (int m = 0; m < 8; m++) pb[m] = Bp[(k0 + bk*8 + m)*ldb];
        }
        #pragma unroll
        for (int kp = 0; kp < 8; kp++) {
            ull av[8], bv[8];
            #pragma unroll
            for (int r = 0; r < 8; r++)
                av[r] = *(const ull*)&As[khalf][cur][(ty + 16*r)*20 + 2*kp];
            #pragma unroll
            for (int j = 0; j < 8; j++)
                bv[j] = *(const ull*)&Bs[khalf][cur][(tx + 8*j)*20 + 2*kp];
            #pragma unroll
            for (int r = 0; r < 8; r++)
                #pragma unroll
                for (int j = 0; j < 8; j++) ffma2(acc[r][j], av[r], bv[j]);
        }
        if (t < 31) {
            #pragma unroll
            for (int m = 0; m < 4; m++) *(float4*)&As[khalf][nxt][(arow + 32*m)*20 + aslot*4] = pa[m];
            #pragma unroll
            for (int m = 0; m < 8; m++) Bs[khalf][nxt][bc*20 + bk*8 + m] = pb[m];
        }
        __syncthreads();
    }

    // ---- combine halves via padded smem (stride 65: bank-conflict-free) ----
    float* comb = (float*)As;
    if (khalf == 1) {
        #pragma unroll
        for (int r = 0; r < 8; r++)
            #pragma unroll
            for (int j = 0; j < 8; j++)
                comb[htid*65 + r*8 + j] = lo2(acc[r][j]) + hi2(acc[r][j]);
    }
    __syncthreads();
    if (khalf == 0) {
        #pragma unroll
        for (int r = 0; r < 8; r++) {
            int row = row0 + ty + 16*r;
            float g0 = 0.f, g1 = 0.f, g2 = 0.f, g3 = 0.f;
            if (sel == 1) {
                const float* bx4 = boxes + (b*NN + row)*4;
                float x0 = bx4[0]*(1.0f/800.0f), y0 = bx4[1]*(1.0f/800.0f);
                float x1 = bx4[2]*(1.0f/800.0f), y1 = bx4[3]*(1.0f/800.0f);
                g0 = x0; g1 = y0; g2 = x1 - x0; g3 = y1 - y0;
            }
            #pragma unroll
            for (int j = 0; j < 8; j++) {
                int c = tx + 8*j;
                float s = (lo2(acc[r][j]) + hi2(acc[r][j])) + comb[htid*65 + r*8 + j];
                if (sel == 1) {
                    s = fmaf(g0, Wg4[0*64 + c], s);
                    s = fmaf(g1, Wg4[1*64 + c], s);
                    s = fmaf(g2, Wg4[2*64 + c], s);
                    s = fmaf(g3, Wg4[3*64 + c], s);
                }
                Cm[row*Nc + dcol0 + c] = s;
            }
        }
    }
}

// ------- merged: relation scores + top-8 (blocks 0..191)  |  asad (192..575) -
// (exact R7 kernel)
__global__ __launch_bounds__(256) void k_rel_asad(
    const float* __restrict__ boxes,
    const float* __restrict__ fc1_w,
    const float* __restrict__ fc1_b,
    const float* __restrict__ fc2_w,
    const float* __restrict__ att_src,
    const float* __restrict__ att_dst)
{
    __shared__ float srow[4][NN];
    __shared__ float sbx[16];
    int bid = blockIdx.x;
    int tid = threadIdx.x, warp = tid >> 5, lane = tid & 31;

    if (bid >= 192) {
        int bn = (bid - 192)*2 + (tid >> 7);
        int h = (tid >> 5) & 3;
        const float* xw = g_xw1 + bn*1024 + h*256 + lane*8;
        float4 v0 = *(const float4*)xw;
        float4 v1 = *(const float4*)(xw + 4);
        const float* asr = att_src + h*256 + lane*8;
        const float* adr = att_dst + h*256 + lane*8;
        float4 s0 = *(const float4*)asr;
        float4 s1 = *(const float4*)(asr + 4);
        float4 d0 = *(const float4*)adr;
        float4 d1 = *(const float4*)(adr + 4);
        float ss = v0.x*s0.x + v0.y*s0.y + v0.z*s0.z + v0.w*s0.w
                 + v1.x*s1.x + v1.y*s1.y + v1.z*s1.z + v1.w*s1.w;
        float dd = v0.x*d0.x + v0.y*d0.y + v0.z*d0.z + v0.w*d0.w
                 + v1.x*d1.x + v1.y*d1.y + v1.z*d1.z + v1.w*d1.w;
        #pragma unroll
        for (int o = 16; o; o >>= 1) {
            ss += __shfl_down_sync(0xffffffffu, ss, o);
            dd += __shfl_down_sync(0xffffffffu, dd, o);
        }
        if (lane == 0) { g_as1[bn*4 + h] = ss; g_ad1[bn*4 + h] = dd; }
        return;
    }

    int b = bid / 96, igrp = bid % 96;
    int i0 = igrp * 4;

    if (tid < 16) sbx[tid] = boxes[(b*NN + i0 + (tid >> 2))*4 + (tid & 3)];

    ull wg2[4][4], sp1q[4][4];
    float w2lo[4], w2hi[4];
    #pragma unroll
    for (int p = 0; p < 4; p++) {
        int k0 = lane + 64*p, k1 = k0 + 32;
        w2lo[p] = fc2_w[k0];
        w2hi[p] = fc2_w[k1];
        #pragma unroll
        for (int d = 0; d < 4; d++)
            wg2[d][p] = pack2(fc1_w[(2048+d)*256 + k0], fc1_w[(2048+d)*256 + k1]);
        float b0 = fc1_b[k0], b1 = fc1_b[k1];
        #pragma unroll
        for (int q = 0; q < 4; q++) {
            const float* p1r = g_p1 + (b*NN + i0 + q)*256;
            sp1q[q][p] = pack2(p1r[k0] + b0, p1r[k1] + b1);
        }
    }
    __syncthreads();

    const float* p2b = g_p2 + b*NN*256;
    const float* bxb = boxes + b*NN*4;

    for (int j = warp; j < NN; j += 8) {
        float4 bj = *(const float4*)&bxb[j*4];
        ull p2v[4];
        #pragma unroll
        for (int p = 0; p < 4; p++) {
            int k0 = lane + 64*p;
            p2v[p] = pack2(p2b[j*256 + k0], p2b[j*256 + k0 + 32]);
        }
        #pragma unroll
        for (int q = 0; q < 4; q++) {
            float d0 = fabsf(sbx[q*4+0] - bj.x);
            float d1 = fabsf(sbx[q*4+1] - bj.y);
            float d2 = fabsf(sbx[q*4+2] - bj.z);
            float d3 = fabsf(sbx[q*4+3] - bj.w);
            ull a0 = pack2(d0, d0), a1 = pack2(d1, d1);
            ull a2 = pack2(d2, d2), a3 = pack2(d3, d3);
            float sum = 0.f;
            #pragma unroll
            for (int p = 0; p < 4; p++) {
                ull t2 = add2v(sp1q[q][p], p2v[p]);
                t2 = fma2v(a0, wg2[0][p], t2);
                t2 = fma2v(a1, wg2[1][p], t2);
                t2 = fma2v(a2, wg2[2][p], t2);
                t2 = fma2v(a3, wg2[3][p], t2);
                float tl, th;
                unpack2(t2, tl, th);
                tl = fmaxf(tl, 0.f);
                th = fmaxf(th, 0.f);
                sum = fmaf(tl, w2lo[p], sum);
                sum = fmaf(th, w2hi[p], sum);
            }
            #pragma unroll
            for (int o = 16; o; o >>= 1) sum += __shfl_down_sync(0xffffffffu, sum, o);
            if (lane == 0)
                srow[q][j] = sum - ((j == i0 + q) ? 1e6f : 0.f);
        }
    }
    __syncthreads();

    if (warp < 4) {
        int q = warp, i = i0 + q;
        for (int sel2 = 0; sel2 < TOPKK; sel2++) {
            float bv = -3.4e38f; int bi = 1 << 30;
            for (int j = lane; j < NN; j += 32) {
                float v = srow[q][j];
                if (v > bv || (v == bv && j < bi)) { bv = v; bi = j; }
            }
            #pragma unroll
            for (int o = 16; o; o >>= 1) {
                float ov = __shfl_xor_sync(0xffffffffu, bv, o);
                int   oi = __shfl_xor_sync(0xffffffffu, bi, o);
                if (ov > bv || (ov == bv && oi < bi)) { bv = ov; bi = oi; }
            }
            if (lane == 0) {
                g_nbr[(b*NN + i)*TOPKK + sel2] = bi;
                srow[q][bi] = -3.4e38f;
            }
            __syncwarp();
        }
    }
}

// -------- GAT1: warp-shfl scan build + softmax + float4 aggregate + xw2 ------
// (R7 kernel with ONLY the scan replaced by the R11-validated warp-shfl scan)
__global__ __launch_bounds__(256) void k_gat1(
    const float* __restrict__ gat1_b,
    const float* __restrict__ gat2_w,
    const float* __restrict__ att_src2,
    const float* __restrict__ att_dst2)
{
    int bn = blockIdx.x; int b = bn / NN, tt = bn % NN;
    __shared__ int   ssrc[MAXDEG];
    __shared__ float sal[NHEADS][MAXDEG];
    __shared__ float sas1[NN*4];
    __shared__ int   wtot[8];
    __shared__ float red[8][2];
    int tid = threadIdx.x;
    int warp = tid >> 5, lane = tid & 31;

    #pragma unroll
    for (int it = 0; it < 6; it++)
        sas1[tid + it*256] = g_as1[b*NN*4 + tid + it*256];

    // ---- build: warp-shfl prefix scan (2 syncs total) ----
    const int* nb = g_nbr + b*NN*TOPKK;
    int myc0 = 0, myc1 = 0;
    int ia = 2*tid, ib2 = 2*tid + 1;
    if (tid < 192) {
        #pragma unroll
        for (int k = 0; k < TOPKK; k++) {
            myc0 += (nb[ia*TOPKK + k] == tt);
            myc1 += (nb[ib2*TOPKK + k] == tt);
        }
    }
    int cnt = myc0 + myc1;
    int incl = cnt;
    #pragma unroll
    for (int d = 1; d < 32; d <<= 1) {
        int v = __shfl_up_sync(0xffffffffu, incl, d);
        if (lane >= d) incl += v;
    }
    if (lane == 31) wtot[warp] = incl;
    __syncthreads();
    int woff = 0, total = 0;
    #pragma unroll
    for (int w = 0; w < 8; w++) {
        int v = wtot[w];
        if (w < warp) woff += v;
        total += v;
    }
    int off = woff + incl - cnt;   // exclusive prefix, tid-ordered
    int* dst = g_srcl + bn*MAXDEG;
    if (tid < 192) {
        if (myc0) {
            #pragma unroll
            for (int k = 0; k < TOPKK; k++)
                if (nb[ia*TOPKK + k] == tt) { ssrc[off] = ia; dst[off] = ia; off++; }
        }
        if (myc1) {
            #pragma unroll
            for (int k = 0; k < TOPKK; k++)
                if (nb[ib2*TOPKK + k] == tt) { ssrc[off] = ib2; dst[off] = ib2; off++; }
        }
    }
    if (tid == 0) {
        ssrc[total] = tt;
        dst[total] = tt;
        g_deg[bn] = total + 1;
    }
    __syncthreads();
    int deg = total + 1;

    // ---- softmax (warp h handles head h; as1 from smem) ----
    if (warp < NHEADS) {
        int h = warp;
        float adv = g_ad1[bn*4 + h];
        float m = -3.4e38f;
        for (int s = lane; s < deg; s += 32) {
            float e = sas1[ssrc[s]*4 + h] + adv;
            e = (e >= 0.f) ? e : 0.2f*e;
            sal[h][s] = e;
            m = fmaxf(m, e);
        }
        #pragma unroll
        for (int o = 16; o; o >>= 1) m = fmaxf(m, __shfl_xor_sync(0xffffffffu, m, o));
        float sum = 0.f;
        for (int s = lane; s < deg; s += 32) {
            float ex = expf(sal[h][s] - m);
            sal[h][s] = ex;
            sum += ex;
        }
        #pragma unroll
        for (int o = 16; o; o >>= 1) sum += __shfl_xor_sync(0xffffffffu, sum, o);
        float inv = 1.f / fmaxf(sum, 1e-16f);
        for (int s = lane; s < deg; s += 32) sal[h][s] *= inv;
    }
    __syncthreads();

    // ---- aggregate: thread owns 4 contiguous cols (float4), h = tid>>6 ----
    const float* xwb = g_xw1 + b*NN*1024;
    const float* salh = sal[tid >> 6];
    float4 acc0 = make_float4(0.f, 0.f, 0.f, 0.f);
    float4 acc1 = make_float4(0.f, 0.f, 0.f, 0.f);
    int col4 = tid * 4;
    int s = 0;
    for (; s + 1 < deg; s += 2) {
        float4 v0 = *(const float4*)&xwb[ssrc[s  ]*1024 + col4];
        float4 v1 = *(const float4*)&xwb[ssrc[s+1]*1024 + col4];
        float a0 = salh[s], a1 = salh[s+1];
        acc0.x = fmaf(v0.x, a0, acc0.x); acc0.y = fmaf(v0.y, a0, acc0.y);
        acc0.z = fmaf(v0.z, a0, acc0.z); acc0.w = fmaf(v0.w, a0, acc0.w);
        acc1.x = fmaf(v1.x, a1, acc1.x); acc1.y = fmaf(v1.y, a1, acc1.y);
        acc1.z = fmaf(v1.z, a1, acc1.z); acc1.w = fmaf(v1.w, a1, acc1.w);
    }
    if (s < deg) {
        float4 v0 = *(const float4*)&xwb[ssrc[s]*1024 + col4];
        float a0 = salh[s];
        acc0.x = fmaf(v0.x, a0, acc0.x); acc0.y = fmaf(v0.y, a0, acc0.y);
        acc0.z = fmaf(v0.z, a0, acc0.z); acc0.w = fmaf(v0.w, a0, acc0.w);
    }
    float4 bia = *(const float4*)&gat1_b[col4];
    float4 oh;
    oh.x = fmaxf(acc0.x + acc1.x + bia.x, 0.f);
    oh.y = fmaxf(acc0.y + acc1.y + bia.y, 0.f);
    oh.z = fmaxf(acc0.z + acc1.z + bia.z, 0.f);
    oh.w = fmaxf(acc0.w + acc1.w + bia.w, 0.f);

    // ---- fused xw2 = h1 @ gat2_w  (block reduction) ----
    float4 w0 = *(const float4*)&gat2_w[col4*2];
    float4 w1 = *(const float4*)&gat2_w[col4*2 + 4];
    float c0 = oh.x*w0.x + oh.y*w0.z + oh.z*w1.x + oh.w*w1.z;
    float c1 = oh.x*w0.y + oh.y*w0.w + oh.z*w1.y + oh.w*w1.w;
    #pragma unroll
    for (int o = 16; o; o >>= 1) {
        c0 += __shfl_down_sync(0xffffffffu, c0, o);
        c1 += __shfl_down_sync(0xffffffffu, c1, o);
    }
    if (lane == 0) { red[warp][0] = c0; red[warp][1] = c1; }
    __syncthreads();
    if (tid == 0) {
        float s0 = 0.f, s1 = 0.f;
        #pragma unroll
        for (int w = 0; w < 8; w++) { s0 += red[w][0]; s1 += red[w][1]; }
        g_xw2[bn*2 + 0] = s0;
        g_xw2[bn*2 + 1] = s1;
        g_as2[bn] = s0*att_src2[0] + s1*att_src2[1];
        g_ad2[bn] = s0*att_dst2[0] + s1*att_dst2[1];
    }
}

// ------- GAT layer 2: 8 nodes/block, batch as2/xw2 preloaded into smem -------
// (exact R7 kernel)
__global__ __launch_bounds__(256) void k_gat2(const float* __restrict__ gat2_b,
                                              float* __restrict__ out)
{
    __shared__ float s_as2[NN];
    __shared__ float s_xw2[NN*2];
    __shared__ float sal[8][MAXDEG];
    __shared__ int   ssrc[8][MAXDEG];
    int tid = threadIdx.x;
    int warp = tid >> 5, lane = tid & 31;
    int n0 = blockIdx.x * 8;
    int b = n0 / NN;

    for (int i = tid; i < NN; i += 256)   s_as2[i] = g_as2[b*NN + i];
    for (int i = tid; i < NN*2; i += 256) s_xw2[i] = g_xw2[b*NN*2 + i];
    __syncthreads();

    int bn = n0 + warp;
    int deg = g_deg[bn];
    for (int s = lane; s < deg; s += 32) ssrc[warp][s] = g_srcl[bn*MAXDEG + s];
    __syncwarp();
    float adv = g_ad2[bn];
    float m = -3.4e38f;
    for (int s = lane; s < deg; s += 32) {
        float e = s_as2[ssrc[warp][s]] + adv;
        e = (e >= 0.f) ? e : 0.2f*e;
        sal[warp][s] = e;
        m = fmaxf(m, e);
    }
    #pragma unroll
    for (int o = 16; o; o >>= 1) m = fmaxf(m, __shfl_xor_sync(0xffffffffu, m, o));
    float sum = 0.f;
    for (int s = lane; s < deg; s += 32) {
        float ex = expf(sal[warp][s] - m);
        sal[warp][s] = ex;
        sum += ex;
    }
    #pragma unroll
    for (int o = 16; o; o >>= 1) sum += __shfl_xor_sync(0xffffffffu, sum, o);
    float inv = 1.f / fmaxf(sum, 1e-16f);
    __syncwarp();
    float a0 = 0.f, a1 = 0.f;
    for (int s = lane; s < deg; s += 32) {
        float w = sal[warp][s] * inv;
        int sc = ssrc[warp][s];
        a0 = fmaf(s_xw2[sc*2 + 0], w, a0);
        a1 = fmaf(s_xw2[sc*2 + 1], w, a1);
    }
    #pragma unroll
    for (int o = 16; o; o >>= 1) {
        a0 += __shfl_down_sync(0xffffffffu, a0, o);
        a1 += __shfl_down_sync(0xffffffffu, a1, o);
    }
    if (lane == 0) {
        out[bn*2 + 0] = a0 + gat2_b[0];
        out[bn*2 + 1] = a1 + gat2_b[1];
    }
}

// ---------------- launch ------------------------------------------------------
extern "C" void kernel_launch(void* const* d_in, const int* in_sizes, int n_in,
                              void* d_out, int out_size)
{
    const float* feats   = (const float*)d_in[0];
    const float* boxes   = (const float*)d_in[1];
    const float* fc1_w   = (const float*)d_in[2];
    const float* fc1_b   = (const float*)d_in[3];
    const float* fc2_w   = (const float*)d_in[4];
    // d_in[5] = fc2_b : constant shift, irrelevant for top-k
    const float* gat1_w  = (const float*)d_in[6];
    const float* g1as    = (const float*)d_in[7];
    const float* g1ad    = (const float*)d_in[8];
    const float* gat1_b  = (const float*)d_in[9];
    const float* gat2_w  = (const float*)d_in[10];
    const float* g2as    = (const float*)d_in[11];
    const float* g2ad    = (const float*)d_in[12];
    const float* gat2_b  = (const float*)d_in[13];
    float* out = (float*)d_out;

    k_gemms   <<<144, 256>>>(feats, fc1_w, gat1_w, boxes);
    k_rel_asad<<<192 + 384, 256>>>(boxes, fc1_w, fc1_b, fc2_w, g1as, g1ad);
    k_gat1    <<<BB*NN, 256>>>(gat1_b, gat2_w, g2as, g2ad);
    k_gat2    <<<96, 256>>>(gat2_b, out);
    (void)in_sizes; (void)n_in; (void)out_size;
}

// round 13
// speedup vs baseline: 1.4224x; 1.0128x over previous
#include <cuda_runtime.h>
#include <math.h>

#define BB 2
#define NN 384
#define CC 1024
#define HREPN 256
#define GHID 256
#define NHEADS 4
#define TOPKK 8
#define MAXDEG 400

typedef unsigned long long ull;

// ---------------- scratch (device globals; no allocation allowed) ------------
__device__ __align__(16) float g_p1 [BB*NN*HREPN];
__device__ __align__(16) float g_p2 [BB*NN*HREPN];
__device__ __align__(16) float g_xw1[BB*NN*NHEADS*GHID];
__device__ float g_as1[BB*NN*NHEADS];
__device__ float g_ad1[BB*NN*NHEADS];
__device__ int   g_nbr[BB*NN*TOPKK];
__device__ int   g_srcl[BB*NN*MAXDEG];
__device__ int   g_deg [BB*NN];
__device__ float g_xw2[BB*NN*2];
__device__ float g_as2[BB*NN];
__device__ float g_ad2[BB*NN];

// ---------------- f32x2 helpers ----------------------------------------------
__device__ __forceinline__ void ffma2(ull &d, ull a, ull b) {
    asm("fma.rn.f32x2 %0, %1, %2, %0;" : "+l"(d) : "l"(a), "l"(b));
}
__device__ __forceinline__ ull fma2v(ull a, ull b, ull c) {
    ull r; asm("fma.rn.f32x2 %0, %1, %2, %3;" : "=l"(r) : "l"(a), "l"(b), "l"(c)); return r;
}
__device__ __forceinline__ ull add2v(ull a, ull b) {
    ull r; asm("add.rn.f32x2 %0, %1, %2;" : "=l"(r) : "l"(a), "l"(b)); return r;
}
__device__ __forceinline__ ull pack2(float lo, float hi) {
    ull r; asm("mov.b64 %0, {%1, %2};" : "=l"(r) : "f"(lo), "f"(hi)); return r;
}
__device__ __forceinline__ void unpack2(ull v, float &lo, float &hi) {
    asm("mov.b64 {%0, %1}, %2;" : "=f"(lo), "=f"(hi) : "l"(v));
}
__device__ __forceinline__ float lo2(ull v) { return __uint_as_float((unsigned)(v & 0xffffffffull)); }
__device__ __forceinline__ float hi2(ull v) { return __uint_as_float((unsigned)(v >> 32)); }

// ---------------- cp.async helpers -------------------------------------------
__device__ __forceinline__ unsigned sptr(const void* p) {
    return (unsigned)__cvta_generic_to_shared(p);
}
__device__ __forceinline__ void cpa16(unsigned dst, const void* src) {
    asm volatile("cp.async.cg.shared.global [%0], [%1], 16;" :: "r"(dst), "l"(src));
}
__device__ __forceinline__ void cpa4(unsigned dst, const void* src) {
    asm volatile("cp.async.ca.shared.global [%0], [%1], 4;" :: "r"(dst), "l"(src));
}

// -------- fused SGEMM: 128x64 tiles, 256 thr, K-split, cp.async + LDS.128 ----
__global__ __launch_bounds__(256, 1) void k_gemms(
    const float* __restrict__ feats,
    const float* __restrict__ fc1_w,
    const float* __restrict__ gat1_w,
    const float* __restrict__ boxes)
{
    __shared__ float As[2][2][128*20];   // [khalf][buf][row*20+k]
    __shared__ float Bs[2][2][64*20];    // [khalf][buf][col*20+k]
    __shared__ float Wg4[4*64];

    int tid = threadIdx.x;
    int khalf = tid >> 7;          // 0 or 1
    int htid  = tid & 127;
    int bid = blockIdx.x;
    int sel, b, by, bx;
    if (bid < 48) { sel = 0; b = bid / 24; int r = bid % 24; by = r / 8;  bx = r % 8;  }
    else { sel = 1; int r = bid - 48; b = r / 48; r %= 48;   by = r / 16; bx = r % 16; }

    int row0 = by * 128, col0 = bx * 64;

    const float* Bm; float* Cm;
    int ldb, Nc, dcol0;
    if (sel == 0) {
        ldb = 256; Nc = 256;
        if (col0 < 256) { Bm = fc1_w;            Cm = g_p1 + b*NN*256; dcol0 = col0; }
        else            { Bm = fc1_w + 1024*256; Cm = g_p2 + b*NN*256; dcol0 = col0 - 256; }
    } else {
        ldb = 1024; Nc = 1024; Bm = gat1_w; Cm = g_xw1 + b*NN*1024; dcol0 = col0;
        Wg4[tid] = gat1_w[(1024 + (tid >> 6))*1024 + col0 + (tid & 63)];
    }

    int tx = htid & 7, ty = htid >> 3;      // 8 x 16 thread grid per half
    ull acc[8][8];
    #pragma unroll
    for (int r = 0; r < 8; r++)
        #pragma unroll
        for (int j = 0; j < 8; j++) acc[r][j] = 0ull;

    int arow = htid >> 2, aslot = htid & 3;   // A loader: rows arow+32m
    int bc = htid & 63, bk = htid >> 6;       // B loader: col bc, k's bk*8..+7

    int kbase = khalf * 512;
    const float* ApB = feats + b*NN*CC + (row0 + arow)*1024 + kbase + aslot*4;
    const float* Bp  = Bm + (ull)(kbase + bk*8)*ldb + dcol0 + bc;

    unsigned aD = sptr(&As[khalf][0][arow*20 + aslot*4]);   // +m*32*20*4B, +buf*2560*4B
    unsigned bD = sptr(&Bs[khalf][0][bc*20 + bk*8]);        // +m*4B, +buf*1280*4B

    // prologue: async-fetch tile 0 into buffer 0
    #pragma unroll
    for (int m = 0; m < 4; m++) cpa16(aD + m*32*20*4, ApB + m*32*1024);
    #pragma unroll
    for (int m = 0; m < 8; m++) cpa4(bD + m*4, Bp + m*ldb);
    asm volatile("cp.async.commit_group;");

    for (int t = 0; t < 32; t++) {
        int cur = t & 1, nxt = cur ^ 1;
        if (t < 31) {
            int k0 = (t + 1) * 16;
            unsigned aDn = aD + nxt*2560*4;
            unsigned bDn = bD + nxt*1280*4;
            const float* Asrc = ApB + k0;
            const float* Bsrc = Bp + k0*ldb;
            #pragma unroll
            for (int m = 0; m < 4; m++) cpa16(aDn + m*32*20*4, Asrc + m*32*1024);
            #pragma unroll
            for (int m = 0; m < 8; m++) cpa4(bDn + m*4, Bsrc + m*ldb);
            asm volatile("cp.async.commit_group;");
            asm volatile("cp.async.wait_group 1;");
        } else {
            asm volatile("cp.async.wait_group 0;");
        }
        __syncthreads();
        #pragma unroll
        for (int kph = 0; kph < 4; kph++) {
            ulonglong2 av[8], bv[8];
            #pragma unroll
            for (int r = 0; r < 8; r++)
                av[r] = *(const ulonglong2*)&As[khalf][cur][(ty + 16*r)*20 + 4*kph];
            #pragma unroll
            for (int j = 0; j < 8; j++)
                bv[j] = *(const ulonglong2*)&Bs[khalf][cur][(tx + 8*j)*20 + 4*kph];
            #pragma unroll
            for (int r = 0; r < 8; r++)
                #pragma unroll
                for (int j = 0; j < 8; j++) ffma2(acc[r][j], av[r].x, bv[j].x);
            #pragma unroll
            for (int r = 0; r < 8; r++)
                #pragma unroll
                for (int j = 0; j < 8; j++) ffma2(acc[r][j], av[r].y, bv[j].y);
        }
        __syncthreads();
    }

    // ---- combine halves via padded smem (stride 65: bank-conflict-free) ----
    float* comb = (float*)As;
    if (khalf == 1) {
        #pragma unroll
        for (int r = 0; r < 8; r++)
            #pragma unroll
            for (int j = 0; j < 8; j++)
                comb[htid*65 + r*8 + j] = lo2(acc[r][j]) + hi2(acc[r][j]);
    }
    __syncthreads();
    if (khalf == 0) {
        #pragma unroll
        for (int r = 0; r < 8; r++) {
            int row = row0 + ty + 16*r;
            float g0 = 0.f, g1 = 0.f, g2 = 0.f, g3 = 0.f;
            if (sel == 1) {
                const float* bx4 = boxes + (b*NN + row)*4;
                float x0 = bx4[0]*(1.0f/800.0f), y0 = bx4[1]*(1.0f/800.0f);
                float x1 = bx4[2]*(1.0f/800.0f), y1 = bx4[3]*(1.0f/800.0f);
                g0 = x0; g1 = y0; g2 = x1 - x0; g3 = y1 - y0;
            }
            #pragma unroll
            for (int j = 0; j < 8; j++) {
                int c = tx + 8*j;
                float s = (lo2(acc[r][j]) + hi2(acc[r][j])) + comb[htid*65 + r*8 + j];
                if (sel == 1) {
                    s = fmaf(g0, Wg4[0*64 + c], s);
                    s = fmaf(g1, Wg4[1*64 + c], s);
                    s = fmaf(g2, Wg4[2*64 + c], s);
                    s = fmaf(g3, Wg4[3*64 + c], s);
                }
                Cm[row*Nc + dcol0 + c] = s;
            }
        }
    }
}

// ------- merged: relation scores + top-8 (blocks 0..191)  |  asad (192..575) -
// (exact R12 kernel)
__global__ __launch_bounds__(256) void k_rel_asad(
    const float* __restrict__ boxes,
    const float* __restrict__ fc1_w,
    const float* __restrict__ fc1_b,
    const float* __restrict__ fc2_w,
    const float* __restrict__ att_src,
    const float* __restrict__ att_dst)
{
    __shared__ float srow[4][NN];
    __shared__ float sbx[16];
    int bid = blockIdx.x;
    int tid = threadIdx.x, warp = tid >> 5, lane = tid & 31;

    if (bid >= 192) {
        int bn = (bid - 192)*2 + (tid >> 7);
        int h = (tid >> 5) & 3;
        const float* xw = g_xw1 + bn*1024 + h*256 + lane*8;
        float4 v0 = *(const float4*)xw;
        float4 v1 = *(const float4*)(xw + 4);
        const float* asr = att_src + h*256 + lane*8;
        const float* adr = att_dst + h*256 + lane*8;
        float4 s0 = *(const float4*)asr;
        float4 s1 = *(const float4*)(asr + 4);
        float4 d0 = *(const float4*)adr;
        float4 d1 = *(const float4*)(adr + 4);
        float ss = v0.x*s0.x + v0.y*s0.y + v0.z*s0.z + v0.w*s0.w
                 + v1.x*s1.x + v1.y*s1.y + v1.z*s1.z + v1.w*s1.w;
        float dd = v0.x*d0.x + v0.y*d0.y + v0.z*d0.z + v0.w*d0.w
                 + v1.x*d1.x + v1.y*d1.y + v1.z*d1.z + v1.w*d1.w;
        #pragma unroll
        for (int o = 16; o; o >>= 1) {
            ss += __shfl_down_sync(0xffffffffu, ss, o);
            dd += __shfl_down_sync(0xffffffffu, dd, o);
        }
        if (lane == 0) { g_as1[bn*4 + h] = ss; g_ad1[bn*4 + h] = dd; }
        return;
    }

    int b = bid / 96, igrp = bid % 96;
    int i0 = igrp * 4;

    if (tid < 16) sbx[tid] = boxes[(b*NN + i0 + (tid >> 2))*4 + (tid & 3)];

    ull wg2[4][4], sp1q[4][4];
    float w2lo[4], w2hi[4];
    #pragma unroll
    for (int p = 0; p < 4; p++) {
        int k0 = lane + 64*p, k1 = k0 + 32;
        w2lo[p] = fc2_w[k0];
        w2hi[p] = fc2_w[k1];
        #pragma unroll
        for (int d = 0; d < 4; d++)
            wg2[d][p] = pack2(fc1_w[(2048+d)*256 + k0], fc1_w[(2048+d)*256 + k1]);
        float b0 = fc1_b[k0], b1 = fc1_b[k1];
        #pragma unroll
        for (int q = 0; q < 4; q++) {
            const float* p1r = g_p1 + (b*NN + i0 + q)*256;
            sp1q[q][p] = pack2(p1r[k0] + b0, p1r[k1] + b1);
        }
    }
    __syncthreads();

    const float* p2b = g_p2 + b*NN*256;
    const float* bxb = boxes + b*NN*4;

    for (int j = warp; j < NN; j += 8) {
        float4 bj = *(const float4*)&bxb[j*4];
        ull p2v[4];
        #pragma unroll
        for (int p = 0; p < 4; p++) {
            int k0 = lane + 64*p;
            p2v[p] = pack2(p2b[j*256 + k0], p2b[j*256 + k0 + 32]);
        }
        #pragma unroll
        for (int q = 0; q < 4; q++) {
            float d0 = fabsf(sbx[q*4+0] - bj.x);
            float d1 = fabsf(sbx[q*4+1] - bj.y);
            float d2 = fabsf(sbx[q*4+2] - bj.z);
            float d3 = fabsf(sbx[q*4+3] - bj.w);
            ull a0 = pack2(d0, d0), a1 = pack2(d1, d1);
            ull a2 = pack2(d2, d2), a3 = pack2(d3, d3);
            float sum = 0.f;
            #pragma unroll
            for (int p = 0; p < 4; p++) {
                ull t2 = add2v(sp1q[q][p], p2v[p]);
                t2 = fma2v(a0, wg2[0][p], t2);
                t2 = fma2v(a1, wg2[1][p], t2);
                t2 = fma2v(a2, wg2[2][p], t2);
                t2 = fma2v(a3, wg2[3][p], t2);
                float tl, th;
                unpack2(t2, tl, th);
                tl = fmaxf(tl, 0.f);
                th = fmaxf(th, 0.f);
                sum = fmaf(tl, w2lo[p], sum);
                sum = fmaf(th, w2hi[p], sum);
            }
            #pragma unroll
            for (int o = 16; o; o >>= 1) sum += __shfl_down_sync(0xffffffffu, sum, o);
            if (lane == 0)
                srow[q][j] = sum - ((j == i0 + q) ? 1e6f : 0.f);
        }
    }
    __syncthreads();

    if (warp < 4) {
        int q = warp, i = i0 + q;
        for (int sel2 = 0; sel2 < TOPKK; sel2++) {
            float bv = -3.4e38f; int bi = 1 << 30;
            for (int j = lane; j < NN; j += 32) {
                float v = srow[q][j];
                if (v > bv || (v == bv && j < bi)) { bv = v; bi = j; }
            }
            #pragma unroll
            for (int o = 16; o; o >>= 1) {
                float ov = __shfl_xor_sync(0xffffffffu, bv, o);
                int   oi = __shfl_xor_sync(0xffffffffu, bi, o);
                if (ov > bv || (ov == bv && oi < bi)) { bv = ov; bi = oi; }
            }
            if (lane == 0) {
                g_nbr[(b*NN + i)*TOPKK + sel2] = bi;
                srow[q][bi] = -3.4e38f;
            }
            __syncwarp();
        }
    }
}

// -------- GAT1: warp-shfl scan build + softmax + float4 aggregate + xw2 ------
// (exact R12 kernel)
__global__ __launch_bounds__(256) void k_gat1(
    const float* __restrict__ gat1_b,
    const float* __restrict__ gat2_w,
    const float* __restrict__ att_src2,
    const float* __restrict__ att_dst2)
{
    int bn = blockIdx.x; int b = bn / NN, tt = bn % NN;
    __shared__ int   ssrc[MAXDEG];
    __shared__ float sal[NHEADS][MAXDEG];
    __shared__ float sas1[NN*4];
    __shared__ int   wtot[8];
    __shared__ float red[8][2];
    int tid = threadIdx.x;
    int warp = tid >> 5, lane = tid & 31;

    #pragma unroll
    for (int it = 0; it < 6; it++)
        sas1[tid + it*256] = g_as1[b*NN*4 + tid + it*256];

    const int* nb = g_nbr + b*NN*TOPKK;
    int myc0 = 0, myc1 = 0;
    int ia = 2*tid, ib2 = 2*tid + 1;
    if (tid < 192) {
        #pragma unroll
        for (int k = 0; k < TOPKK; k++) {
            myc0 += (nb[ia*TOPKK + k] == tt);
            myc1 += (nb[ib2*TOPKK + k] == tt);
        }
    }
    int cnt = myc0 + myc1;
    int incl = cnt;
    #pragma unroll
    for (int d = 1; d < 32; d <<= 1) {
        int v = __shfl_up_sync(0xffffffffu, incl, d);
        if (lane >= d) incl += v;
    }
    if (lane == 31) wtot[warp] = incl;
    __syncthreads();
    int woff = 0, total = 0;
    #pragma unroll
    for (int w = 0; w < 8; w++) {
        int v = wtot[w];
        if (w < warp) woff += v;
        total += v;
    }
    int off = woff + incl - cnt;
    int* dst = g_srcl + bn*MAXDEG;
    if (tid < 192) {
        if (myc0) {
            #pragma unroll
            for (int k = 0; k < TOPKK; k++)
                if (nb[ia*TOPKK + k] == tt) { ssrc[off] = ia; dst[off] = ia; off++; }
        }
        if (myc1) {
            #pragma unroll
            for (int k = 0; k < TOPKK; k++)
                if (nb[ib2*TOPKK + k] == tt) { ssrc[off] = ib2; dst[off] = ib2; off++; }
        }
    }
    if (tid == 0) {
        ssrc[total] = tt;
        dst[total] = tt;
        g_deg[bn] = total + 1;
    }
    __syncthreads();
    int deg = total + 1;

    if (warp < NHEADS) {
        int h = warp;
        float adv = g_ad1[bn*4 + h];
        float m = -3.4e38f;
        for (int s = lane; s < deg; s += 32) {
            float e = sas1[ssrc[s]*4 + h] + adv;
            e = (e >= 0.f) ? e : 0.2f*e;
            sal[h][s] = e;
            m = fmaxf(m, e);
        }
        #pragma unroll
        for (int o = 16; o; o >>= 1) m = fmaxf(m, __shfl_xor_sync(0xffffffffu, m, o));
        float sum = 0.f;
        for (int s = lane; s < deg; s += 32) {
            float ex = expf(sal[h][s] - m);
            sal[h][s] = ex;
            sum += ex;
        }
        #pragma unroll
        for (int o = 16; o; o >>= 1) sum += __shfl_xor_sync(0xffffffffu, sum, o);
        float inv = 1.f / fmaxf(sum, 1e-16f);
        for (int s = lane; s < deg; s += 32) sal[h][s] *= inv;
    }
    __syncthreads();

    const float* xwb = g_xw1 + b*NN*1024;
    const float* salh = sal[tid >> 6];
    float4 acc0 = make_float4(0.f, 0.f, 0.f, 0.f);
    float4 acc1 = make_float4(0.f, 0.f, 0.f, 0.f);
    int col4 = tid * 4;
    int s = 0;
    for (; s + 1 < deg; s += 2) {
        float4 v0 = *(const float4*)&xwb[ssrc[s  ]*1024 + col4];
        float4 v1 = *(const float4*)&xwb[ssrc[s+1]*1024 + col4];
        float a0 = salh[s], a1 = salh[s+1];
        acc0.x = fmaf(v0.x, a0, acc0.x); acc0.y = fmaf(v0.y, a0, acc0.y);
        acc0.z = fmaf(v0.z, a0, acc0.z); acc0.w = fmaf(v0.w, a0, acc0.w);
        acc1.x = fmaf(v1.x, a1, acc1.x); acc1.y = fmaf(v1.y, a1, acc1.y);
        acc1.z = fmaf(v1.z, a1, acc1.z); acc1.w = fmaf(v1.w, a1, acc1.w);
    }
    if (s < deg) {
        float4 v0 = *(const float4*)&xwb[ssrc[s]*1024 + col4];
        float a0 = salh[s];
        acc0.x = fmaf(v0.x, a0, acc0.x); acc0.y = fmaf(v0.y, a0, acc0.y);
        acc0.z = fmaf(v0.z, a0, acc0.z); acc0.w = fmaf(v0.w, a0, acc0.w);
    }
    float4 bia = *(const float4*)&gat1_b[col4];
    float4 oh;
    oh.x = fmaxf(acc0.x + acc1.x + bia.x, 0.f);
    oh.y = fmaxf(acc0.y + acc1.y + bia.y, 0.f);
    oh.z = fmaxf(acc0.z + acc1.z + bia.z, 0.f);
    oh.w = fmaxf(acc0.w + acc1.w + bia.w, 0.f);

    float4 w0 = *(const float4*)&gat2_w[col4*2];
    float4 w1 = *(const float4*)&gat2_w[col4*2 + 4];
    float c0 = oh.x*w0.x + oh.y*w0.z + oh.z*w1.x + oh.w*w1.z;
    float c1 = oh.x*w0.y + oh.y*w0.w + oh.z*w1.y + oh.w*w1.w;
    #pragma unroll
    for (int o = 16; o; o >>= 1) {
        c0 += __shfl_down_sync(0xffffffffu, c0, o);
        c1 += __shfl_down_sync(0xffffffffu, c1, o);
    }
    if (lane == 0) { red[warp][0] = c0; red[warp][1] = c1; }
    __syncthreads();
    if (tid == 0) {
        float s0 = 0.f, s1 = 0.f;
        #pragma unroll
        for (int w = 0; w < 8; w++) { s0 += red[w][0]; s1 += red[w][1]; }
        g_xw2[bn*2 + 0] = s0;
        g_xw2[bn*2 + 1] = s1;
        g_as2[bn] = s0*att_src2[0] + s1*att_src2[1];
        g_ad2[bn] = s0*att_dst2[0] + s1*att_dst2[1];
    }
}

// ------- GAT layer 2: 8 nodes/block, batch as2/xw2 preloaded into smem -------
// (exact R12 kernel)
__global__ __launch_bounds__(256) void k_gat2(const float* __restrict__ gat2_b,
                                              float* __restrict__ out)
{
    __shared__ float s_as2[NN];
    __shared__ float s_xw2[NN*2];
    __shared__ float sal[8][MAXDEG];
    __shared__ int   ssrc[8][MAXDEG];
    int tid = threadIdx.x;
    int warp = tid >> 5, lane = tid & 31;
    int n0 = blockIdx.x * 8;
    int b = n0 / NN;

    for (int i = tid; i < NN; i += 256)   s_as2[i] = g_as2[b*NN + i];
    for (int i = tid; i < NN*2; i += 256) s_xw2[i] = g_xw2[b*NN*2 + i];
    __syncthreads();

    int bn = n0 + warp;
    int deg = g_deg[bn];
    for (int s = lane; s < deg; s += 32) ssrc[warp][s] = g_srcl[bn*MAXDEG + s];
    __syncwarp();
    float adv = g_ad2[bn];
    float m = -3.4e38f;
    for (int s = lane; s < deg; s += 32) {
        float e = s_as2[ssrc[warp][s]] + adv;
        e = (e >= 0.f) ? e : 0.2f*e;
        sal[warp][s] = e;
        m = fmaxf(m, e);
    }
    #pragma unroll
    for (int o = 16; o; o >>= 1) m = fmaxf(m, __shfl_xor_sync(0xffffffffu, m, o));
    float sum = 0.f;
    for (int s = lane; s < deg; s += 32) {
        float ex = expf(sal[warp][s] - m);
        sal[warp][s] = ex;
        sum += ex;
    }
    #pragma unroll
    for (int o = 16; o; o >>= 1) sum += __shfl_xor_sync(0xffffffffu, sum, o);
    float inv = 1.f / fmaxf(sum, 1e-16f);
    __syncwarp();
    float a0 = 0.f, a1 = 0.f;
    for (int s = lane; s < deg; s += 32) {
        float w = sal[warp][s] * inv;
        int sc = ssrc[warp][s];
        a0 = fmaf(s_xw2[sc*2 + 0], w, a0);
        a1 = fmaf(s_xw2[sc*2 + 1], w, a1);
    }
    #pragma unroll
    for (int o = 16; o; o >>= 1) {
        a0 += __shfl_down_sync(0xffffffffu, a0, o);
        a1 += __shfl_down_sync(0xffffffffu, a1, o);
    }
    if (lane == 0) {
        out[bn*2 + 0] = a0 + gat2_b[0];
        out[bn*2 + 1] = a1 + gat2_b[1];
    }
}

// ---------------- launch ------------------------------------------------------
extern "C" void kernel_launch(void* const* d_in, const int* in_sizes, int n_in,
                              void* d_out, int out_size)
{
    const float* feats   = (const float*)d_in[0];
    const float* boxes   = (const float*)d_in[1];
    const float* fc1_w   = (const float*)d_in[2];
    const float* fc1_b   = (const float*)d_in[3];
    const float* fc2_w   = (const float*)d_in[4];
    // d_in[5] = fc2_b : constant shift, irrelevant for top-k
    const float* gat1_w  = (const float*)d_in[6];
    const float* g1as    = (const float*)d_in[7];
    const float* g1ad    = (const float*)d_in[8];
    const float* gat1_b  = (const float*)d_in[9];
    const float* gat2_w  = (const float*)d_in[10];
    const float* g2as    = (const float*)d_in[11];
    const float* g2ad    = (const float*)d_in[12];
    const float* gat2_b  = (const float*)d_in[13];
    float* out = (float*)d_out;

    k_gemms   <<<144, 256>>>(feats, fc1_w, gat1_w, boxes);
    k_rel_asad<<<192 + 384, 256>>>(boxes, fc1_w, fc1_b, fc2_w, g1as, g1ad);
    k_gat1    <<<BB*NN, 256>>>(gat1_b, gat2_w, g2as, g2ad);
    k_gat2    <<<96, 256>>>(gat2_b, out);
    (void)in_sizes; (void)n_in; (void)out_size;
}

// round 14
// speedup vs baseline: 1.4289x; 1.0046x over previous
#include <cuda_runtime.h>
#include <math.h>

#define BB 2
#define NN 384
#define CC 1024
#define HREPN 256
#define GHID 256
#define NHEADS 4
#define TOPKK 8
#define MAXDEG 400

typedef unsigned long long ull;

// ---------------- scratch (device globals; no allocation allowed) ------------
__device__ __align__(16) float g_p1 [BB*NN*HREPN];
__device__ __align__(16) float g_p2 [BB*NN*HREPN];
__device__ __align__(16) float g_xw1[BB*NN*NHEADS*GHID];
__device__ float g_as1[BB*NN*NHEADS];
__device__ float g_ad1[BB*NN*NHEADS];
__device__ int   g_nbr[BB*NN*TOPKK];
__device__ int   g_srcl[BB*NN*MAXDEG];
__device__ int   g_deg [BB*NN];
__device__ float g_xw2[BB*NN*2];
__device__ float g_as2[BB*NN];
__device__ float g_ad2[BB*NN];

// ---------------- f32x2 helpers ----------------------------------------------
__device__ __forceinline__ void ffma2(ull &d, ull a, ull b) {
    asm("fma.rn.f32x2 %0, %1, %2, %0;" : "+l"(d) : "l"(a), "l"(b));
}
__device__ __forceinline__ ull fma2v(ull a, ull b, ull c) {
    ull r; asm("fma.rn.f32x2 %0, %1, %2, %3;" : "=l"(r) : "l"(a), "l"(b), "l"(c)); return r;
}
__device__ __forceinline__ ull add2v(ull a, ull b) {
    ull r; asm("add.rn.f32x2 %0, %1, %2;" : "=l"(r) : "l"(a), "l"(b)); return r;
}
__device__ __forceinline__ ull pack2(float lo, float hi) {
    ull r; asm("mov.b64 %0, {%1, %2};" : "=l"(r) : "f"(lo), "f"(hi)); return r;
}
__device__ __forceinline__ void unpack2(ull v, float &lo, float &hi) {
    asm("mov.b64 {%0, %1}, %2;" : "=f"(lo), "=f"(hi) : "l"(v));
}
__device__ __forceinline__ float lo2(ull v) { return __uint_as_float((unsigned)(v & 0xffffffffull)); }
__device__ __forceinline__ float hi2(ull v) { return __uint_as_float((unsigned)(v >> 32)); }

// ---------------- PDL helpers -------------------------------------------------
__device__ __forceinline__ void pdl_wait()   { asm volatile("griddepcontrol.wait;" ::: "memory"); }
__device__ __forceinline__ void pdl_launch() { asm volatile("griddepcontrol.launch_dependents;" ::: "memory"); }

// ---------------- cp.async helpers -------------------------------------------
__device__ __forceinline__ unsigned sptr(const void* p) {
    return (unsigned)__cvta_generic_to_shared(p);
}
__device__ __forceinline__ void cpa16(unsigned dst, const void* src) {
    asm volatile("cp.async.cg.shared.global [%0], [%1], 16;" :: "r"(dst), "l"(src));
}
__device__ __forceinline__ void cpa4(unsigned dst, const void* src) {
    asm volatile("cp.async.ca.shared.global [%0], [%1], 4;" :: "r"(dst), "l"(src));
}

// -------- fused SGEMM: 128x64 tiles, 256 thr, K-split, cp.async + LDS.128 ----
__global__ __launch_bounds__(256, 1) void k_gemms(
    const float* __restrict__ feats,
    const float* __restrict__ fc1_w,
    const float* __restrict__ gat1_w,
    const float* __restrict__ boxes)
{
    __shared__ float As[2][2][128*20];   // [khalf][buf][row*20+k]
    __shared__ float Bs[2][2][64*20];    // [khalf][buf][col*20+k]
    __shared__ float Wg4[4*64];

    int tid = threadIdx.x;
    int khalf = tid >> 7;          // 0 or 1
    int htid  = tid & 127;
    int bid = blockIdx.x;
    int sel, b, by, bx;
    if (bid < 48) { sel = 0; b = bid / 24; int r = bid % 24; by = r / 8;  bx = r % 8;  }
    else { sel = 1; int r = bid - 48; b = r / 48; r %= 48;   by = r / 16; bx = r % 16; }

    int row0 = by * 128, col0 = bx * 64;

    const float* Bm; float* Cm;
    int ldb, Nc, dcol0;
    if (sel == 0) {
        ldb = 256; Nc = 256;
        if (col0 < 256) { Bm = fc1_w;            Cm = g_p1 + b*NN*256; dcol0 = col0; }
        else            { Bm = fc1_w + 1024*256; Cm = g_p2 + b*NN*256; dcol0 = col0 - 256; }
    } else {
        ldb = 1024; Nc = 1024; Bm = gat1_w; Cm = g_xw1 + b*NN*1024; dcol0 = col0;
        Wg4[tid] = gat1_w[(1024 + (tid >> 6))*1024 + col0 + (tid & 63)];
    }

    int tx = htid & 7, ty = htid >> 3;      // 8 x 16 thread grid per half
    ull acc[8][8];
    #pragma unroll
    for (int r = 0; r < 8; r++)
        #pragma unroll
        for (int j = 0; j < 8; j++) acc[r][j] = 0ull;

    int arow = htid >> 2, aslot = htid & 3;   // A loader: rows arow+32m
    int bc = htid & 63, bk = htid >> 6;       // B loader: col bc, k's bk*8..+7

    int kbase = khalf * 512;
    const float* ApB = feats + b*NN*CC + (row0 + arow)*1024 + kbase + aslot*4;
    const float* Bp  = Bm + (ull)(kbase + bk*8)*ldb + dcol0 + bc;

    unsigned aD = sptr(&As[khalf][0][arow*20 + aslot*4]);
    unsigned bD = sptr(&Bs[khalf][0][bc*20 + bk*8]);

    #pragma unroll
    for (int m = 0; m < 4; m++) cpa16(aD + m*32*20*4, ApB + m*32*1024);
    #pragma unroll
    for (int m = 0; m < 8; m++) cpa4(bD + m*4, Bp + m*ldb);
    asm volatile("cp.async.commit_group;");

    for (int t = 0; t < 32; t++) {
        int cur = t & 1, nxt = cur ^ 1;
        if (t < 31) {
            int k0 = (t + 1) * 16;
            unsigned aDn = aD + nxt*2560*4;
            unsigned bDn = bD + nxt*1280*4;
            const float* Asrc = ApB + k0;
            const float* Bsrc = Bp + k0*ldb;
            #pragma unroll
            for (int m = 0; m < 4; m++) cpa16(aDn + m*32*20*4, Asrc + m*32*1024);
            #pragma unroll
            for (int m = 0; m < 8; m++) cpa4(bDn + m*4, Bsrc + m*ldb);
            asm volatile("cp.async.commit_group;");
            asm volatile("cp.async.wait_group 1;");
        } else {
            asm volatile("cp.async.wait_group 0;");
        }
        __syncthreads();
        #pragma unroll
        for (int kph = 0; kph < 4; kph++) {
            ulonglong2 av[8], bv[8];
            #pragma unroll
            for (int r = 0; r < 8; r++)
                av[r] = *(const ulonglong2*)&As[khalf][cur][(ty + 16*r)*20 + 4*kph];
            #pragma unroll
            for (int j = 0; j < 8; j++)
                bv[j] = *(const ulonglong2*)&Bs[khalf][cur][(tx + 8*j)*20 + 4*kph];
            #pragma unroll
            for (int r = 0; r < 8; r++)
                #pragma unroll
                for (int j = 0; j < 8; j++) ffma2(acc[r][j], av[r].x, bv[j].x);
            #pragma unroll
            for (int r = 0; r < 8; r++)
                #pragma unroll
                for (int j = 0; j < 8; j++) ffma2(acc[r][j], av[r].y, bv[j].y);
        }
        __syncthreads();
    }

    // ---- combine halves via padded smem (stride 65: bank-conflict-free) ----
    float* comb = (float*)As;
    if (khalf == 1) {
        #pragma unroll
        for (int r = 0; r < 8; r++)
            #pragma unroll
            for (int j = 0; j < 8; j++)
                comb[htid*65 + r*8 + j] = lo2(acc[r][j]) + hi2(acc[r][j]);
    }
    __syncthreads();
    if (khalf == 0) {
        #pragma unroll
        for (int r = 0; r < 8; r++) {
            int row = row0 + ty + 16*r;
            float g0 = 0.f, g1 = 0.f, g2 = 0.f, g3 = 0.f;
            if (sel == 1) {
                const float* bx4 = boxes + (b*NN + row)*4;
                float x0 = bx4[0]*(1.0f/800.0f), y0 = bx4[1]*(1.0f/800.0f);
                float x1 = bx4[2]*(1.0f/800.0f), y1 = bx4[3]*(1.0f/800.0f);
                g0 = x0; g1 = y0; g2 = x1 - x0; g3 = y1 - y0;
            }
            #pragma unroll
            for (int j = 0; j < 8; j++) {
                int c = tx + 8*j;
                float s = (lo2(acc[r][j]) + hi2(acc[r][j])) + comb[htid*65 + r*8 + j];
                if (sel == 1) {
                    s = fmaf(g0, Wg4[0*64 + c], s);
                    s = fmaf(g1, Wg4[1*64 + c], s);
                    s = fmaf(g2, Wg4[2*64 + c], s);
                    s = fmaf(g3, Wg4[3*64 + c], s);
                }
                Cm[row*Nc + dcol0 + c] = s;
            }
        }
    }
    pdl_launch();
}

// ------- merged: relation scores + top-8 (blocks 0..191)  |  asad (192..575) -
__global__ __launch_bounds__(256) void k_rel_asad(
    const float* __restrict__ boxes,
    const float* __restrict__ fc1_w,
    const float* __restrict__ fc1_b,
    const float* __restrict__ fc2_w,
    const float* __restrict__ att_src,
    const float* __restrict__ att_dst)
{
    __shared__ float srow[4][NN];
    __shared__ float sbx[16];
    int bid = blockIdx.x;
    int tid = threadIdx.x, warp = tid >> 5, lane = tid & 31;

    if (bid >= 192) {
        // independent prologue: attention weights (kernel inputs)
        int h = (tid >> 5) & 3;
        const float* asr = att_src + h*256 + lane*8;
        const float* adr = att_dst + h*256 + lane*8;
        float4 s0 = *(const float4*)asr;
        float4 s1 = *(const float4*)(asr + 4);
        float4 d0 = *(const float4*)adr;
        float4 d1 = *(const float4*)(adr + 4);
        pdl_wait();                       // g_xw1 produced by k_gemms
        int bn = (bid - 192)*2 + (tid >> 7);
        const float* xw = g_xw1 + bn*1024 + h*256 + lane*8;
        float4 v0 = *(const float4*)xw;
        float4 v1 = *(const float4*)(xw + 4);
        float ss = v0.x*s0.x + v0.y*s0.y + v0.z*s0.z + v0.w*s0.w
                 + v1.x*s1.x + v1.y*s1.y + v1.z*s1.z + v1.w*s1.w;
        float dd = v0.x*d0.x + v0.y*d0.y + v0.z*d0.z + v0.w*d0.w
                 + v1.x*d1.x + v1.y*d1.y + v1.z*d1.z + v1.w*d1.w;
        #pragma unroll
        for (int o = 16; o; o >>= 1) {
            ss += __shfl_down_sync(0xffffffffu, ss, o);
            dd += __shfl_down_sync(0xffffffffu, dd, o);
        }
        if (lane == 0) { g_as1[bn*4 + h] = ss; g_ad1[bn*4 + h] = dd; }
        pdl_launch();
        return;
    }

    int b = bid / 96, igrp = bid % 96;
    int i0 = igrp * 4;

    if (tid < 16) sbx[tid] = boxes[(b*NN + i0 + (tid >> 2))*4 + (tid & 3)];

    // independent prologue: fc weights/bias (kernel inputs)
    ull wg2[4][4], sp1q[4][4];
    float w2lo[4], w2hi[4], bb0[4], bb1[4];
    #pragma unroll
    for (int p = 0; p < 4; p++) {
        int k0 = lane + 64*p, k1 = k0 + 32;
        w2lo[p] = fc2_w[k0];
        w2hi[p] = fc2_w[k1];
        #pragma unroll
        for (int d = 0; d < 4; d++)
            wg2[d][p] = pack2(fc1_w[(2048+d)*256 + k0], fc1_w[(2048+d)*256 + k1]);
        bb0[p] = fc1_b[k0];
        bb1[p] = fc1_b[k1];
    }
    pdl_wait();                           // g_p1/g_p2 produced by k_gemms
    #pragma unroll
    for (int p = 0; p < 4; p++) {
        int k0 = lane + 64*p, k1 = k0 + 32;
        #pragma unroll
        for (int q = 0; q < 4; q++) {
            const float* p1r = g_p1 + (b*NN + i0 + q)*256;
            sp1q[q][p] = pack2(p1r[k0] + bb0[p], p1r[k1] + bb1[p]);
        }
    }
    __syncthreads();

    const float* p2b = g_p2 + b*NN*256;
    const float* bxb = boxes + b*NN*4;

    for (int j = warp; j < NN; j += 8) {
        float4 bj = *(const float4*)&bxb[j*4];
        ull p2v[4];
        #pragma unroll
        for (int p = 0; p < 4; p++) {
            int k0 = lane + 64*p;
            p2v[p] = pack2(p2b[j*256 + k0], p2b[j*256 + k0 + 32]);
        }
        #pragma unroll
        for (int q = 0; q < 4; q++) {
            float d0 = fabsf(sbx[q*4+0] - bj.x);
            float d1 = fabsf(sbx[q*4+1] - bj.y);
            float d2 = fabsf(sbx[q*4+2] - bj.z);
            float d3 = fabsf(sbx[q*4+3] - bj.w);
            ull a0 = pack2(d0, d0), a1 = pack2(d1, d1);
            ull a2 = pack2(d2, d2), a3 = pack2(d3, d3);
            float sum = 0.f;
            #pragma unroll
            for (int p = 0; p < 4; p++) {
                ull t2 = add2v(sp1q[q][p], p2v[p]);
                t2 = fma2v(a0, wg2[0][p], t2);
                t2 = fma2v(a1, wg2[1][p], t2);
                t2 = fma2v(a2, wg2[2][p], t2);
                t2 = fma2v(a3, wg2[3][p], t2);
                float tl, th;
                unpack2(t2, tl, th);
                tl = fmaxf(tl, 0.f);
                th = fmaxf(th, 0.f);
                sum = fmaf(tl, w2lo[p], sum);
                sum = fmaf(th, w2hi[p], sum);
            }
            #pragma unroll
            for (int o = 16; o; o >>= 1) sum += __shfl_down_sync(0xffffffffu, sum, o);
            if (lane == 0)
                srow[q][j] = sum - ((j == i0 + q) ? 1e6f : 0.f);
        }
    }
    __syncthreads();

    if (warp < 4) {
        int q = warp, i = i0 + q;
        for (int sel2 = 0; sel2 < TOPKK; sel2++) {
            float bv = -3.4e38f; int bi = 1 << 30;
            for (int j = lane; j < NN; j += 32) {
                float v = srow[q][j];
                if (v > bv || (v == bv && j < bi)) { bv = v; bi = j; }
            }
            #pragma unroll
            for (int o = 16; o; o >>= 1) {
                float ov = __shfl_xor_sync(0xffffffffu, bv, o);
                int   oi = __shfl_xor_sync(0xffffffffu, bi, o);
                if (ov > bv || (ov == bv && oi < bi)) { bv = ov; bi = oi; }
            }
            if (lane == 0) {
                g_nbr[(b*NN + i)*TOPKK + sel2] = bi;
                srow[q][bi] = -3.4e38f;
            }
            __syncwarp();
        }
    }
    pdl_launch();
}

// -------- GAT1: warp-shfl scan build + softmax + float4 aggregate + xw2 ------
__global__ __launch_bounds__(256) void k_gat1(
    const float* __restrict__ gat1_b,
    const float* __restrict__ gat2_w,
    const float* __restrict__ att_src2,
    const float* __restrict__ att_dst2)
{
    int bn = blockIdx.x; int b = bn / NN, tt = bn % NN;
    __shared__ int   ssrc[MAXDEG];
    __shared__ float sal[NHEADS][MAXDEG];
    __shared__ float sas1[NN*4];
    __shared__ int   wtot[8];
    __shared__ float red[8][2];
    int tid = threadIdx.x;
    int warp = tid >> 5, lane = tid & 31;

    pdl_wait();                           // g_as1/g_nbr produced by k_rel_asad

    #pragma unroll
    for (int it = 0; it < 6; it++)
        sas1[tid + it*256] = g_as1[b*NN*4 + tid + it*256];

    const int* nb = g_nbr + b*NN*TOPKK;
    int myc0 = 0, myc1 = 0;
    int ia = 2*tid, ib2 = 2*tid + 1;
    if (tid < 192) {
        #pragma unroll
        for (int k = 0; k < TOPKK; k++) {
            myc0 += (nb[ia*TOPKK + k] == tt);
            myc1 += (nb[ib2*TOPKK + k] == tt);
        }
    }
    int cnt = myc0 + myc1;
    int incl = cnt;
    #pragma unroll
    for (int d = 1; d < 32; d <<= 1) {
        int v = __shfl_up_sync(0xffffffffu, incl, d);
        if (lane >= d) incl += v;
    }
    if (lane == 31) wtot[warp] = incl;
    __syncthreads();
    int woff = 0, total = 0;
    #pragma unroll
    for (int w = 0; w < 8; w++) {
        int v = wtot[w];
        if (w < warp) woff += v;
        total += v;
    }
    int off = woff + incl - cnt;
    int* dst = g_srcl + bn*MAXDEG;
    if (tid < 192) {
        if (myc0) {
            #pragma unroll
            for (int k = 0; k < TOPKK; k++)
                if (nb[ia*TOPKK + k] == tt) { ssrc[off] = ia; dst[off] = ia; off++; }
        }
        if (myc1) {
            #pragma unroll
            for (int k = 0; k < TOPKK; k++)
                if (nb[ib2*TOPKK + k] == tt) { ssrc[off] = ib2; dst[off] = ib2; off++; }
        }
    }
    if (tid == 0) {
        ssrc[total] = tt;
        dst[total] = tt;
        g_deg[bn] = total + 1;
    }
    __syncthreads();
    int deg = total + 1;

    if (warp < NHEADS) {
        int h = warp;
        float adv = g_ad1[bn*4 + h];
        float m = -3.4e38f;
        for (int s = lane; s < deg; s += 32) {
            float e = sas1[ssrc[s]*4 + h] + adv;
            e = (e >= 0.f) ? e : 0.2f*e;
            sal[h][s] = e;
            m = fmaxf(m, e);
        }
        #pragma unroll
        for (int o = 16; o; o >>= 1) m = fmaxf(m, __shfl_xor_sync(0xffffffffu, m, o));
        float sum = 0.f;
        for (int s = lane; s < deg; s += 32) {
            float ex = expf(sal[h][s] - m);
            sal[h][s] = ex;
            sum += ex;
        }
        #pragma unroll
        for (int o = 16; o; o >>= 1) sum += __shfl_xor_sync(0xffffffffu, sum, o);
        float inv = 1.f / fmaxf(sum, 1e-16f);
        for (int s = lane; s < deg; s += 32) sal[h][s] *= inv;
    }
    __syncthreads();

    const float* xwb = g_xw1 + b*NN*1024;
    const float* salh = sal[tid >> 6];
    float4 acc0 = make_float4(0.f, 0.f, 0.f, 0.f);
    float4 acc1 = make_float4(0.f, 0.f, 0.f, 0.f);
    int col4 = tid * 4;
    int s = 0;
    for (; s + 1 < deg; s += 2) {
        float4 v0 = *(const float4*)&xwb[ssrc[s  ]*1024 + col4];
        float4 v1 = *(const float4*)&xwb[ssrc[s+1]*1024 + col4];
        float a0 = salh[s], a1 = salh[s+1];
        acc0.x = fmaf(v0.x, a0, acc0.x); acc0.y = fmaf(v0.y, a0, acc0.y);
        acc0.z = fmaf(v0.z, a0, acc0.z); acc0.w = fmaf(v0.w, a0, acc0.w);
        acc1.x = fmaf(v1.x, a1, acc1.x); acc1.y = fmaf(v1.y, a1, acc1.y);
        acc1.z = fmaf(v1.z, a1, acc1.z); acc1.w = fmaf(v1.w, a1, acc1.w);
    }
    if (s < deg) {
        float4 v0 = *(const float4*)&xwb[ssrc[s]*1024 + col4];
        float a0 = salh[s];
        acc0.x = fmaf(v0.x, a0, acc0.x); acc0.y = fmaf(v0.y, a0, acc0.y);
        acc0.z = fmaf(v0.z, a0, acc0.z); acc0.w = fmaf(v0.w, a0, acc0.w);
    }
    float4 bia = *(const float4*)&gat1_b[col4];
    float4 oh;
    oh.x = fmaxf(acc0.x + acc1.x + bia.x, 0.f);
    oh.y = fmaxf(acc0.y + acc1.y + bia.y, 0.f);
    oh.z = fmaxf(acc0.z + acc1.z + bia.z, 0.f);
    oh.w = fmaxf(acc0.w + acc1.w + bia.w, 0.f);

    float4 w0 = *(const float4*)&gat2_w[col4*2];
    float4 w1 = *(const float4*)&gat2_w[col4*2 + 4];
    float c0 = oh.x*w0.x + oh.y*w0.z + oh.z*w1.x + oh.w*w1.z;
    float c1 = oh.x*w0.y + oh.y*w0.w + oh.z*w1.y + oh.w*w1.w;
    #pragma unroll
    for (int o = 16; o; o >>= 1) {
        c0 += __shfl_down_sync(0xffffffffu, c0, o);
        c1 += __shfl_down_sync(0xffffffffu, c1, o);
    }
    if (lane == 0) { red[warp][0] = c0; red[warp][1] = c1; }
    __syncthreads();
    if (tid == 0) {
        float s0 = 0.f, s1 = 0.f;
        #pragma unroll
        for (int w = 0; w < 8; w++) { s0 += red[w][0]; s1 += red[w][1]; }
        g_xw2[bn*2 + 0] = s0;
        g_xw2[bn*2 + 1] = s1;
        g_as2[bn] = s0*att_src2[0] + s1*att_src2[1];
        g_ad2[bn] = s0*att_dst2[0] + s1*att_dst2[1];
    }
    pdl_launch();
}

// ------- GAT layer 2: 8 nodes/block, batch as2/xw2 preloaded into smem -------
__global__ __launch_bounds__(256) void k_gat2(const float* __restrict__ gat2_b,
                                              float* __restrict__ out)
{
    __shared__ float s_as2[NN];
    __shared__ float s_xw2[NN*2];
    __shared__ float sal[8][MAXDEG];
    __shared__ int   ssrc[8][MAXDEG];
    int tid = threadIdx.x;
    int warp = tid >> 5, lane = tid & 31;
    int n0 = blockIdx.x * 8;
    int b = n0 / NN;

    pdl_wait();                           // g_as2/g_xw2/g_deg produced by k_gat1

    for (int i = tid; i < NN; i += 256)   s_as2[i] = g_as2[b*NN + i];
    for (int i = tid; i < NN*2; i += 256) s_xw2[i] = g_xw2[b*NN*2 + i];
    __syncthreads();

    int bn = n0 + warp;
    int deg = g_deg[bn];
    for (int s = lane; s < deg; s += 32) ssrc[warp][s] = g_srcl[bn*MAXDEG + s];
    __syncwarp();
    float adv = g_ad2[bn];
    float m = -3.4e38f;
    for (int s = lane; s < deg; s += 32) {
        float e = s_as2[ssrc[warp][s]] + adv;
        e = (e >= 0.f) ? e : 0.2f*e;
        sal[warp][s] = e;
        m = fmaxf(m, e);
    }
    #pragma unroll
    for (int o = 16; o; o >>= 1) m = fmaxf(m, __shfl_xor_sync(0xffffffffu, m, o));
    float sum = 0.f;
    for (int s = lane; s < deg; s += 32) {
        float ex = expf(sal[warp][s] - m);
        sal[warp][s] = ex;
        sum += ex;
    }
    #pragma unroll
    for (int o = 16; o; o >>= 1) sum += __shfl_xor_sync(0xffffffffu, sum, o);
    float inv = 1.f / fmaxf(sum, 1e-16f);
    __syncwarp();
    float a0 = 0.f, a1 = 0.f;
    for (int s = lane; s < deg; s += 32) {
        float w = sal[warp][s] * inv;
        int sc = ssrc[warp][s];
        a0 = fmaf(s_xw2[sc*2 + 0], w, a0);
        a1 = fmaf(s_xw2[sc*2 + 1], w, a1);
    }
    #pragma unroll
    for (int o = 16; o; o >>= 1) {
        a0 += __shfl_down_sync(0xffffffffu, a0, o);
        a1 += __shfl_down_sync(0xffffffffu, a1, o);
    }
    if (lane == 0) {
        out[bn*2 + 0] = a0 + gat2_b[0];
        out[bn*2 + 1] = a1 + gat2_b[1];
    }
}

// ---------------- launch ------------------------------------------------------
extern "C" void kernel_launch(void* const* d_in, const int* in_sizes, int n_in,
                              void* d_out, int out_size)
{
    const float* feats   = (const float*)d_in[0];
    const float* boxes   = (const float*)d_in[1];
    const float* fc1_w   = (const float*)d_in[2];
    const float* fc1_b   = (const float*)d_in[3];
    const float* fc2_w   = (const float*)d_in[4];
    // d_in[5] = fc2_b : constant shift, irrelevant for top-k
    const float* gat1_w  = (const float*)d_in[6];
    const float* g1as    = (const float*)d_in[7];
    const float* g1ad    = (const float*)d_in[8];
    const float* gat1_b  = (const float*)d_in[9];
    const float* gat2_w  = (const float*)d_in[10];
    const float* g2as    = (const float*)d_in[11];
    const float* g2ad    = (const float*)d_in[12];
    const float* gat2_b  = (const float*)d_in[13];
    float* out = (float*)d_out;

    k_gemms<<<144, 256>>>(feats, fc1_w, gat1_w, boxes);

    cudaLaunchAttribute pdl_attr[1];
    pdl_attr[0].id = cudaLaunchAttributeProgrammaticStreamSerialization;
    pdl_attr[0].val.programmaticStreamSerializationAllowed = 1;

    {
        cudaLaunchConfig_t cfg = {};
        cfg.gridDim = dim3(192 + 384, 1, 1);
        cfg.blockDim = dim3(256, 1, 1);
        cfg.stream = 0;
        cfg.attrs = pdl_attr;
        cfg.numAttrs = 1;
        cudaLaunchKernelEx(&cfg, k_rel_asad, boxes, fc1_w, fc1_b, fc2_w, g1as, g1ad);
    }
    {
        cudaLaunchConfig_t cfg = {};
        cfg.gridDim = dim3(BB*NN, 1, 1);
        cfg.blockDim = dim3(256, 1, 1);
        cfg.stream = 0;
        cfg.attrs = pdl_attr;
        cfg.numAttrs = 1;
        cudaLaunchKernelEx(&cfg, k_gat1, gat1_b, gat2_w, g2as, g2ad);
    }
    {
        cudaLaunchConfig_t cfg = {};
        cfg.gridDim = dim3(96, 1, 1);
        cfg.blockDim = dim3(256, 1, 1);
        cfg.stream = 0;
        cfg.attrs = pdl_attr;
        cfg.numAttrs = 1;
        cudaLaunchKernelEx(&cfg, k_gat2, gat2_b, out);
    }
    (void)in_sizes; (void)n_in; (void)out_size;
}

// round 16
// speedup vs baseline: 1.5137x; 1.0594x over previous
#include <cuda_runtime.h>
#include <cuda_bf16.h>
#include <math.h>

#define BB 2
#define NN 384
#define CC 1024
#define HREPN 256
#define GHID 256
#define NHEADS 4
#define TOPKK 8
#define MAXDEG 400

typedef unsigned long long ull;

// ---------------- scratch (device globals; no allocation allowed) ------------
__device__ __align__(16) float g_p1 [BB*NN*HREPN];
__device__ __align__(16) float g_p2 [BB*NN*HREPN];
__device__ __align__(16) float g_xw1[BB*NN*NHEADS*GHID];
__device__ float g_as1[BB*NN*NHEADS];
__device__ float g_ad1[BB*NN*NHEADS];
__device__ int   g_nbr[BB*NN*TOPKK];
__device__ int   g_srcl[BB*NN*MAXDEG];
__device__ int   g_deg [BB*NN];
__device__ float g_xw2[BB*NN*2];
__device__ float g_as2[BB*NN];
__device__ float g_ad2[BB*NN];
// bf16 hi/lo decompositions (written once by k_split)
__device__ __align__(16) __nv_bfloat16 g_fhi[BB*NN*CC];
__device__ __align__(16) __nv_bfloat16 g_flo[BB*NN*CC];
__device__ __align__(16) __nv_bfloat16 g_whi[1024*1024];   // [n][k]
__device__ __align__(16) __nv_bfloat16 g_wlo[1024*1024];

// ---------------- f32x2 helpers ----------------------------------------------
__device__ __forceinline__ void ffma2(ull &d, ull a, ull b) {
    asm("fma.rn.f32x2 %0, %1, %2, %0;" : "+l"(d) : "l"(a), "l"(b));
}
__device__ __forceinline__ ull fma2v(ull a, ull b, ull c) {
    ull r; asm("fma.rn.f32x2 %0, %1, %2, %3;" : "=l"(r) : "l"(a), "l"(b), "l"(c)); return r;
}
__device__ __forceinline__ ull add2v(ull a, ull b) {
    ull r; asm("add.rn.f32x2 %0, %1, %2;" : "=l"(r) : "l"(a), "l"(b)); return r;
}
__device__ __forceinline__ ull pack2(float lo, float hi) {
    ull r; asm("mov.b64 %0, {%1, %2};" : "=l"(r) : "f"(lo), "f"(hi)); return r;
}
__device__ __forceinline__ void unpack2(ull v, float &lo, float &hi) {
    asm("mov.b64 {%0, %1}, %2;" : "=f"(lo), "=f"(hi) : "l"(v));
}
__device__ __forceinline__ float lo2(ull v) { return __uint_as_float((unsigned)(v & 0xffffffffull)); }
__device__ __forceinline__ float hi2(ull v) { return __uint_as_float((unsigned)(v >> 32)); }

// ---------------- PDL helpers -------------------------------------------------
__device__ __forceinline__ void pdl_wait()   { asm volatile("griddepcontrol.wait;" ::: "memory"); }
__device__ __forceinline__ void pdl_launch() { asm volatile("griddepcontrol.launch_dependents;" ::: "memory"); }

// ---------------- bf16 split + HMMA helpers -----------------------------------
__device__ __forceinline__ void bsplit(float v, unsigned short &h, unsigned short &l) {
    __nv_bfloat16 hb = __float2bfloat16(v);
    float r = v - __bfloat162float(hb);
    __nv_bfloat16 lb = __float2bfloat16(r);
    h = *(unsigned short*)&hb;
    l = *(unsigned short*)&lb;
}
__device__ __forceinline__ void hmma(float* d, const unsigned* a, const unsigned* b) {
    asm volatile(
        "mma.sync.aligned.m16n8k16.row.col.f32.bf16.bf16.f32 "
        "{%0,%1,%2,%3}, {%4,%5,%6,%7}, {%8,%9}, {%0,%1,%2,%3};"
        : "+f"(d[0]), "+f"(d[1]), "+f"(d[2]), "+f"(d[3])
        : "r"(a[0]), "r"(a[1]), "r"(a[2]), "r"(a[3]), "r"(b[0]), "r"(b[1]));
}

// ======= k_split: one-shot bf16 hi/lo decomposition of feats + gat1_w ========
__global__ __launch_bounds__(256) void k_split(
    const float* __restrict__ feats,
    const float* __restrict__ gat1_w)
{
    __shared__ float tile[32][33];
    int bid = blockIdx.x, tid = threadIdx.x;
    if (bid < 768) {
        int idx4 = (bid*256 + tid)*4;
        float4 v = *(const float4*)&feats[idx4];
        unsigned short h0,l0,h1,l1,h2,l2,h3,l3;
        bsplit(v.x,h0,l0); bsplit(v.y,h1,l1); bsplit(v.z,h2,l2); bsplit(v.w,h3,l3);
        ushort4 hs = make_ushort4(h0,h1,h2,h3);
        ushort4 ls = make_ushort4(l0,l1,l2,l3);
        *(ushort4*)&g_fhi[idx4] = hs;
        *(ushort4*)&g_flo[idx4] = ls;
    } else {
        int t = bid - 768;                 // 0..1023
        int tk0 = (t >> 5)*32, tn0 = (t & 31)*32;
        int r = tid >> 3, c4 = (tid & 7)*4;
        float4 w = *(const float4*)&gat1_w[(ull)(tk0 + r)*1024 + tn0 + c4];
        tile[r][c4+0] = w.x; tile[r][c4+1] = w.y;
        tile[r][c4+2] = w.z; tile[r][c4+3] = w.w;
        __syncthreads();
        int n = tid >> 3, k4 = (tid & 7)*4;
        unsigned short hh[4], ll[4];
        #pragma unroll
        for (int e = 0; e < 4; e++) bsplit(tile[k4+e][n], hh[e], ll[e]);
        ushort4 hs = make_ushort4(hh[0],hh[1],hh[2],hh[3]);
        ushort4 ls = make_ushort4(ll[0],ll[1],ll[2],ll[3]);
        *(ushort4*)&g_whi[(ull)(tn0 + n)*1024 + tk0 + k4] = hs;
        *(ushort4*)&g_wlo[(ull)(tn0 + n)*1024 + tk0 + k4] = ls;
    }
    pdl_launch();
}

// ===== k_gemms: 0..95 p1/p2 exact FFMA2 (64x64) | 96..143 xw1 bf16 HMMA ======
__global__ __launch_bounds__(256) void k_gemms(
    const float* __restrict__ feats,
    const float* __restrict__ fc1_w,
    const float* __restrict__ gat1_w,
    const float* __restrict__ boxes)
{
    __shared__ __align__(16) float spool[11264];   // 45KB union
    int tid = threadIdx.x;
    int bid = blockIdx.x;

    if (bid < 96) {
        // ============== p1/p2 exact fp32: 64x64 tile, K-split ===============
        int b = bid / 48; int r = bid % 48;
        int by = r / 8, bx = r % 8;
        int row0 = by*64, col0 = bx*64;
        const float* Bm; float* Cm; int dcol0;
        if (col0 < 256) { Bm = fc1_w;            Cm = g_p1 + b*NN*256; dcol0 = col0; }
        else            { Bm = fc1_w + 1024*256; Cm = g_p2 + b*NN*256; dcol0 = col0 - 256; }

        int khalf = tid >> 7, htid = tid & 127;
        float* As = spool +        khalf*2560;      // 2 bufs x 64*20
        float* Bs = spool + 5120 + khalf*2816;      // 2 bufs x 64*22
        int tx = htid & 15, ty = htid >> 4;

        ull acc[8][4];
        #pragma unroll
        for (int rr = 0; rr < 8; rr++)
            #pragma unroll
            for (int j = 0; j < 4; j++) acc[rr][j] = 0ull;

        int arow = htid >> 1, aslot = htid & 1;
        int bc = htid & 63, bk2 = htid >> 6;
        int kbase = khalf * 512;
        const float* Ap = feats + (ull)(b*NN + row0 + arow)*1024 + kbase + aslot*8;
        const float* Bp = Bm + (ull)kbase*256 + dcol0 + bc;

        float4 pa0 = *(const float4*)Ap;
        float4 pa1 = *(const float4*)(Ap + 4);
        float pb[8];
        #pragma unroll
        for (int m = 0; m < 8; m++) pb[m] = Bp[(bk2*8 + m)*256];
        *(float4*)&As[arow*20 + aslot*8]     = pa0;
        *(float4*)&As[arow*20 + aslot*8 + 4] = pa1;
        #pragma unroll
        for (int m = 0; m < 8; m++) Bs[bc*22 + bk2*8 + m] = pb[m];
        __syncthreads();

        for (int t = 0; t < 32; t++) {
            int cur = t & 1, nxt = cur ^ 1;
            if (t < 31) {
                int k0 = (t + 1) * 16;
                pa0 = *(const float4*)(Ap + k0);
                pa1 = *(const float4*)(Ap + k0 + 4);
                #pragma unroll
                for (int m = 0; m < 8; m++) pb[m] = Bp[(k0 + bk2*8 + m)*256];
            }
            #pragma unroll
            for (int kp = 0; kp < 8; kp++) {
                ull av[8], bv[4];
                #pragma unroll
                for (int rr = 0; rr < 8; rr++)
                    av[rr] = *(const ull*)&As[cur*1280 + (ty + 8*rr)*20 + 2*kp];
                #pragma unroll
                for (int j = 0; j < 4; j++)
                    bv[j] = *(const ull*)&Bs[cur*1408 + (tx + 16*j)*22 + 2*kp];
                #pragma unroll
                for (int rr = 0; rr < 8; rr++)
                    #pragma unroll
                    for (int j = 0; j < 4; j++) ffma2(acc[rr][j], av[rr], bv[j]);
            }
            if (t < 31) {
                *(float4*)&As[nxt*1280 + arow*20 + aslot*8]     = pa0;
                *(float4*)&As[nxt*1280 + arow*20 + aslot*8 + 4] = pa1;
                #pragma unroll
                for (int m = 0; m < 8; m++) Bs[nxt*1408 + bc*22 + bk2*8 + m] = pb[m];
            }
            __syncthreads();
        }

        float* comb = spool;
        if (khalf == 1) {
            #pragma unroll
            for (int rr = 0; rr < 8; rr++)
                #pragma unroll
                for (int j = 0; j < 4; j++)
                    comb[htid*33 + rr*4 + j] = lo2(acc[rr][j]) + hi2(acc[rr][j]);
        }
        __syncthreads();
        if (khalf == 0) {
            #pragma unroll
            for (int rr = 0; rr < 8; rr++) {
                int row = row0 + ty + 8*rr;
                #pragma unroll
                for (int j = 0; j < 4; j++) {
                    float s = (lo2(acc[rr][j]) + hi2(acc[rr][j])) + comb[htid*33 + rr*4 + j];
                    Cm[row*256 + dcol0 + tx + 16*j] = s;
                }
            }
        }
    } else {
        // ============== xw1 bf16 HMMA 3-pass: 128x128 tile ==================
        pdl_wait();    // g_fhi/g_flo/g_whi/g_wlo produced by k_split
        int idx = bid - 96;
        int b = idx / 24; int r = idx % 24;
        int by = r / 8, bx = r % 8;
        int row0 = by*128, col0 = bx*128;

        __nv_bfloat16* Ah = (__nv_bfloat16*)spool;             // 128x40
        __nv_bfloat16* Al = Ah + 5120;
        __nv_bfloat16* Bh = Al + 5120;                         // [n(128)][40]
        __nv_bfloat16* Bl = Bh + 5120;
        float* Wg4   = spool + 10240;                          // [4][128]
        float* sgeom = spool + 10752;                          // [4][128]

        // Wg4 + per-row geometry
        Wg4[tid]       = gat1_w[(ull)(1024 + (tid >> 7))*1024 + col0 + (tid & 127)];
        Wg4[tid + 256] = gat1_w[(ull)(1026 + (tid >> 7))*1024 + col0 + (tid & 127)];
        if (tid < 128) {
            const float* bx4 = boxes + (ull)(b*NN + row0 + tid)*4;
            float x0 = bx4[0]*(1.0f/800.0f), y0 = bx4[1]*(1.0f/800.0f);
            float x1 = bx4[2]*(1.0f/800.0f), y1 = bx4[3]*(1.0f/800.0f);
            sgeom[0*128 + tid] = x0;
            sgeom[1*128 + tid] = y0;
            sgeom[2*128 + tid] = x1 - x0;
            sgeom[3*128 + tid] = y1 - y0;
        }

        int warp = tid >> 5, lane = tid & 31;
        int g = lane >> 2, tq = (lane & 3)*2;
        int wm = warp & 1, wn = warp >> 1;        // warp tile 64x32 at (64wm, 32wn)

        float acc[4][4][4];
        #pragma unroll
        for (int i = 0; i < 4; i++)
            #pragma unroll
            for (int j = 0; j < 4; j++)
                #pragma unroll
                for (int e = 0; e < 4; e++) acc[i][j][e] = 0.f;

        int lrow = tid >> 1, lhalf = tid & 1;     // loader: row/col + 16-k half
        const __nv_bfloat16* fha = g_fhi + (ull)(b*NN + row0 + lrow)*1024 + lhalf*16;
        const __nv_bfloat16* fla = g_flo + (ull)(b*NN + row0 + lrow)*1024 + lhalf*16;
        const __nv_bfloat16* wha = g_whi + (ull)(col0 + lrow)*1024 + lhalf*16;
        const __nv_bfloat16* wla = g_wlo + (ull)(col0 + lrow)*1024 + lhalf*16;
        int soff = lrow*40 + lhalf*16;

        int4 pah0, pah1, pal0, pal1, pbh0, pbh1, pbl0, pbl1;
        pah0 = *(const int4*)(fha);      pah1 = *(const int4*)(fha + 8);
        pal0 = *(const int4*)(fla);      pal1 = *(const int4*)(fla + 8);
        pbh0 = *(const int4*)(wha);      pbh1 = *(const int4*)(wha + 8);
        pbl0 = *(const int4*)(wla);      pbl1 = *(const int4*)(wla + 8);

        for (int c = 0; c < 32; c++) {
            __syncthreads();
            *(int4*)&Ah[soff] = pah0; *(int4*)&Ah[soff + 8] = pah1;
            *(int4*)&Al[soff] = pal0; *(int4*)&Al[soff + 8] = pal1;
            *(int4*)&Bh[soff] = pbh0; *(int4*)&Bh[soff + 8] = pbh1;
            *(int4*)&Bl[soff] = pbl0; *(int4*)&Bl[soff + 8] = pbl1;
            __syncthreads();
            if (c < 31) {
                int k0 = (c + 1)*32;
                pah0 = *(const int4*)(fha + k0); pah1 = *(const int4*)(fha + k0 + 8);
                pal0 = *(const int4*)(fla + k0); pal1 = *(const int4*)(fla + k0 + 8);
                pbh0 = *(const int4*)(wha + k0); pbh1 = *(const int4*)(wha + k0 + 8);
                pbl0 = *(const int4*)(wla + k0); pbl1 = *(const int4*)(wla + k0 + 8);
            }
            #pragma unroll
            for (int ks = 0; ks < 32; ks += 16) {
                unsigned ah[4][4], al[4][4], bh[4][2], bl[4][2];
                #pragma unroll
                for (int i = 0; i < 4; i++) {
                    int R = wm*64 + i*16 + g;
                    ah[i][0] = *(const unsigned*)&Ah[ R     *40 + ks + tq];
                    ah[i][1] = *(const unsigned*)&Ah[(R + 8)*40 + ks + tq];
                    ah[i][2] = *(const unsigned*)&Ah[ R     *40 + ks + tq + 8];
                    ah[i][3] = *(const unsigned*)&Ah[(R + 8)*40 + ks + tq + 8];
                    al[i][0] = *(const unsigned*)&Al[ R     *40 + ks + tq];
                    al[i][1] = *(const unsigned*)&Al[(R + 8)*40 + ks + tq];
                    al[i][2] = *(const unsigned*)&Al[ R     *40 + ks + tq + 8];
                    al[i][3] = *(const unsigned*)&Al[(R + 8)*40 + ks + tq + 8];
                }
                #pragma unroll
                for (int j = 0; j < 4; j++) {
                    int C = wn*32 + j*8 + g;
                    bh[j][0] = *(const unsigned*)&Bh[C*40 + ks + tq];
                    bh[j][1] = *(const unsigned*)&Bh[C*40 + ks + tq + 8];
                    bl[j][0] = *(const unsigned*)&Bl[C*40 + ks + tq];
                    bl[j][1] = *(const unsigned*)&Bl[C*40 + ks + tq + 8];
                }
                #pragma unroll
                for (int i = 0; i < 4; i++)
                    #pragma unroll
                    for (int j = 0; j < 4; j++) {
                        hmma(acc[i][j], ah[i], bh[j]);
                        hmma(acc[i][j], al[i], bh[j]);
                        hmma(acc[i][j], ah[i], bl[j]);
                    }
            }
        }
        __syncthreads();

        // epilogue: geometry fold + store
        int tqc = (lane & 3)*2;
        #pragma unroll
        for (int i = 0; i < 4; i++) {
            int r1 = wm*64 + i*16 + g;
            int r2 = r1 + 8;
            #pragma unroll
            for (int j = 0; j < 4; j++) {
                int cl = wn*32 + j*8 + tqc;
                float w00 = Wg4[cl],     w01 = Wg4[cl+1];
                float w10 = Wg4[128+cl], w11 = Wg4[128+cl+1];
                float w20 = Wg4[256+cl], w21 = Wg4[256+cl+1];
                float w30 = Wg4[384+cl], w31 = Wg4[384+cl+1];
                float s0 = acc[i][j][0], s1 = acc[i][j][1];
                s0 = fmaf(sgeom[r1],     w00, s0); s1 = fmaf(sgeom[r1],     w01, s1);
                s0 = fmaf(sgeom[128+r1], w10, s0); s1 = fmaf(sgeom[128+r1], w11, s1);
                s0 = fmaf(sgeom[256+r1], w20, s0); s1 = fmaf(sgeom[256+r1], w21, s1);
                s0 = fmaf(sgeom[384+r1], w30, s0); s1 = fmaf(sgeom[384+r1], w31, s1);
                *(float2*)&g_xw1[(ull)(b*NN + row0 + r1)*1024 + col0 + cl] = make_float2(s0, s1);
                float s2 = acc[i][j][2], s3 = acc[i][j][3];
                s2 = fmaf(sgeom[r2],     w00, s2); s3 = fmaf(sgeom[r2],     w01, s3);
                s2 = fmaf(sgeom[128+r2], w10, s2); s3 = fmaf(sgeom[128+r2], w11, s3);
                s2 = fmaf(sgeom[256+r2], w20, s2); s3 = fmaf(sgeom[256+r2], w21, s3);
                s2 = fmaf(sgeom[384+r2], w30, s2); s3 = fmaf(sgeom[384+r2], w31, s3);
                *(float2*)&g_xw1[(ull)(b*NN + row0 + r2)*1024 + col0 + cl] = make_float2(s2, s3);
            }
        }
    }
    pdl_launch();
}

// ------- merged: relation scores + top-8 (blocks 0..191)  |  asad (192..575) -
__global__ __launch_bounds__(256) void k_rel_asad(
    const float* __restrict__ boxes,
    const float* __restrict__ fc1_w,
    const float* __restrict__ fc1_b,
    const float* __restrict__ fc2_w,
    const float* __restrict__ att_src,
    const float* __restrict__ att_dst)
{
    __shared__ float srow[4][NN];
    __shared__ float sbx[16];
    int bid = blockIdx.x;
    int tid = threadIdx.x, warp = tid >> 5, lane = tid & 31;

    if (bid >= 192) {
        int h = (tid >> 5) & 3;
        const float* asr = att_src + h*256 + lane*8;
        const float* adr = att_dst + h*256 + lane*8;
        float4 s0 = *(const float4*)asr;
        float4 s1 = *(const float4*)(asr + 4);
        float4 d0 = *(const float4*)adr;
        float4 d1 = *(const float4*)(adr + 4);
        pdl_wait();
        int bn = (bid - 192)*2 + (tid >> 7);
        const float* xw = g_xw1 + bn*1024 + h*256 + lane*8;
        float4 v0 = *(const float4*)xw;
        float4 v1 = *(const float4*)(xw + 4);
        float ss = v0.x*s0.x + v0.y*s0.y + v0.z*s0.z + v0.w*s0.w
                 + v1.x*s1.x + v1.y*s1.y + v1.z*s1.z + v1.w*s1.w;
        float dd = v0.x*d0.x + v0.y*d0.y + v0.z*d0.z + v0.w*d0.w
                 + v1.x*d1.x + v1.y*d1.y + v1.z*d1.z + v1.w*d1.w;
        #pragma unroll
        for (int o = 16; o; o >>= 1) {
            ss += __shfl_down_sync(0xffffffffu, ss, o);
            dd += __shfl_down_sync(0xffffffffu, dd, o);
        }
        if (lane == 0) { g_as1[bn*4 + h] = ss; g_ad1[bn*4 + h] = dd; }
        pdl_launch();
        return;
    }

    int b = bid / 96, igrp = bid % 96;
    int i0 = igrp * 4;

    if (tid < 16) sbx[tid] = boxes[(b*NN + i0 + (tid >> 2))*4 + (tid & 3)];

    ull wg2[4][4], sp1q[4][4];
    float w2lo[4], w2hi[4], bb0[4], bb1[4];
    #pragma unroll
    for (int p = 0; p < 4; p++) {
        int k0 = lane + 64*p, k1 = k0 + 32;
        w2lo[p] = fc2_w[k0];
        w2hi[p] = fc2_w[k1];
        #pragma unroll
        for (int d = 0; d < 4; d++)
            wg2[d][p] = pack2(fc1_w[(2048+d)*256 + k0], fc1_w[(2048+d)*256 + k1]);
        bb0[p] = fc1_b[k0];
        bb1[p] = fc1_b[k1];
    }
    pdl_wait();
    #pragma unroll
    for (int p = 0; p < 4; p++) {
        int k0 = lane + 64*p, k1 = k0 + 32;
        #pragma unroll
        for (int q = 0; q < 4; q++) {
            const float* p1r = g_p1 + (b*NN + i0 + q)*256;
            sp1q[q][p] = pack2(p1r[k0] + bb0[p], p1r[k1] + bb1[p]);
        }
    }
    __syncthreads();

    const float* p2b = g_p2 + b*NN*256;
    const float* bxb = boxes + b*NN*4;

    for (int j = warp; j < NN; j += 8) {
        float4 bj = *(const float4*)&bxb[j*4];
        ull p2v[4];
        #pragma unroll
        for (int p = 0; p < 4; p++) {
            int k0 = lane + 64*p;
            p2v[p] = pack2(p2b[j*256 + k0], p2b[j*256 + k0 + 32]);
        }
        #pragma unroll
        for (int q = 0; q < 4; q++) {
            float d0 = fabsf(sbx[q*4+0] - bj.x);
            float d1 = fabsf(sbx[q*4+1] - bj.y);
            float d2 = fabsf(sbx[q*4+2] - bj.z);
            float d3 = fabsf(sbx[q*4+3] - bj.w);
            ull a0 = pack2(d0, d0), a1 = pack2(d1, d1);
            ull a2 = pack2(d2, d2), a3 = pack2(d3, d3);
            float sum = 0.f;
            #pragma unroll
            for (int p = 0; p < 4; p++) {
                ull t2 = add2v(sp1q[q][p], p2v[p]);
                t2 = fma2v(a0, wg2[0][p], t2);
                t2 = fma2v(a1, wg2[1][p], t2);
                t2 = fma2v(a2, wg2[2][p], t2);
                t2 = fma2v(a3, wg2[3][p], t2);
                float tl, th;
                unpack2(t2, tl, th);
                tl = fmaxf(tl, 0.f);
                th = fmaxf(th, 0.f);
                sum = fmaf(tl, w2lo[p], sum);
                sum = fmaf(th, w2hi[p], sum);
            }
            #pragma unroll
            for (int o = 16; o; o >>= 1) sum += __shfl_down_sync(0xffffffffu, sum, o);
            if (lane == 0)
                srow[q][j] = sum - ((j == i0 + q) ? 1e6f : 0.f);
        }
    }
    __syncthreads();

    if (warp < 4) {
        int q = warp, i = i0 + q;
        for (int sel2 = 0; sel2 < TOPKK; sel2++) {
            float bv = -3.4e38f; int bi = 1 << 30;
            for (int j = lane; j < NN; j += 32) {
                float v = srow[q][j];
                if (v > bv || (v == bv && j < bi)) { bv = v; bi = j; }
            }
            #pragma unroll
            for (int o = 16; o; o >>= 1) {
                float ov = __shfl_xor_sync(0xffffffffu, bv, o);
                int   oi = __shfl_xor_sync(0xffffffffu, bi, o);
                if (ov > bv || (ov == bv && oi < bi)) { bv = ov; bi = oi; }
            }
            if (lane == 0) {
                g_nbr[(b*NN + i)*TOPKK + sel2] = bi;
                srow[q][bi] = -3.4e38f;
            }
            __syncwarp();
        }
    }
    pdl_launch();
}

// -------- GAT1: warp-shfl scan build + softmax + float4 aggregate + xw2 ------
__global__ __launch_bounds__(256) void k_gat1(
    const float* __restrict__ gat1_b,
    const float* __restrict__ gat2_w,
    const float* __restrict__ att_src2,
    const float* __restrict__ att_dst2)
{
    int bn = blockIdx.x; int b = bn / NN, tt = bn % NN;
    __shared__ int   ssrc[MAXDEG];
    __shared__ float sal[NHEADS][MAXDEG];
    __shared__ float sas1[NN*4];
    __shared__ int   wtot[8];
    __shared__ float red[8][2];
    int tid = threadIdx.x;
    int warp = tid >> 5, lane = tid & 31;

    pdl_wait();

    #pragma unroll
    for (int it = 0; it < 6; it++)
        sas1[tid + it*256] = g_as1[b*NN*4 + tid + it*256];

    const int* nb = g_nbr + b*NN*TOPKK;
    int myc0 = 0, myc1 = 0;
    int ia = 2*tid, ib2 = 2*tid + 1;
    if (tid < 192) {
        #pragma unroll
        for (int k = 0; k < TOPKK; k++) {
            myc0 += (nb[ia*TOPKK + k] == tt);
            myc1 += (nb[ib2*TOPKK + k] == tt);
        }
    }
    int cnt = myc0 + myc1;
    int incl = cnt;
    #pragma unroll
    for (int d = 1; d < 32; d <<= 1) {
        int v = __shfl_up_sync(0xffffffffu, incl, d);
        if (lane >= d) incl += v;
    }
    if (lane == 31) wtot[warp] = incl;
    __syncthreads();
    int woff = 0, total = 0;
    #pragma unroll
    for (int w = 0; w < 8; w++) {
        int v = wtot[w];
        if (w < warp) woff += v;
        total += v;
    }
    int off = woff + incl - cnt;
    int* dst = g_srcl + bn*MAXDEG;
    if (tid < 192) {
        if (myc0) {
            #pragma unroll
            for (int k = 0; k < TOPKK; k++)
                if (nb[ia*TOPKK + k] == tt) { ssrc[off] = ia; dst[off] = ia; off++; }
        }
        if (myc1) {
            #pragma unroll
            for (int k = 0; k < TOPKK; k++)
                if (nb[ib2*TOPKK + k] == tt) { ssrc[off] = ib2; dst[off] = ib2; off++; }
        }
    }
    if (tid == 0) {
        ssrc[total] = tt;
        dst[total] = tt;
        g_deg[bn] = total + 1;
    }
    __syncthreads();
    int deg = total + 1;

    if (warp < NHEADS) {
        int h = warp;
        float adv = g_ad1[bn*4 + h];
        float m = -3.4e38f;
        for (int s = lane; s < deg; s += 32) {
            float e = sas1[ssrc[s]*4 + h] + adv;
            e = (e >= 0.f) ? e : 0.2f*e;
            sal[h][s] = e;
            m = fmaxf(m, e);
        }
        #pragma unroll
        for (int o = 16; o; o >>= 1) m = fmaxf(m, __shfl_xor_sync(0xffffffffu, m, o));
        float sum = 0.f;
        for (int s = lane; s < deg; s += 32) {
            float ex = expf(sal[h][s] - m);
            sal[h][s] = ex;
            sum += ex;
        }
        #pragma unroll
        for (int o = 16; o; o >>= 1) sum += __shfl_xor_sync(0xffffffffu, sum, o);
        float inv = 1.f / fmaxf(sum, 1e-16f);
        for (int s = lane; s < deg; s += 32) sal[h][s] *= inv;
    }
    __syncthreads();

    const float* xwb = g_xw1 + b*NN*1024;
    const float* salh = sal[tid >> 6];
    float4 acc0 = make_float4(0.f, 0.f, 0.f, 0.f);
    float4 acc1 = make_float4(0.f, 0.f, 0.f, 0.f);
    int col4 = tid * 4;
    int s = 0;
    for (; s + 1 < deg; s += 2) {
        float4 v0 = *(const float4*)&xwb[ssrc[s  ]*1024 + col4];
        float4 v1 = *(const float4*)&xwb[ssrc[s+1]*1024 + col4];
        float a0 = salh[s], a1 = salh[s+1];
        acc0.x = fmaf(v0.x, a0, acc0.x); acc0.y = fmaf(v0.y, a0, acc0.y);
        acc0.z = fmaf(v0.z, a0, acc0.z); acc0.w = fmaf(v0.w, a0, acc0.w);
        acc1.x = fmaf(v1.x, a1, acc1.x); acc1.y = fmaf(v1.y, a1, acc1.y);
        acc1.z = fmaf(v1.z, a1, acc1.z); acc1.w = fmaf(v1.w, a1, acc1.w);
    }
    if (s < deg) {
        float4 v0 = *(const float4*)&xwb[ssrc[s]*1024 + col4];
        float a0 = salh[s];
        acc0.x = fmaf(v0.x, a0, acc0.x); acc0.y = fmaf(v0.y, a0, acc0.y);
        acc0.z = fmaf(v0.z, a0, acc0.z); acc0.w = fmaf(v0.w, a0, acc0.w);
    }
    float4 bia = *(const float4*)&gat1_b[col4];
    float4 oh;
    oh.x = fmaxf(acc0.x + acc1.x + bia.x, 0.f);
    oh.y = fmaxf(acc0.y + acc1.y + bia.y, 0.f);
    oh.z = fmaxf(acc0.z + acc1.z + bia.z, 0.f);
    oh.w = fmaxf(acc0.w + acc1.w + bia.w, 0.f);

    float4 w0 = *(const float4*)&gat2_w[col4*2];
    float4 w1 = *(const float4*)&gat2_w[col4*2 + 4];
    float c0 = oh.x*w0.x + oh.y*w0.z + oh.z*w1.x + oh.w*w1.z;
    float c1 = oh.x*w0.y + oh.y*w0.w + oh.z*w1.y + oh.w*w1.w;
    #pragma unroll
    for (int o = 16; o; o >>= 1) {
        c0 += __shfl_down_sync(0xffffffffu, c0, o);
        c1 += __shfl_down_sync(0xffffffffu, c1, o);
    }
    if (lane == 0) { red[warp][0] = c0; red[warp][1] = c1; }
    __syncthreads();
    if (tid == 0) {
        float s0 = 0.f, s1 = 0.f;
        #pragma unroll
        for (int w = 0; w < 8; w++) { s0 += red[w][0]; s1 += red[w][1]; }
        g_xw2[bn*2 + 0] = s0;
        g_xw2[bn*2 + 1] = s1;
        g_as2[bn] = s0*att_src2[0] + s1*att_src2[1];
        g_ad2[bn] = s0*att_dst2[0] + s1*att_dst2[1];
    }
    pdl_launch();
}

// ------- GAT layer 2: 8 nodes/block, batch as2/xw2 preloaded into smem -------
__global__ __launch_bounds__(256) void k_gat2(const float* __restrict__ gat2_b,
                                              float* __restrict__ out)
{
    __shared__ float s_as2[NN];
    __shared__ float s_xw2[NN*2];
    __shared__ float sal[8][MAXDEG];
    __shared__ int   ssrc[8][MAXDEG];
    int tid = threadIdx.x;
    int warp = tid >> 5, lane = tid & 31;
    int n0 = blockIdx.x * 8;
    int b = n0 / NN;

    pdl_wait();

    for (int i = tid; i < NN; i += 256)   s_as2[i] = g_as2[b*NN + i];
    for (int i = tid; i < NN*2; i += 256) s_xw2[i] = g_xw2[b*NN*2 + i];
    __syncthreads();

    int bn = n0 + warp;
    int deg = g_deg[bn];
    for (int s = lane; s < deg; s += 32) ssrc[warp][s] = g_srcl[bn*MAXDEG + s];
    __syncwarp();
    float adv = g_ad2[bn];
    float m = -3.4e38f;
    for (int s = lane; s < deg; s += 32) {
        float e = s_as2[ssrc[warp][s]] + adv;
        e = (e >= 0.f) ? e : 0.2f*e;
        sal[warp][s] = e;
        m = fmaxf(m, e);
    }
    #pragma unroll
    for (int o = 16; o; o >>= 1) m = fmaxf(m, __shfl_xor_sync(0xffffffffu, m, o));
    float sum = 0.f;
    for (int s = lane; s < deg; s += 32) {
        float ex = expf(sal[warp][s] - m);
        sal[warp][s] = ex;
        sum += ex;
    }
    #pragma unroll
    for (int o = 16; o; o >>= 1) sum += __shfl_xor_sync(0xffffffffu, sum, o);
    float inv = 1.f / fmaxf(sum, 1e-16f);
    __syncwarp();
    float a0 = 0.f, a1 = 0.f;
    for (int s = lane; s < deg; s += 32) {
        float w = sal[warp][s] * inv;
        int sc = ssrc[warp][s];
        a0 = fmaf(s_xw2[sc*2 + 0], w, a0);
        a1 = fmaf(s_xw2[sc*2 + 1], w, a1);
    }
    #pragma unroll
    for (int o = 16; o; o >>= 1) {
        a0 += __shfl_down_sync(0xffffffffu, a0, o);
        a1 += __shfl_down_sync(0xffffffffu, a1, o);
    }
    if (lane == 0) {
        out[bn*2 + 0] = a0 + gat2_b[0];
        out[bn*2 + 1] = a1 + gat2_b[1];
    }
}

// ---------------- launch ------------------------------------------------------
extern "C" void kernel_launch(void* const* d_in, const int* in_sizes, int n_in,
                              void* d_out, int out_size)
{
    const float* feats   = (const float*)d_in[0];
    const float* boxes   = (const float*)d_in[1];
    const float* fc1_w   = (const float*)d_in[2];
    const float* fc1_b   = (const float*)d_in[3];
    const float* fc2_w   = (const float*)d_in[4];
    // d_in[5] = fc2_b : constant shift, irrelevant for top-k
    const float* gat1_w  = (const float*)d_in[6];
    const float* g1as    = (const float*)d_in[7];
    const float* g1ad    = (const float*)d_in[8];
    const float* gat1_b  = (const float*)d_in[9];
    const float* gat2_w  = (const float*)d_in[10];
    const float* g2as    = (const float*)d_in[11];
    const float* g2ad    = (const float*)d_in[12];
    const float* gat2_b  = (const float*)d_in[13];
    float* out = (float*)d_out;

    cudaLaunchAttribute pdl_attr[1];
    pdl_attr[0].id = cudaLaunchAttributeProgrammaticStreamSerialization;
    pdl_attr[0].val.programmaticStreamSerializationAllowed = 1;

    k_split<<<1792, 256>>>(feats, gat1_w);
    {
        cudaLaunchConfig_t cfg = {};
        cfg.gridDim = dim3(144, 1, 1);
        cfg.blockDim = dim3(256, 1, 1);
        cfg.stream = 0;
        cfg.attrs = pdl_attr;
        cfg.numAttrs = 1;
        cudaLaunchKernelEx(&cfg, k_gemms, feats, fc1_w, gat1_w, boxes);
    }
    {
        cudaLaunchConfig_t cfg = {};
        cfg.gridDim = dim3(192 + 384, 1, 1);
        cfg.blockDim = dim3(256, 1, 1);
        cfg.stream = 0;
        cfg.attrs = pdl_attr;
        cfg.numAttrs = 1;
        cudaLaunchKernelEx(&cfg, k_rel_asad, boxes, fc1_w, fc1_b, fc2_w, g1as, g1ad);
    }
    {
        cudaLaunchConfig_t cfg = {};
        cfg.gridDim = dim3(BB*NN, 1, 1);
        cfg.blockDim = dim3(256, 1, 1);
        cfg.stream = 0;
        cfg.attrs = pdl_attr;
        cfg.numAttrs = 1;
        cudaLaunchKernelEx(&cfg, k_gat1, gat1_b, gat2_w, g2as, g2ad);
    }
    {
        cudaLaunchConfig_t cfg = {};
        cfg.gridDim = dim3(96, 1, 1);
        cfg.blockDim = dim3(256, 1, 1);
        cfg.stream = 0;
        cfg.attrs = pdl_attr;
        cfg.numAttrs = 1;
        cudaLaunchKernelEx(&cfg, k_gat2, gat2_b, out);
    }
    (void)in_sizes; (void)n_in; (void)out_size;
}

// round 17
// speedup vs baseline: 1.5430x; 1.0193x over previous
#include <cuda_runtime.h>
#include <cuda_bf16.h>
#include <math.h>

#define BB 2
#define NN 384
#define CC 1024
#define HREPN 256
#define GHID 256
#define NHEADS 4
#define TOPKK 8
#define MAXDEG 400

typedef unsigned long long ull;

// ---------------- scratch (device globals; no allocation allowed) ------------
__device__ __align__(16) float g_p1 [BB*NN*HREPN];
__device__ __align__(16) float g_p2 [BB*NN*HREPN];
__device__ __align__(16) float g_xw1[BB*NN*NHEADS*GHID];
__device__ float g_as1[BB*NN*NHEADS];
__device__ float g_ad1[BB*NN*NHEADS];
__device__ int   g_nbr[BB*NN*TOPKK];
__device__ int   g_srcl[BB*NN*MAXDEG];
__device__ int   g_deg [BB*NN];
__device__ float g_xw2[BB*NN*2];
__device__ float g_as2[BB*NN];
__device__ float g_ad2[BB*NN];
// bf16 hi/lo decompositions (written once by k_split)
__device__ __align__(16) __nv_bfloat16 g_fhi[BB*NN*CC];
__device__ __align__(16) __nv_bfloat16 g_flo[BB*NN*CC];
__device__ __align__(16) __nv_bfloat16 g_whi[1024*1024];   // [n][k]
__device__ __align__(16) __nv_bfloat16 g_wlo[1024*1024];

// ---------------- f32x2 helpers ----------------------------------------------
__device__ __forceinline__ void ffma2(ull &d, ull a, ull b) {
    asm("fma.rn.f32x2 %0, %1, %2, %0;" : "+l"(d) : "l"(a), "l"(b));
}
__device__ __forceinline__ ull fma2v(ull a, ull b, ull c) {
    ull r; asm("fma.rn.f32x2 %0, %1, %2, %3;" : "=l"(r) : "l"(a), "l"(b), "l"(c)); return r;
}
__device__ __forceinline__ ull add2v(ull a, ull b) {
    ull r; asm("add.rn.f32x2 %0, %1, %2;" : "=l"(r) : "l"(a), "l"(b)); return r;
}
__device__ __forceinline__ ull pack2(float lo, float hi) {
    ull r; asm("mov.b64 %0, {%1, %2};" : "=l"(r) : "f"(lo), "f"(hi)); return r;
}
__device__ __forceinline__ void unpack2(ull v, float &lo, float &hi) {
    asm("mov.b64 {%0, %1}, %2;" : "=f"(lo), "=f"(hi) : "l"(v));
}
__device__ __forceinline__ float lo2(ull v) { return __uint_as_float((unsigned)(v & 0xffffffffull)); }
__device__ __forceinline__ float hi2(ull v) { return __uint_as_float((unsigned)(v >> 32)); }

// ---------------- PDL helpers -------------------------------------------------
__device__ __forceinline__ void pdl_wait()   { asm volatile("griddepcontrol.wait;" ::: "memory"); }
__device__ __forceinline__ void pdl_launch() { asm volatile("griddepcontrol.launch_dependents;" ::: "memory"); }

// ---------------- bf16 split + HMMA helpers -----------------------------------
__device__ __forceinline__ void bsplit(float v, unsigned short &h, unsigned short &l) {
    __nv_bfloat16 hb = __float2bfloat16(v);
    float r = v - __bfloat162float(hb);
    __nv_bfloat16 lb = __float2bfloat16(r);
    h = *(unsigned short*)&hb;
    l = *(unsigned short*)&lb;
}
__device__ __forceinline__ void hmma(float* d, const unsigned* a, const unsigned* b) {
    asm volatile(
        "mma.sync.aligned.m16n8k16.row.col.f32.bf16.bf16.f32 "
        "{%0,%1,%2,%3}, {%4,%5,%6,%7}, {%8,%9}, {%0,%1,%2,%3};"
        : "+f"(d[0]), "+f"(d[1]), "+f"(d[2]), "+f"(d[3])
        : "r"(a[0]), "r"(a[1]), "r"(a[2]), "r"(a[3]), "r"(b[0]), "r"(b[1]));
}

// ======= k_split: one-shot bf16 hi/lo decomposition of feats + gat1_w ========
__global__ __launch_bounds__(256) void k_split(
    const float* __restrict__ feats,
    const float* __restrict__ gat1_w)
{
    __shared__ float tile[32][33];
    int bid = blockIdx.x, tid = threadIdx.x;
    if (bid < 768) {
        int idx4 = (bid*256 + tid)*4;
        float4 v = *(const float4*)&feats[idx4];
        unsigned short h0,l0,h1,l1,h2,l2,h3,l3;
        bsplit(v.x,h0,l0); bsplit(v.y,h1,l1); bsplit(v.z,h2,l2); bsplit(v.w,h3,l3);
        ushort4 hs = make_ushort4(h0,h1,h2,h3);
        ushort4 ls = make_ushort4(l0,l1,l2,l3);
        *(ushort4*)&g_fhi[idx4] = hs;
        *(ushort4*)&g_flo[idx4] = ls;
    } else {
        int t = bid - 768;                 // 0..1023
        int tk0 = (t >> 5)*32, tn0 = (t & 31)*32;
        int r = tid >> 3, c4 = (tid & 7)*4;
        float4 w = *(const float4*)&gat1_w[(ull)(tk0 + r)*1024 + tn0 + c4];
        tile[r][c4+0] = w.x; tile[r][c4+1] = w.y;
        tile[r][c4+2] = w.z; tile[r][c4+3] = w.w;
        __syncthreads();
        int n = tid >> 3, k4 = (tid & 7)*4;
        unsigned short hh[4], ll[4];
        #pragma unroll
        for (int e = 0; e < 4; e++) bsplit(tile[k4+e][n], hh[e], ll[e]);
        ushort4 hs = make_ushort4(hh[0],hh[1],hh[2],hh[3]);
        ushort4 ls = make_ushort4(ll[0],ll[1],ll[2],ll[3]);
        *(ushort4*)&g_whi[(ull)(tn0 + n)*1024 + tk0 + k4] = hs;
        *(ushort4*)&g_wlo[(ull)(tn0 + n)*1024 + tk0 + k4] = ls;
    }
    pdl_launch();
}

// ===== k_gemms: 0..95 p1/p2 exact FFMA2 (64x64) | 96..143 xw1 bf16 HMMA ======
__global__ __launch_bounds__(256) void k_gemms(
    const float* __restrict__ feats,
    const float* __restrict__ fc1_w,
    const float* __restrict__ gat1_w,
    const float* __restrict__ boxes)
{
    __shared__ __align__(16) float spool[11264];   // 45KB union
    int tid = threadIdx.x;
    int bid = blockIdx.x;

    if (bid < 96) {
        // ============== p1/p2 exact fp32: 64x64 tile, K-split ===============
        int b = bid / 48; int r = bid % 48;
        int by = r / 8, bx = r % 8;
        int row0 = by*64, col0 = bx*64;
        const float* Bm; float* Cm; int dcol0;
        if (col0 < 256) { Bm = fc1_w;            Cm = g_p1 + b*NN*256; dcol0 = col0; }
        else            { Bm = fc1_w + 1024*256; Cm = g_p2 + b*NN*256; dcol0 = col0 - 256; }

        int khalf = tid >> 7, htid = tid & 127;
        float* As = spool +        khalf*2560;      // 2 bufs x 64*20
        float* Bs = spool + 5120 + khalf*2816;      // 2 bufs x 64*22
        int tx = htid & 15, ty = htid >> 4;

        ull acc[8][4];
        #pragma unroll
        for (int rr = 0; rr < 8; rr++)
            #pragma unroll
            for (int j = 0; j < 4; j++) acc[rr][j] = 0ull;

        int arow = htid >> 1, aslot = htid & 1;
        int bc = htid & 63, bk2 = htid >> 6;
        int kbase = khalf * 512;
        const float* Ap = feats + (ull)(b*NN + row0 + arow)*1024 + kbase + aslot*8;
        const float* Bp = Bm + (ull)kbase*256 + dcol0 + bc;

        float4 pa0 = *(const float4*)Ap;
        float4 pa1 = *(const float4*)(Ap + 4);
        float pb[8];
        #pragma unroll
        for (int m = 0; m < 8; m++) pb[m] = Bp[(bk2*8 + m)*256];
        *(float4*)&As[arow*20 + aslot*8]     = pa0;
        *(float4*)&As[arow*20 + aslot*8 + 4] = pa1;
        #pragma unroll
        for (int m = 0; m < 8; m++) Bs[bc*22 + bk2*8 + m] = pb[m];
        __syncthreads();

        for (int t = 0; t < 32; t++) {
            int cur = t & 1, nxt = cur ^ 1;
            if (t < 31) {
                int k0 = (t + 1) * 16;
                pa0 = *(const float4*)(Ap + k0);
                pa1 = *(const float4*)(Ap + k0 + 4);
                #pragma unroll
                for (int m = 0; m < 8; m++) pb[m] = Bp[(k0 + bk2*8 + m)*256];
            }
            #pragma unroll
            for (int kp = 0; kp < 8; kp++) {
                ull av[8], bv[4];
                #pragma unroll
                for (int rr = 0; rr < 8; rr++)
                    av[rr] = *(const ull*)&As[cur*1280 + (ty + 8*rr)*20 + 2*kp];
                #pragma unroll
                for (int j = 0; j < 4; j++)
                    bv[j] = *(const ull*)&Bs[cur*1408 + (tx + 16*j)*22 + 2*kp];
                #pragma unroll
                for (int rr = 0; rr < 8; rr++)
                    #pragma unroll
                    for (int j = 0; j < 4; j++) ffma2(acc[rr][j], av[rr], bv[j]);
            }
            if (t < 31) {
                *(float4*)&As[nxt*1280 + arow*20 + aslot*8]     = pa0;
                *(float4*)&As[nxt*1280 + arow*20 + aslot*8 + 4] = pa1;
                #pragma unroll
                for (int m = 0; m < 8; m++) Bs[nxt*1408 + bc*22 + bk2*8 + m] = pb[m];
            }
            __syncthreads();
        }

        float* comb = spool;
        if (khalf == 1) {
            #pragma unroll
            for (int rr = 0; rr < 8; rr++)
                #pragma unroll
                for (int j = 0; j < 4; j++)
                    comb[htid*33 + rr*4 + j] = lo2(acc[rr][j]) + hi2(acc[rr][j]);
        }
        __syncthreads();
        if (khalf == 0) {
            #pragma unroll
            for (int rr = 0; rr < 8; rr++) {
                int row = row0 + ty + 8*rr;
                #pragma unroll
                for (int j = 0; j < 4; j++) {
                    float s = (lo2(acc[rr][j]) + hi2(acc[rr][j])) + comb[htid*33 + rr*4 + j];
                    Cm[row*256 + dcol0 + tx + 16*j] = s;
                }
            }
        }
    } else {
        // ============== xw1 bf16 HMMA 3-pass: 128x128 tile ==================
        pdl_wait();    // g_fhi/g_flo/g_whi/g_wlo produced by k_split
        int idx = bid - 96;
        int b = idx / 24; int r = idx % 24;
        int by = r / 8, bx = r % 8;
        int row0 = by*128, col0 = bx*128;

        __nv_bfloat16* Ah = (__nv_bfloat16*)spool;             // 128x40
        __nv_bfloat16* Al = Ah + 5120;
        __nv_bfloat16* Bh = Al + 5120;                         // [n(128)][40]
        __nv_bfloat16* Bl = Bh + 5120;
        float* Wg4   = spool + 10240;                          // [4][128]
        float* sgeom = spool + 10752;                          // [4][128]

        Wg4[tid]       = gat1_w[(ull)(1024 + (tid >> 7))*1024 + col0 + (tid & 127)];
        Wg4[tid + 256] = gat1_w[(ull)(1026 + (tid >> 7))*1024 + col0 + (tid & 127)];
        if (tid < 128) {
            const float* bx4 = boxes + (ull)(b*NN + row0 + tid)*4;
            float x0 = bx4[0]*(1.0f/800.0f), y0 = bx4[1]*(1.0f/800.0f);
            float x1 = bx4[2]*(1.0f/800.0f), y1 = bx4[3]*(1.0f/800.0f);
            sgeom[0*128 + tid] = x0;
            sgeom[1*128 + tid] = y0;
            sgeom[2*128 + tid] = x1 - x0;
            sgeom[3*128 + tid] = y1 - y0;
        }

        int warp = tid >> 5, lane = tid & 31;
        int g = lane >> 2, tq = (lane & 3)*2;
        int wm = warp & 1, wn = warp >> 1;        // warp tile 64x32 at (64wm, 32wn)

        float acc[4][4][4];
        #pragma unroll
        for (int i = 0; i < 4; i++)
            #pragma unroll
            for (int j = 0; j < 4; j++)
                #pragma unroll
                for (int e = 0; e < 4; e++) acc[i][j][e] = 0.f;

        int lrow = tid >> 1, lhalf = tid & 1;
        const __nv_bfloat16* fha = g_fhi + (ull)(b*NN + row0 + lrow)*1024 + lhalf*16;
        const __nv_bfloat16* fla = g_flo + (ull)(b*NN + row0 + lrow)*1024 + lhalf*16;
        const __nv_bfloat16* wha = g_whi + (ull)(col0 + lrow)*1024 + lhalf*16;
        const __nv_bfloat16* wla = g_wlo + (ull)(col0 + lrow)*1024 + lhalf*16;
        int soff = lrow*40 + lhalf*16;

        int4 pah0, pah1, pal0, pal1, pbh0, pbh1, pbl0, pbl1;
        pah0 = *(const int4*)(fha);      pah1 = *(const int4*)(fha + 8);
        pal0 = *(const int4*)(fla);      pal1 = *(const int4*)(fla + 8);
        pbh0 = *(const int4*)(wha);      pbh1 = *(const int4*)(wha + 8);
        pbl0 = *(const int4*)(wla);      pbl1 = *(const int4*)(wla + 8);

        for (int c = 0; c < 32; c++) {
            __syncthreads();
            *(int4*)&Ah[soff] = pah0; *(int4*)&Ah[soff + 8] = pah1;
            *(int4*)&Al[soff] = pal0; *(int4*)&Al[soff + 8] = pal1;
            *(int4*)&Bh[soff] = pbh0; *(int4*)&Bh[soff + 8] = pbh1;
            *(int4*)&Bl[soff] = pbl0; *(int4*)&Bl[soff + 8] = pbl1;
            __syncthreads();
            if (c < 31) {
                int k0 = (c + 1)*32;
                pah0 = *(const int4*)(fha + k0); pah1 = *(const int4*)(fha + k0 + 8);
                pal0 = *(const int4*)(fla + k0); pal1 = *(const int4*)(fla + k0 + 8);
                pbh0 = *(const int4*)(wha + k0); pbh1 = *(const int4*)(wha + k0 + 8);
                pbl0 = *(const int4*)(wla + k0); pbl1 = *(const int4*)(wla + k0 + 8);
            }
            #pragma unroll
            for (int ks = 0; ks < 32; ks += 16) {
                unsigned ah[4][4], al[4][4], bh[4][2], bl[4][2];
                #pragma unroll
                for (int i = 0; i < 4; i++) {
                    int R = wm*64 + i*16 + g;
                    ah[i][0] = *(const unsigned*)&Ah[ R     *40 + ks + tq];
                    ah[i][1] = *(const unsigned*)&Ah[(R + 8)*40 + ks + tq];
                    ah[i][2] = *(const unsigned*)&Ah[ R     *40 + ks + tq + 8];
                    ah[i][3] = *(const unsigned*)&Ah[(R + 8)*40 + ks + tq + 8];
                    al[i][0] = *(const unsigned*)&Al[ R     *40 + ks + tq];
                    al[i][1] = *(const unsigned*)&Al[(R + 8)*40 + ks + tq];
                    al[i][2] = *(const unsigned*)&Al[ R     *40 + ks + tq + 8];
                    al[i][3] = *(const unsigned*)&Al[(R + 8)*40 + ks + tq + 8];
                }
                #pragma unroll
                for (int j = 0; j < 4; j++) {
                    int C = wn*32 + j*8 + g;
                    bh[j][0] = *(const unsigned*)&Bh[C*40 + ks + tq];
                    bh[j][1] = *(const unsigned*)&Bh[C*40 + ks + tq + 8];
                    bl[j][0] = *(const unsigned*)&Bl[C*40 + ks + tq];
                    bl[j][1] = *(const unsigned*)&Bl[C*40 + ks + tq + 8];
                }
                #pragma unroll
                for (int i = 0; i < 4; i++)
                    #pragma unroll
                    for (int j = 0; j < 4; j++) {
                        hmma(acc[i][j], ah[i], bh[j]);
                        hmma(acc[i][j], al[i], bh[j]);
                        hmma(acc[i][j], ah[i], bl[j]);
                    }
            }
        }
        __syncthreads();

        int tqc = (lane & 3)*2;
        #pragma unroll
        for (int i = 0; i < 4; i++) {
            int r1 = wm*64 + i*16 + g;
            int r2 = r1 + 8;
            #pragma unroll
            for (int j = 0; j < 4; j++) {
                int cl = wn*32 + j*8 + tqc;
                float w00 = Wg4[cl],     w01 = Wg4[cl+1];
                float w10 = Wg4[128+cl], w11 = Wg4[128+cl+1];
                float w20 = Wg4[256+cl], w21 = Wg4[256+cl+1];
                float w30 = Wg4[384+cl], w31 = Wg4[384+cl+1];
                float s0 = acc[i][j][0], s1 = acc[i][j][1];
                s0 = fmaf(sgeom[r1],     w00, s0); s1 = fmaf(sgeom[r1],     w01, s1);
                s0 = fmaf(sgeom[128+r1], w10, s0); s1 = fmaf(sgeom[128+r1], w11, s1);
                s0 = fmaf(sgeom[256+r1], w20, s0); s1 = fmaf(sgeom[256+r1], w21, s1);
                s0 = fmaf(sgeom[384+r1], w30, s0); s1 = fmaf(sgeom[384+r1], w31, s1);
                *(float2*)&g_xw1[(ull)(b*NN + row0 + r1)*1024 + col0 + cl] = make_float2(s0, s1);
                float s2 = acc[i][j][2], s3 = acc[i][j][3];
                s2 = fmaf(sgeom[r2],     w00, s2); s3 = fmaf(sgeom[r2],     w01, s3);
                s2 = fmaf(sgeom[128+r2], w10, s2); s3 = fmaf(sgeom[128+r2], w11, s3);
                s2 = fmaf(sgeom[256+r2], w20, s2); s3 = fmaf(sgeom[256+r2], w21, s3);
                s2 = fmaf(sgeom[384+r2], w30, s2); s3 = fmaf(sgeom[384+r2], w31, s3);
                *(float2*)&g_xw1[(ull)(b*NN + row0 + r2)*1024 + col0 + cl] = make_float2(s2, s3);
            }
        }
    }
    pdl_launch();
}

// ------- merged: relation scores + top-8 (blocks 0..191)  |  asad (192..575) -
__global__ __launch_bounds__(256) void k_rel_asad(
    const float* __restrict__ boxes,
    const float* __restrict__ fc1_w,
    const float* __restrict__ fc1_b,
    const float* __restrict__ fc2_w,
    const float* __restrict__ att_src,
    const float* __restrict__ att_dst)
{
    __shared__ float srow[4][NN];
    __shared__ float sbx[16];
    int bid = blockIdx.x;
    int tid = threadIdx.x, warp = tid >> 5, lane = tid & 31;

    if (bid >= 192) {
        int h = (tid >> 5) & 3;
        const float* asr = att_src + h*256 + lane*8;
        const float* adr = att_dst + h*256 + lane*8;
        float4 s0 = *(const float4*)asr;
        float4 s1 = *(const float4*)(asr + 4);
        float4 d0 = *(const float4*)adr;
        float4 d1 = *(const float4*)(adr + 4);
        pdl_wait();
        int bn = (bid - 192)*2 + (tid >> 7);
        const float* xw = g_xw1 + bn*1024 + h*256 + lane*8;
        float4 v0 = *(const float4*)xw;
        float4 v1 = *(const float4*)(xw + 4);
        float ss = v0.x*s0.x + v0.y*s0.y + v0.z*s0.z + v0.w*s0.w
                 + v1.x*s1.x + v1.y*s1.y + v1.z*s1.z + v1.w*s1.w;
        float dd = v0.x*d0.x + v0.y*d0.y + v0.z*d0.z + v0.w*d0.w
                 + v1.x*d1.x + v1.y*d1.y + v1.z*d1.z + v1.w*d1.w;
        #pragma unroll
        for (int o = 16; o; o >>= 1) {
            ss += __shfl_down_sync(0xffffffffu, ss, o);
            dd += __shfl_down_sync(0xffffffffu, dd, o);
        }
        if (lane == 0) { g_as1[bn*4 + h] = ss; g_ad1[bn*4 + h] = dd; }
        pdl_launch();
        return;
    }

    int b = bid / 96, igrp = bid % 96;
    int i0 = igrp * 4;

    if (tid < 16) sbx[tid] = boxes[(b*NN + i0 + (tid >> 2))*4 + (tid & 3)];

    ull wg2[4][4], sp1q[4][4];
    float w2lo[4], w2hi[4], bb0[4], bb1[4];
    #pragma unroll
    for (int p = 0; p < 4; p++) {
        int k0 = lane + 64*p, k1 = k0 + 32;
        w2lo[p] = fc2_w[k0];
        w2hi[p] = fc2_w[k1];
        #pragma unroll
        for (int d = 0; d < 4; d++)
            wg2[d][p] = pack2(fc1_w[(2048+d)*256 + k0], fc1_w[(2048+d)*256 + k1]);
        bb0[p] = fc1_b[k0];
        bb1[p] = fc1_b[k1];
    }
    pdl_wait();
    #pragma unroll
    for (int p = 0; p < 4; p++) {
        int k0 = lane + 64*p, k1 = k0 + 32;
        #pragma unroll
        for (int q = 0; q < 4; q++) {
            const float* p1r = g_p1 + (b*NN + i0 + q)*256;
            sp1q[q][p] = pack2(p1r[k0] + bb0[p], p1r[k1] + bb1[p]);
        }
    }
    __syncthreads();

    const float* p2b = g_p2 + b*NN*256;
    const float* bxb = boxes + b*NN*4;

    for (int j = warp; j < NN; j += 8) {
        float4 bj = *(const float4*)&bxb[j*4];
        ull p2v[4];
        #pragma unroll
        for (int p = 0; p < 4; p++) {
            int k0 = lane + 64*p;
            p2v[p] = pack2(p2b[j*256 + k0], p2b[j*256 + k0 + 32]);
        }
        #pragma unroll
        for (int q = 0; q < 4; q++) {
            float d0 = fabsf(sbx[q*4+0] - bj.x);
            float d1 = fabsf(sbx[q*4+1] - bj.y);
            float d2 = fabsf(sbx[q*4+2] - bj.z);
            float d3 = fabsf(sbx[q*4+3] - bj.w);
            ull a0 = pack2(d0, d0), a1 = pack2(d1, d1);
            ull a2 = pack2(d2, d2), a3 = pack2(d3, d3);
            float sum = 0.f;
            #pragma unroll
            for (int p = 0; p < 4; p++) {
                ull t2 = add2v(sp1q[q][p], p2v[p]);
                t2 = fma2v(a0, wg2[0][p], t2);
                t2 = fma2v(a1, wg2[1][p], t2);
                t2 = fma2v(a2, wg2[2][p], t2);
                t2 = fma2v(a3, wg2[3][p], t2);
                float tl, th;
                unpack2(t2, tl, th);
                tl = fmaxf(tl, 0.f);
                th = fmaxf(th, 0.f);
                sum = fmaf(tl, w2lo[p], sum);
                sum = fmaf(th, w2hi[p], sum);
            }
            #pragma unroll
            for (int o = 16; o; o >>= 1) sum += __shfl_down_sync(0xffffffffu, sum, o);
            if (lane == 0)
                srow[q][j] = sum - ((j == i0 + q) ? 1e6f : 0.f);
        }
    }
    __syncthreads();

    if (warp < 4) {
        int q = warp, i = i0 + q;
        for (int sel2 = 0; sel2 < TOPKK; sel2++) {
            float bv = -3.4e38f; int bi = 1 << 30;
            for (int j = lane; j < NN; j += 32) {
                float v = srow[q][j];
                if (v > bv || (v == bv && j < bi)) { bv = v; bi = j; }
            }
            #pragma unroll
            for (int o = 16; o; o >>= 1) {
                float ov = __shfl_xor_sync(0xffffffffu, bv, o);
                int   oi = __shfl_xor_sync(0xffffffffu, bi, o);
                if (ov > bv || (ov == bv && oi < bi)) { bv = ov; bi = oi; }
            }
            if (lane == 0) {
                g_nbr[(b*NN + i)*TOPKK + sel2] = bi;
                srow[q][bi] = -3.4e38f;
            }
            __syncwarp();
        }
    }
    pdl_launch();
}

// ---- GAT1: 4 nodes/block, smem-staged nbr scan + softmax + aggregate + xw2 --
__global__ __launch_bounds__(256) void k_gat1(
    const float* __restrict__ gat1_b,
    const float* __restrict__ gat2_w,
    const float* __restrict__ att_src2,
    const float* __restrict__ att_dst2)
{
    int bn0 = blockIdx.x * 4;
    int b = bn0 / NN, tt0 = bn0 % NN;
    __shared__ int   snbr[NN*TOPKK];            // 12KB
    __shared__ float sas1[NN*4];                // 6KB
    __shared__ int   ssrc4[4][MAXDEG];          // 6.4KB
    __shared__ float sal4[4][NHEADS][MAXDEG];   // 25.6KB
    __shared__ int   wtot[8];
    __shared__ int   sdeg[4];
    __shared__ float red[8][2];
    int tid = threadIdx.x;
    int warp = tid >> 5, lane = tid & 31;

    pdl_wait();

    // batch preloads: as1 (6KB) + nbr (12KB, int4)
    #pragma unroll
    for (int it = 0; it < 6; it++)
        sas1[tid + it*256] = g_as1[b*NN*4 + tid + it*256];
    {
        const int4* src = (const int4*)(g_nbr + b*NN*TOPKK);
        int4* dst4 = (int4*)snbr;
        #pragma unroll
        for (int it = 0; it < 3; it++)
            dst4[tid + it*256] = src[tid + it*256];
    }
    __syncthreads();

    // ---- build: 4 targets, identical tid-ordered compaction per target ----
    #pragma unroll
    for (int q = 0; q < 4; q++) {
        int tt = tt0 + q;
        int bn = bn0 + q;
        int myc0 = 0, myc1 = 0;
        int ia = 2*tid, ib2 = 2*tid + 1;
        if (tid < 192) {
            #pragma unroll
            for (int k = 0; k < TOPKK; k++) {
                myc0 += (snbr[ia*TOPKK + k] == tt);
                myc1 += (snbr[ib2*TOPKK + k] == tt);
            }
        }
        int cnt = myc0 + myc1;
        int incl = cnt;
        #pragma unroll
        for (int d = 1; d < 32; d <<= 1) {
            int v = __shfl_up_sync(0xffffffffu, incl, d);
            if (lane >= d) incl += v;
        }
        if (lane == 31) wtot[warp] = incl;
        __syncthreads();
        int woff = 0, total = 0;
        #pragma unroll
        for (int w = 0; w < 8; w++) {
            int v = wtot[w];
            if (w < warp) woff += v;
            total += v;
        }
        int off = woff + incl - cnt;
        int* dst = g_srcl + bn*MAXDEG;
        if (tid < 192) {
            if (myc0) {
                #pragma unroll
                for (int k = 0; k < TOPKK; k++)
                    if (snbr[ia*TOPKK + k] == tt) { ssrc4[q][off] = ia; dst[off] = ia; off++; }
            }
            if (myc1) {
                #pragma unroll
                for (int k = 0; k < TOPKK; k++)
                    if (snbr[ib2*TOPKK + k] == tt) { ssrc4[q][off] = ib2; dst[off] = ib2; off++; }
            }
        }
        if (tid == 0) {
            ssrc4[q][total] = tt;
            dst[total] = tt;
            g_deg[bn] = total + 1;
            sdeg[q] = total + 1;
        }
        __syncthreads();
    }

    // ---- softmax: warp w -> target w>>1, heads (w&1)*2 and +1 ----
    {
        int q = warp >> 1;
        int deg = sdeg[q];
        int bn = bn0 + q;
        #pragma unroll
        for (int hh = 0; hh < 2; hh++) {
            int h = (warp & 1)*2 + hh;
            float adv = g_ad1[bn*4 + h];
            float m = -3.4e38f;
            for (int s = lane; s < deg; s += 32) {
                float e = sas1[ssrc4[q][s]*4 + h] + adv;
                e = (e >= 0.f) ? e : 0.2f*e;
                sal4[q][h][s] = e;
                m = fmaxf(m, e);
            }
            #pragma unroll
            for (int o = 16; o; o >>= 1) m = fmaxf(m, __shfl_xor_sync(0xffffffffu, m, o));
            float sum = 0.f;
            for (int s = lane; s < deg; s += 32) {
                float ex = expf(sal4[q][h][s] - m);
                sal4[q][h][s] = ex;
                sum += ex;
            }
            #pragma unroll
            for (int o = 16; o; o >>= 1) sum += __shfl_xor_sync(0xffffffffu, sum, o);
            float inv = 1.f / fmaxf(sum, 1e-16f);
            for (int s = lane; s < deg; s += 32) sal4[q][h][s] *= inv;
        }
    }
    __syncthreads();

    // ---- aggregate + fused xw2: loop over the 4 targets ----
    const float* xwb = g_xw1 + b*NN*1024;
    int col4 = tid * 4;
    int hmy = tid >> 6;
    float4 bia = *(const float4*)&gat1_b[col4];
    float4 w0 = *(const float4*)&gat2_w[col4*2];
    float4 w1 = *(const float4*)&gat2_w[col4*2 + 4];

    #pragma unroll
    for (int q = 0; q < 4; q++) {
        int bn = bn0 + q;
        int deg = sdeg[q];
        const float* salh = sal4[q][hmy];
        const int* sq = ssrc4[q];
        float4 acc0 = make_float4(0.f, 0.f, 0.f, 0.f);
        float4 acc1 = make_float4(0.f, 0.f, 0.f, 0.f);
        int s = 0;
        for (; s + 1 < deg; s += 2) {
            float4 v0 = *(const float4*)&xwb[sq[s  ]*1024 + col4];
            float4 v1 = *(const float4*)&xwb[sq[s+1]*1024 + col4];
            float a0 = salh[s], a1 = salh[s+1];
            acc0.x = fmaf(v0.x, a0, acc0.x); acc0.y = fmaf(v0.y, a0, acc0.y);
            acc0.z = fmaf(v0.z, a0, acc0.z); acc0.w = fmaf(v0.w, a0, acc0.w);
            acc1.x = fmaf(v1.x, a1, acc1.x); acc1.y = fmaf(v1.y, a1, acc1.y);
            acc1.z = fmaf(v1.z, a1, acc1.z); acc1.w = fmaf(v1.w, a1, acc1.w);
        }
        if (s < deg) {
            float4 v0 = *(const float4*)&xwb[sq[s]*1024 + col4];
            float a0 = salh[s];
            acc0.x = fmaf(v0.x, a0, acc0.x); acc0.y = fmaf(v0.y, a0, acc0.y);
            acc0.z = fmaf(v0.z, a0, acc0.z); acc0.w = fmaf(v0.w, a0, acc0.w);
        }
        float4 oh;
        oh.x = fmaxf(acc0.x + acc1.x + bia.x, 0.f);
        oh.y = fmaxf(acc0.y + acc1.y + bia.y, 0.f);
        oh.z = fmaxf(acc0.z + acc1.z + bia.z, 0.f);
        oh.w = fmaxf(acc0.w + acc1.w + bia.w, 0.f);

        float c0 = oh.x*w0.x + oh.y*w0.z + oh.z*w1.x + oh.w*w1.z;
        float c1 = oh.x*w0.y + oh.y*w0.w + oh.z*w1.y + oh.w*w1.w;
        #pragma unroll
        for (int o = 16; o; o >>= 1) {
            c0 += __shfl_down_sync(0xffffffffu, c0, o);
            c1 += __shfl_down_sync(0xffffffffu, c1, o);
        }
        if (lane == 0) { red[warp][0] = c0; red[warp][1] = c1; }
        __syncthreads();
        if (tid == 0) {
            float s0 = 0.f, s1 = 0.f;
            #pragma unroll
            for (int w = 0; w < 8; w++) { s0 += red[w][0]; s1 += red[w][1]; }
            g_xw2[bn*2 + 0] = s0;
            g_xw2[bn*2 + 1] = s1;
            g_as2[bn] = s0*att_src2[0] + s1*att_src2[1];
            g_ad2[bn] = s0*att_dst2[0] + s1*att_dst2[1];
        }
        __syncthreads();
    }
    pdl_launch();
}

// ------- GAT layer 2: 8 nodes/block, batch as2/xw2 preloaded into smem -------
__global__ __launch_bounds__(256) void k_gat2(const float* __restrict__ gat2_b,
                                              float* __restrict__ out)
{
    __shared__ float s_as2[NN];
    __shared__ float s_xw2[NN*2];
    __shared__ float sal[8][MAXDEG];
    __shared__ int   ssrc[8][MAXDEG];
    int tid = threadIdx.x;
    int warp = tid >> 5, lane = tid & 31;
    int n0 = blockIdx.x * 8;
    int b = n0 / NN;

    pdl_wait();

    for (int i = tid; i < NN; i += 256)   s_as2[i] = g_as2[b*NN + i];
    for (int i = tid; i < NN*2; i += 256) s_xw2[i] = g_xw2[b*NN*2 + i];
    __syncthreads();

    int bn = n0 + warp;
    int deg = g_deg[bn];
    for (int s = lane; s < deg; s += 32) ssrc[warp][s] = g_srcl[bn*MAXDEG + s];
    __syncwarp();
    float adv = g_ad2[bn];
    float m = -3.4e38f;
    for (int s = lane; s < deg; s += 32) {
        float e = s_as2[ssrc[warp][s]] + adv;
        e = (e >= 0.f) ? e : 0.2f*e;
        sal[warp][s] = e;
        m = fmaxf(m, e);
    }
    #pragma unroll
    for (int o = 16; o; o >>= 1) m = fmaxf(m, __shfl_xor_sync(0xffffffffu, m, o));
    float sum = 0.f;
    for (int s = lane; s < deg; s += 32) {
        float ex = expf(sal[warp][s] - m);
        sal[warp][s] = ex;
        sum += ex;
    }
    #pragma unroll
    for (int o = 16; o; o >>= 1) sum += __shfl_xor_sync(0xffffffffu, sum, o);
    float inv = 1.f / fmaxf(sum, 1e-16f);
    __syncwarp();
    float a0 = 0.f, a1 = 0.f;
    for (int s = lane; s < deg; s += 32) {
        float w = sal[warp][s] * inv;
        int sc = ssrc[warp][s];
        a0 = fmaf(s_xw2[sc*2 + 0], w, a0);
        a1 = fmaf(s_xw2[sc*2 + 1], w, a1);
    }
    #pragma unroll
    for (int o = 16; o; o >>= 1) {
        a0 += __shfl_down_sync(0xffffffffu, a0, o);
        a1 += __shfl_down_sync(0xffffffffu, a1, o);
    }
    if (lane == 0) {
        out[bn*2 + 0] = a0 + gat2_b[0];
        out[bn*2 + 1] = a1 + gat2_b[1];
    }
}

// ---------------- launch ------------------------------------------------------
extern "C" void kernel_launch(void* const* d_in, const int* in_sizes, int n_in,
                              void* d_out, int out_size)
{
    const float* feats   = (const float*)d_in[0];
    const float* boxes   = (const float*)d_in[1];
    const float* fc1_w   = (const float*)d_in[2];
    const float* fc1_b   = (const float*)d_in[3];
    const float* fc2_w   = (const float*)d_in[4];
    // d_in[5] = fc2_b : constant shift, irrelevant for top-k
    const float* gat1_w  = (const float*)d_in[6];
    const float* g1as    = (const float*)d_in[7];
    const float* g1ad    = (const float*)d_in[8];
    const float* gat1_b  = (const float*)d_in[9];
    const float* gat2_w  = (const float*)d_in[10];
    const float* g2as    = (const float*)d_in[11];
    const float* g2ad    = (const float*)d_in[12];
    const float* gat2_b  = (const float*)d_in[13];
    float* out = (float*)d_out;

    cudaLaunchAttribute pdl_attr[1];
    pdl_attr[0].id = cudaLaunchAttributeProgrammaticStreamSerialization;
    pdl_attr[0].val.programmaticStreamSerializationAllowed = 1;

    k_split<<<1792, 256>>>(feats, gat1_w);
    {
        cudaLaunchConfig_t cfg = {};
        cfg.gridDim = dim3(144, 1, 1);
        cfg.blockDim = dim3(256, 1, 1);
        cfg.stream = 0;
        cfg.attrs = pdl_attr;
        cfg.numAttrs = 1;
        cudaLaunchKernelEx(&cfg, k_gemms, feats, fc1_w, gat1_w, boxes);
    }
    {
        cudaLaunchConfig_t cfg = {};
        cfg.gridDim = dim3(192 + 384, 1, 1);
        cfg.blockDim = dim3(256, 1, 1);
        cfg.stream = 0;
        cfg.attrs = pdl_attr;
        cfg.numAttrs = 1;
        cudaLaunchKernelEx(&cfg, k_rel_asad, boxes, fc1_w, fc1_b, fc2_w, g1as, g1ad);
    }
    {
        cudaLaunchConfig_t cfg = {};
        cfg.gridDim = dim3(BB*96, 1, 1);
        cfg.blockDim = dim3(256, 1, 1);
        cfg.stream = 0;
        cfg.attrs = pdl_attr;
        cfg.numAttrs = 1;
        cudaLaunchKernelEx(&cfg, k_gat1, gat1_b, gat2_w, g2as, g2ad);
    }
    {
        cudaLaunchConfig_t cfg = {};
        cfg.gridDim = dim3(96, 1, 1);
        cfg.blockDim = dim3(256, 1, 1);
        cfg.stream = 0;
        cfg.attrs = pdl_attr;
        cfg.numAttrs = 1;
        cudaLaunchKernelEx(&cfg, k_gat2, gat2_b, out);
    }
    (void)in_sizes; (void)n_in; (void)out_size;
}